// round 6
// baseline (speedup 1.0000x reference)
#include <cuda_runtime.h>
#include <cuda_bf16.h>
#include <cstdint>
#include <math.h>

// Problem constants
#define BSZ 4
#define SEQ 1024
#define DMODEL 1024
#define NHEAD 16
#define DHEAD 64
#define LPE 2045   // 2*s-1, s = 1023

// Scratch
__device__ float g_qkv[BSZ * SEQ * 3 * DMODEL];
__device__ float g_pe [LPE * DMODEL];
__device__ float g_pek[LPE * DMODEL];
__device__ float g_ao [BSZ * SEQ * DMODEL];

// ---------------------------------------------------------------------------
__device__ __forceinline__ uint32_t f2tf32(float x) {
    uint32_t y;
    asm("cvt.rna.tf32.f32 %0, %1;" : "=r"(y) : "f"(x));
    return y;
}
__device__ __forceinline__ float f2tf32f(float x) {
    return __uint_as_float(f2tf32(x));
}

__device__ __forceinline__ void mma_tf32(float* d, const uint32_t* a,
                                         const uint32_t* b) {
    asm volatile(
        "mma.sync.aligned.m16n8k8.row.col.f32.tf32.tf32.f32 "
        "{%0,%1,%2,%3}, {%4,%5,%6,%7}, {%8,%9}, {%0,%1,%2,%3};\n"
        : "+f"(d[0]), "+f"(d[1]), "+f"(d[2]), "+f"(d[3])
        : "r"(a[0]), "r"(a[1]), "r"(a[2]), "r"(a[3]),
          "r"(b[0]), "r"(b[1]));
}

// XOR-swizzled 64-float row layout
__device__ __forceinline__ int swz(int row, int col) {
    return row * 64 + ((((col >> 2) ^ (row & 7)) << 2) | (col & 3));
}

// ---------------------------------------------------------------------------
__global__ void pegen_kernel(float* __restrict__ pe) {
    int idx = blockIdx.x * blockDim.x + threadIdx.x;
    if (idx >= LPE * DMODEL) return;
    int l  = idx >> 10;
    int kk = idx & 1023;
    int p2 = kk & ~1;
    float expnt = (float)p2 / 1024.0f;
    float denom = powf(10000.0f, expnt);
    float t = (float)(l - 1022);
    float ang = t / denom;
    float v = (kk & 1) ? cosf(ang) : sinf(ang);
    pe[idx] = v * 0.03125f;
}

// ===========================================================================
// TF32 mma.sync GEMM (unchanged from R3)
// ===========================================================================
#define ASTR 36
#define BSTR 136
#define A_STAGE (128 * ASTR)
#define B_STAGE (32 * BSTR)
#define GEMM_SMEM_BYTES ((2 * A_STAGE + 2 * B_STAGE) * 4)

__global__ __launch_bounds__(256)
void gemm_mma_kernel(const float* __restrict__ A, const float* __restrict__ B,
                     float* __restrict__ C, int M, int N, int K) {
    extern __shared__ float sm[];
    float* AsBase = sm;
    float* BsBase = sm + 2 * A_STAGE;

    int tid  = threadIdx.x;
    int wid  = tid >> 5;
    int lane = tid & 31;
    int g    = lane >> 2;
    int tg   = lane & 3;
    int wm0  = (wid >> 2) * 64;
    int wn0  = (wid & 3) * 32;
    int bm = blockIdx.y * 128;
    int bn = blockIdx.x * 128;

    float acc[4][4][4];
#pragma unroll
    for (int mt = 0; mt < 4; mt++)
#pragma unroll
        for (int nt = 0; nt < 4; nt++)
#pragma unroll
            for (int r = 0; r < 4; r++) acc[mt][nt][r] = 0.0f;

    float4 pa[4], pb[4];

    auto ldTile = [&](int k0) {
#pragma unroll
        for (int it = 0; it < 4; it++) {
            int l = tid + 256 * it;
            int row = l >> 3, c4 = (l & 7) << 2;
            int gr = bm + row;
            pa[it] = (gr < M)
                ? *(const float4*)(A + (size_t)gr * K + k0 + c4)
                : make_float4(0.f, 0.f, 0.f, 0.f);
        }
#pragma unroll
        for (int it = 0; it < 4; it++) {
            int l = tid + 256 * it;
            int kr = l >> 5, n4 = (l & 31) << 2;
            pb[it] = *(const float4*)(B + (size_t)(k0 + kr) * N + bn + n4);
        }
    };

    auto stsTile = [&](int s) {
        float* as = AsBase + s * A_STAGE;
        float* bs = BsBase + s * B_STAGE;
#pragma unroll
        for (int it = 0; it < 4; it++) {
            int l = tid + 256 * it;
            int row = l >> 3, c4 = (l & 7) << 2;
            uint4 v = make_uint4(f2tf32(pa[it].x), f2tf32(pa[it].y),
                                 f2tf32(pa[it].z), f2tf32(pa[it].w));
            *(uint4*)(as + row * ASTR + c4) = v;
        }
#pragma unroll
        for (int it = 0; it < 4; it++) {
            int l = tid + 256 * it;
            int kr = l >> 5, n4 = (l & 31) << 2;
            uint4 v = make_uint4(f2tf32(pb[it].x), f2tf32(pb[it].y),
                                 f2tf32(pb[it].z), f2tf32(pb[it].w));
            *(uint4*)(bs + kr * BSTR + n4) = v;
        }
    };

    auto compute = [&](int s) {
        const float* as = AsBase + s * A_STAGE;
        const float* bs = BsBase + s * B_STAGE;
#pragma unroll
        for (int ks = 0; ks < 4; ks++) {
            int k8 = ks * 8;
            uint32_t af[4][4], bf[4][2];
#pragma unroll
            for (int mt = 0; mt < 4; mt++) {
                const float* p = as + (wm0 + mt * 16 + g) * ASTR + k8 + tg;
                af[mt][0] = __float_as_uint(p[0]);
                af[mt][1] = __float_as_uint(p[8 * ASTR]);
                af[mt][2] = __float_as_uint(p[4]);
                af[mt][3] = __float_as_uint(p[8 * ASTR + 4]);
            }
#pragma unroll
            for (int nt = 0; nt < 4; nt++) {
                const float* p = bs + (k8 + tg) * BSTR + wn0 + nt * 8 + g;
                bf[nt][0] = __float_as_uint(p[0]);
                bf[nt][1] = __float_as_uint(p[4 * BSTR]);
            }
#pragma unroll
            for (int mt = 0; mt < 4; mt++)
#pragma unroll
                for (int nt = 0; nt < 4; nt++)
                    mma_tf32(acc[mt][nt], af[mt], bf[nt]);
        }
    };

    int T = K >> 5;
    ldTile(0);
    stsTile(0);
    __syncthreads();

    for (int t = 0; t < T; t++) {
        int s = t & 1;
        if (t + 1 < T) ldTile((t + 1) << 5);
        compute(s);
        if (t + 1 < T) {
            stsTile(s ^ 1);
            __syncthreads();
        }
    }

#pragma unroll
    for (int mt = 0; mt < 4; mt++) {
        int r0 = bm + wm0 + mt * 16 + g;
        int r1 = r0 + 8;
#pragma unroll
        for (int nt = 0; nt < 4; nt++) {
            int col = bn + wn0 + nt * 8 + 2 * tg;
            if (r0 < M)
                *(float2*)(C + (size_t)r0 * N + col) =
                    make_float2(acc[mt][nt][0], acc[mt][nt][1]);
            if (r1 < M)
                *(float2*)(C + (size_t)r1 * N + col) =
                    make_float2(acc[mt][nt][2], acc[mt][nt][3]);
        }
    }
}

// ===========================================================================
// Tensor-core fused relative attention, v2: warp m=32 (2 row-blocks).
// CTA = 128 q-rows, 4 warps, 128 threads, 2 CTAs/SM.  Grid = 4*16*8 = 512.
// Smem (floats): Ks 4096 | Vs 4096 | PEl 192x64=12288 | U 8192 | Msk 64
//   U: Q staging at start, then per-warp 2048-float slabs (Spos 16x84, P 16x64sw)
// Total 28736 floats = 114944 B -> 2 CTAs/SM.
// ===========================================================================
#define A2_KS 0
#define A2_VS 4096
#define A2_PE 8192
#define A2_U  20480
#define A2_MSK 28672
#define A2_SMEM_BYTES (28736 * 4)
#define SPAD 84
#define SLAB 2048

__global__ __launch_bounds__(128, 2)
void attn_mma2_kernel(const float* __restrict__ qkv, const float* __restrict__ pek,
                      const unsigned char* __restrict__ mask,
                      const float* __restrict__ cb, const float* __restrict__ pb,
                      float* __restrict__ ao) {
    extern __shared__ float sm[];
    float* Ks  = sm + A2_KS;
    float* Vs  = sm + A2_VS;
    float* PEl = sm + A2_PE;
    float* U   = sm + A2_U;
    float* Msk = sm + A2_MSK;

    int tid = threadIdx.x;
    int wid = tid >> 5;
    int lane = tid & 31;
    int g = lane >> 2;
    int tg = lane & 3;
    int qt = blockIdx.x & 7;
    int bh = blockIdx.x >> 3;
    int h  = bh & 15;
    int b  = bh >> 4;
    int q0 = qt * 128;

    const float* cbh = cb + h * DHEAD;
    const float* pbh = pb + h * DHEAD;

    // ---- Stage Q+content_bias into U (tf32, swizzled), 128 rows ----
    for (int idx = tid; idx < 2048; idx += 128) {
        int i = idx >> 4, cc = idx & 15;
        int c4 = cc * 4;
        const float* src = qkv + ((size_t)(b * SEQ + q0 + i)) * 3072 + h * 192 + c4;
        float4 v = *(const float4*)src;
        int sa = i * 64 + ((cc ^ (i & 7)) << 2);
        U[sa + 0] = f2tf32f(v.x + cbh[c4 + 0]);
        U[sa + 1] = f2tf32f(v.y + cbh[c4 + 1]);
        U[sa + 2] = f2tf32f(v.z + cbh[c4 + 2]);
        U[sa + 3] = f2tf32f(v.w + cbh[c4 + 3]);
    }
    __syncthreads();

    // ---- Persist Qc fragments (2 row-blocks x 8 k-steps) ----
    uint32_t qcf[2][8][4];
#pragma unroll
    for (int rb = 0; rb < 2; rb++) {
        int r0 = 32 * wid + 16 * rb + g, r1 = r0 + 8;
#pragma unroll
        for (int ks = 0; ks < 8; ks++) {
            int c0 = ks * 8 + tg, c1 = c0 + 4;
            qcf[rb][ks][0] = __float_as_uint(U[swz(r0, c0)]);
            qcf[rb][ks][1] = __float_as_uint(U[swz(r1, c0)]);
            qcf[rb][ks][2] = __float_as_uint(U[swz(r0, c1)]);
            qcf[rb][ks][3] = __float_as_uint(U[swz(r1, c1)]);
        }
    }
    __syncthreads();

    // ---- pos-bias minus content-bias deltas for this thread's frag cols ----
    float dd0[8], dd1[8];
#pragma unroll
    for (int ks = 0; ks < 8; ks++) {
        int c0 = ks * 8 + tg;
        dd0[ks] = pbh[c0] - cbh[c0];
        dd1[ks] = pbh[c0 + 4] - cbh[c0 + 4];
    }
    bool z0 = (q0 == 0 && wid == 0 && g == 0);  // global q-row 0 (row-block 0)

    float oac[2][8][4];
#pragma unroll
    for (int rb = 0; rb < 2; rb++)
#pragma unroll
        for (int nt = 0; nt < 8; nt++)
#pragma unroll
            for (int r = 0; r < 4; r++) oac[rb][nt][r] = 0.0f;
    float mrow[2][2], lrow[2][2];
#pragma unroll
    for (int rb = 0; rb < 2; rb++) {
        mrow[rb][0] = mrow[rb][1] = -1e30f;
        lrow[rb][0] = lrow[rb][1] = 0.0f;
    }

    float* slab = U + wid * SLAB;

    for (int kt = 0; kt < 16; kt++) {
        int k0 = kt * 64;
        int lbase = 895 + k0 - q0;
        __syncthreads();   // prior-iter Ks/Vs/PEl/Msk reads done

        // ---- Stage K, V (64 rows each) ----
        for (int idx = tid; idx < 1024; idx += 128) {
            int i = idx >> 4, cc = idx & 15;
            const float* base = qkv + ((size_t)(b * SEQ + k0 + i)) * 3072 + h * 192;
            float4 kv = *(const float4*)(base + 64 + cc * 4);
            float4 vv = *(const float4*)(base + 128 + cc * 4);
            int sa = i * 64 + ((cc ^ (i & 7)) << 2);
            Ks[sa + 0] = f2tf32f(kv.x); Ks[sa + 1] = f2tf32f(kv.y);
            Ks[sa + 2] = f2tf32f(kv.z); Ks[sa + 3] = f2tf32f(kv.w);
            Vs[sa + 0] = f2tf32f(vv.x); Vs[sa + 1] = f2tf32f(vv.y);
            Vs[sa + 2] = f2tf32f(vv.z); Vs[sa + 3] = f2tf32f(vv.w);
        }
        // ---- Stage PE band (192 rows; row 191 zero-padded / OOB-zeroed) ----
        for (int idx = tid; idx < 3072; idx += 128) {
            int l = idx >> 4, cc = idx & 15;
            int lg = lbase + l;
            float4 v = (l < 191 && lg >= 0 && lg < LPE)
                ? *(const float4*)(pek + (size_t)lg * DMODEL + h * DHEAD + cc * 4)
                : make_float4(0.f, 0.f, 0.f, 0.f);
            int sa = l * 64 + ((cc ^ (l & 7)) << 2);
            PEl[sa + 0] = f2tf32f(v.x); PEl[sa + 1] = f2tf32f(v.y);
            PEl[sa + 2] = f2tf32f(v.z); PEl[sa + 3] = f2tf32f(v.w);
        }
        if (tid < 64) Msk[tid] = mask[b * SEQ + k0 + tid] ? -1e30f : 0.0f;
        __syncthreads();

#pragma unroll
        for (int rb = 0; rb < 2; rb++) {
            // ---- Content scores: Qc @ K^T ----
            float sc[8][4];
#pragma unroll
            for (int nt = 0; nt < 8; nt++) {
                int n0 = nt * 8;
                sc[nt][0] = sc[nt][1] = sc[nt][2] = sc[nt][3] = 0.0f;
#pragma unroll
                for (int ks = 0; ks < 8; ks++) {
                    uint32_t bf[2];
                    bf[0] = __float_as_uint(Ks[swz(n0 + g, ks * 8 + tg)]);
                    bf[1] = __float_as_uint(Ks[swz(n0 + g, ks * 8 + tg + 4)]);
                    mma_tf32(sc[nt], qcf[rb][ks], bf);
                }
            }

            // ---- Build Qp fragments from Qc + delta ----
            uint32_t ap[8][4];
#pragma unroll
            for (int ks = 0; ks < 8; ks++) {
                ap[ks][0] = f2tf32(__uint_as_float(qcf[rb][ks][0]) + dd0[ks]);
                ap[ks][1] = f2tf32(__uint_as_float(qcf[rb][ks][1]) + dd0[ks]);
                ap[ks][2] = f2tf32(__uint_as_float(qcf[rb][ks][2]) + dd1[ks]);
                ap[ks][3] = f2tf32(__uint_as_float(qcf[rb][ks][3]) + dd1[ks]);
            }
            if (z0 && rb == 0) {
#pragma unroll
                for (int ks = 0; ks < 8; ks++) { ap[ks][0] = 0u; ap[ks][2] = 0u; }
            }

            // ---- Band: Spos = Qp @ PEband^T  (10 n-tiles for this rb) ----
            int s0t = 14 - 4 * wid - 2 * rb;
#pragma unroll
            for (int t = 0; t < 10; t++) {
                int br = (s0t + t) * 8 + g;
                float sp[4] = {0.f, 0.f, 0.f, 0.f};
#pragma unroll
                for (int ks = 0; ks < 8; ks++) {
                    uint32_t bf[2];
                    bf[0] = __float_as_uint(PEl[swz(br, ks * 8 + tg)]);
                    bf[1] = __float_as_uint(PEl[swz(br, ks * 8 + tg + 4)]);
                    mma_tf32(sp, ap[ks], bf);
                }
                int cc0 = 8 * t + 2 * tg;
                slab[g * SPAD + cc0]       = sp[0];
                slab[g * SPAD + cc0 + 1]   = sp[1];
                slab[(g + 8) * SPAD + cc0]     = sp[2];
                slab[(g + 8) * SPAD + cc0 + 1] = sp[3];
            }
            __syncwarp();

            // ---- Gather diagonals, combine, mask, row max ----
            float mt0 = -1e30f, mt1 = -1e30f;
#pragma unroll
            for (int nt = 0; nt < 8; nt++) {
                int j0 = nt * 8 + 2 * tg;
                int c00 = j0 - g + 15;       // row g  (c' = j - r' + 15)
                int c10 = j0 - g + 7;        // row g+8
                float p0 = slab[g * SPAD + c00];
                float p1 = slab[g * SPAD + c00 + 1];
                float p2 = slab[(g + 8) * SPAD + c10];
                float p3 = slab[(g + 8) * SPAD + c10 + 1];
                if (kt == 0 && nt == 0 && tg == 0) { p0 = 0.0f; p2 = 0.0f; }
                float mk0 = Msk[j0], mk1 = Msk[j0 + 1];
                sc[nt][0] = (sc[nt][0] + p0) * 0.125f + mk0;
                sc[nt][1] = (sc[nt][1] + p1) * 0.125f + mk1;
                sc[nt][2] = (sc[nt][2] + p2) * 0.125f + mk0;
                sc[nt][3] = (sc[nt][3] + p3) * 0.125f + mk1;
                mt0 = fmaxf(mt0, fmaxf(sc[nt][0], sc[nt][1]));
                mt1 = fmaxf(mt1, fmaxf(sc[nt][2], sc[nt][3]));
            }
            mt0 = fmaxf(mt0, __shfl_xor_sync(0xffffffffu, mt0, 1));
            mt0 = fmaxf(mt0, __shfl_xor_sync(0xffffffffu, mt0, 2));
            mt1 = fmaxf(mt1, __shfl_xor_sync(0xffffffffu, mt1, 1));
            mt1 = fmaxf(mt1, __shfl_xor_sync(0xffffffffu, mt1, 2));

            // ---- Online softmax ----
            float mn0 = fmaxf(mrow[rb][0], mt0), mn1 = fmaxf(mrow[rb][1], mt1);
            float c0 = __expf(mrow[rb][0] - mn0), c1 = __expf(mrow[rb][1] - mn1);
            mrow[rb][0] = mn0; mrow[rb][1] = mn1;
#pragma unroll
            for (int nt = 0; nt < 8; nt++) {
                oac[rb][nt][0] *= c0; oac[rb][nt][1] *= c0;
                oac[rb][nt][2] *= c1; oac[rb][nt][3] *= c1;
            }
            float rs0 = 0.0f, rs1 = 0.0f;
#pragma unroll
            for (int nt = 0; nt < 8; nt++) {
                sc[nt][0] = __expf(sc[nt][0] - mn0);
                sc[nt][1] = __expf(sc[nt][1] - mn0);
                sc[nt][2] = __expf(sc[nt][2] - mn1);
                sc[nt][3] = __expf(sc[nt][3] - mn1);
                rs0 += sc[nt][0] + sc[nt][1];
                rs1 += sc[nt][2] + sc[nt][3];
            }
            rs0 += __shfl_xor_sync(0xffffffffu, rs0, 1);
            rs0 += __shfl_xor_sync(0xffffffffu, rs0, 2);
            rs1 += __shfl_xor_sync(0xffffffffu, rs1, 1);
            rs1 += __shfl_xor_sync(0xffffffffu, rs1, 2);
            lrow[rb][0] = lrow[rb][0] * c0 + rs0;
            lrow[rb][1] = lrow[rb][1] * c1 + rs1;

            __syncwarp();   // all gathers done before P overwrites slab

            // ---- Write P (16 rows, swizzled, tf32) ----
#pragma unroll
            for (int nt = 0; nt < 8; nt++) {
                int j0 = nt * 8 + 2 * tg;
                slab[swz(g, j0)]         = f2tf32f(sc[nt][0]);
                slab[swz(g, j0 + 1)]     = f2tf32f(sc[nt][1]);
                slab[swz(g + 8, j0)]     = f2tf32f(sc[nt][2]);
                slab[swz(g + 8, j0 + 1)] = f2tf32f(sc[nt][3]);
            }
            __syncwarp();

            // ---- O(rb) += P @ V ----
            uint32_t pf[8][4];
#pragma unroll
            for (int ks = 0; ks < 8; ks++) {
                int c0c = ks * 8 + tg, c1c = c0c + 4;
                pf[ks][0] = __float_as_uint(slab[swz(g, c0c)]);
                pf[ks][1] = __float_as_uint(slab[swz(g + 8, c0c)]);
                pf[ks][2] = __float_as_uint(slab[swz(g, c1c)]);
                pf[ks][3] = __float_as_uint(slab[swz(g + 8, c1c)]);
            }
#pragma unroll
            for (int nt = 0; nt < 8; nt++) {
                int n0 = nt * 8;
#pragma unroll
                for (int ks = 0; ks < 8; ks++) {
                    uint32_t bf[2];
                    bf[0] = __float_as_uint(Vs[swz(ks * 8 + tg, n0 + g)]);
                    bf[1] = __float_as_uint(Vs[swz(ks * 8 + tg + 4, n0 + g)]);
                    mma_tf32(oac[rb][nt], pf[ks], bf);
                }
            }
            __syncwarp();   // slab reads done before next rb's band writes
        }
    }

    // ---- Epilogue ----
#pragma unroll
    for (int rb = 0; rb < 2; rb++) {
        float inv0 = 1.0f / lrow[rb][0], inv1 = 1.0f / lrow[rb][1];
        int r0 = q0 + 32 * wid + 16 * rb + g, r1 = r0 + 8;
        size_t rowA = ((size_t)(b * SEQ + r0)) * DMODEL + h * DHEAD;
        size_t rowB = ((size_t)(b * SEQ + r1)) * DMODEL + h * DHEAD;
#pragma unroll
        for (int nt = 0; nt < 8; nt++) {
            int col = nt * 8 + 2 * tg;
            *(float2*)(ao + rowA + col) =
                make_float2(oac[rb][nt][0] * inv0, oac[rb][nt][1] * inv0);
            *(float2*)(ao + rowB + col) =
                make_float2(oac[rb][nt][2] * inv1, oac[rb][nt][3] * inv1);
        }
    }
}

// ---------------------------------------------------------------------------
extern "C" void kernel_launch(void* const* d_in, const int* in_sizes, int n_in,
                              void* d_out, int out_size) {
    const float* x          = (const float*)d_in[0];
    const unsigned char* mk = (const unsigned char*)d_in[1];
    const float* Wqkv       = (const float*)d_in[2];
    const float* Wpe        = (const float*)d_in[3];
    const float* Wo         = (const float*)d_in[4];
    const float* cb         = (const float*)d_in[5];
    const float* pb         = (const float*)d_in[6];
    float* out              = (float*)d_out;

    float *qkv, *pe, *pek, *ao;
    cudaGetSymbolAddress((void**)&qkv, g_qkv);
    cudaGetSymbolAddress((void**)&pe,  g_pe);
    cudaGetSymbolAddress((void**)&pek, g_pek);
    cudaGetSymbolAddress((void**)&ao,  g_ao);

    cudaFuncSetAttribute(gemm_mma_kernel,
                         cudaFuncAttributeMaxDynamicSharedMemorySize,
                         GEMM_SMEM_BYTES);
    cudaFuncSetAttribute(attn_mma2_kernel,
                         cudaFuncAttributeMaxDynamicSharedMemorySize,
                         A2_SMEM_BYTES);

    pegen_kernel<<<(LPE * DMODEL + 255) / 256, 256>>>(pe);

    {
        dim3 grid(3072 / 128, 4096 / 128);
        gemm_mma_kernel<<<grid, 256, GEMM_SMEM_BYTES>>>(x, Wqkv, qkv,
                                                        BSZ * SEQ, 3 * DMODEL, DMODEL);
    }
    {
        dim3 grid(1024 / 128, (LPE + 127) / 128);
        gemm_mma_kernel<<<grid, 256, GEMM_SMEM_BYTES>>>(pe, Wpe, pek,
                                                        LPE, DMODEL, DMODEL);
    }

    attn_mma2_kernel<<<BSZ * NHEAD * (SEQ / 128), 128, A2_SMEM_BYTES>>>(
        qkv, pek, mk, cb, pb, ao);

    {
        dim3 grid(1024 / 128, 4096 / 128);
        gemm_mma_kernel<<<grid, 256, GEMM_SMEM_BYTES>>>(ao, Wo, out,
                                                        BSZ * SEQ, DMODEL, DMODEL);
    }
}

// round 7
// speedup vs baseline: 1.1170x; 1.1170x over previous
#include <cuda_runtime.h>
#include <cuda_bf16.h>
#include <cstdint>
#include <math.h>

// Problem constants
#define BSZ 4
#define SEQ 1024
#define DMODEL 1024
#define NHEAD 16
#define DHEAD 64
#define LPE 2045   // 2*s-1, s = 1023

// Scratch
__device__ float g_qkv[BSZ * SEQ * 3 * DMODEL];
__device__ float g_pe [LPE * DMODEL];
__device__ float g_pek[LPE * DMODEL];
__device__ float g_ao [BSZ * SEQ * DMODEL];
__device__ float g_pbias[NHEAD * 2048];   // (pb-cb) . pek[l], per head

// ---------------------------------------------------------------------------
__device__ __forceinline__ uint32_t f2tf32(float x) {
    uint32_t y;
    asm("cvt.rna.tf32.f32 %0, %1;" : "=r"(y) : "f"(x));
    return y;
}
__device__ __forceinline__ float f2tf32f(float x) {
    return __uint_as_float(f2tf32(x));
}

__device__ __forceinline__ void mma_tf32(float* d, const uint32_t* a,
                                         const uint32_t* b) {
    asm volatile(
        "mma.sync.aligned.m16n8k8.row.col.f32.tf32.tf32.f32 "
        "{%0,%1,%2,%3}, {%4,%5,%6,%7}, {%8,%9}, {%0,%1,%2,%3};\n"
        : "+f"(d[0]), "+f"(d[1]), "+f"(d[2]), "+f"(d[3])
        : "r"(a[0]), "r"(a[1]), "r"(a[2]), "r"(a[3]),
          "r"(b[0]), "r"(b[1]));
}

// XOR-swizzled 64-float row layout
__device__ __forceinline__ int swz(int row, int col) {
    return row * 64 + ((((col >> 2) ^ (row & 7)) << 2) | (col & 3));
}

// ---------------------------------------------------------------------------
__global__ void pegen_kernel(float* __restrict__ pe) {
    int idx = blockIdx.x * blockDim.x + threadIdx.x;
    if (idx >= LPE * DMODEL) return;
    int l  = idx >> 10;
    int kk = idx & 1023;
    int p2 = kk & ~1;
    float expnt = (float)p2 / 1024.0f;
    float denom = powf(10000.0f, expnt);
    float t = (float)(l - 1022);
    float ang = t / denom;
    float v = (kk & 1) ? cosf(ang) : sinf(ang);
    pe[idx] = v * 0.03125f;
}

// pbias[h][l] = sum_c (pb[h,c]-cb[h,c]) * pek[l, h*64+c]
__global__ void pbias_kernel(const float* __restrict__ pek,
                             const float* __restrict__ cb,
                             const float* __restrict__ pb,
                             float* __restrict__ pbias) {
    int idx = blockIdx.x * blockDim.x + threadIdx.x;
    if (idx >= NHEAD * 2048) return;
    int h = idx >> 11, l = idx & 2047;
    float s = 0.0f;
    if (l < LPE) {
        const float* row = pek + (size_t)l * DMODEL + h * DHEAD;
#pragma unroll 16
        for (int c = 0; c < DHEAD; c++)
            s += (pb[h * DHEAD + c] - cb[h * DHEAD + c]) * row[c];
    }
    pbias[idx] = s;
}

// ===========================================================================
// TF32 mma.sync GEMM (unchanged from R3)
// ===========================================================================
#define ASTR 36
#define BSTR 136
#define A_STAGE (128 * ASTR)
#define B_STAGE (32 * BSTR)
#define GEMM_SMEM_BYTES ((2 * A_STAGE + 2 * B_STAGE) * 4)

__global__ __launch_bounds__(256)
void gemm_mma_kernel(const float* __restrict__ A, const float* __restrict__ B,
                     float* __restrict__ C, int M, int N, int K) {
    extern __shared__ float sm[];
    float* AsBase = sm;
    float* BsBase = sm + 2 * A_STAGE;

    int tid  = threadIdx.x;
    int wid  = tid >> 5;
    int lane = tid & 31;
    int g    = lane >> 2;
    int tg   = lane & 3;
    int wm0  = (wid >> 2) * 64;
    int wn0  = (wid & 3) * 32;
    int bm = blockIdx.y * 128;
    int bn = blockIdx.x * 128;

    float acc[4][4][4];
#pragma unroll
    for (int mt = 0; mt < 4; mt++)
#pragma unroll
        for (int nt = 0; nt < 4; nt++)
#pragma unroll
            for (int r = 0; r < 4; r++) acc[mt][nt][r] = 0.0f;

    float4 pa[4], pb4[4];

    auto ldTile = [&](int k0) {
#pragma unroll
        for (int it = 0; it < 4; it++) {
            int l = tid + 256 * it;
            int row = l >> 3, c4 = (l & 7) << 2;
            int gr = bm + row;
            pa[it] = (gr < M)
                ? *(const float4*)(A + (size_t)gr * K + k0 + c4)
                : make_float4(0.f, 0.f, 0.f, 0.f);
        }
#pragma unroll
        for (int it = 0; it < 4; it++) {
            int l = tid + 256 * it;
            int kr = l >> 5, n4 = (l & 31) << 2;
            pb4[it] = *(const float4*)(B + (size_t)(k0 + kr) * N + bn + n4);
        }
    };

    auto stsTile = [&](int s) {
        float* as = AsBase + s * A_STAGE;
        float* bs = BsBase + s * B_STAGE;
#pragma unroll
        for (int it = 0; it < 4; it++) {
            int l = tid + 256 * it;
            int row = l >> 3, c4 = (l & 7) << 2;
            uint4 v = make_uint4(f2tf32(pa[it].x), f2tf32(pa[it].y),
                                 f2tf32(pa[it].z), f2tf32(pa[it].w));
            *(uint4*)(as + row * ASTR + c4) = v;
        }
#pragma unroll
        for (int it = 0; it < 4; it++) {
            int l = tid + 256 * it;
            int kr = l >> 5, n4 = (l & 31) << 2;
            uint4 v = make_uint4(f2tf32(pb4[it].x), f2tf32(pb4[it].y),
                                 f2tf32(pb4[it].z), f2tf32(pb4[it].w));
            *(uint4*)(bs + kr * BSTR + n4) = v;
        }
    };

    auto compute = [&](int s) {
        const float* as = AsBase + s * A_STAGE;
        const float* bs = BsBase + s * B_STAGE;
#pragma unroll
        for (int ks = 0; ks < 4; ks++) {
            int k8 = ks * 8;
            uint32_t af[4][4], bf[4][2];
#pragma unroll
            for (int mt = 0; mt < 4; mt++) {
                const float* p = as + (wm0 + mt * 16 + g) * ASTR + k8 + tg;
                af[mt][0] = __float_as_uint(p[0]);
                af[mt][1] = __float_as_uint(p[8 * ASTR]);
                af[mt][2] = __float_as_uint(p[4]);
                af[mt][3] = __float_as_uint(p[8 * ASTR + 4]);
            }
#pragma unroll
            for (int nt = 0; nt < 4; nt++) {
                const float* p = bs + (k8 + tg) * BSTR + wn0 + nt * 8 + g;
                bf[nt][0] = __float_as_uint(p[0]);
                bf[nt][1] = __float_as_uint(p[4 * BSTR]);
            }
#pragma unroll
            for (int mt = 0; mt < 4; mt++)
#pragma unroll
                for (int nt = 0; nt < 4; nt++)
                    mma_tf32(acc[mt][nt], af[mt], bf[nt]);
        }
    };

    int T = K >> 5;
    ldTile(0);
    stsTile(0);
    __syncthreads();

    for (int t = 0; t < T; t++) {
        int s = t & 1;
        if (t + 1 < T) ldTile((t + 1) << 5);
        compute(s);
        if (t + 1 < T) {
            stsTile(s ^ 1);
            __syncthreads();
        }
    }

#pragma unroll
    for (int mt = 0; mt < 4; mt++) {
        int r0 = bm + wm0 + mt * 16 + g;
        int r1 = r0 + 8;
#pragma unroll
        for (int nt = 0; nt < 4; nt++) {
            int col = bn + wn0 + nt * 8 + 2 * tg;
            if (r0 < M)
                *(float2*)(C + (size_t)r0 * N + col) =
                    make_float2(acc[mt][nt][0], acc[mt][nt][1]);
            if (r1 < M)
                *(float2*)(C + (size_t)r1 * N + col) =
                    make_float2(acc[mt][nt][2], acc[mt][nt][3]);
        }
    }
}

// ===========================================================================
// Attention v3: CTA = 256 q-rows, 8 warps x 32 rows, 1 CTA/SM, grid 256.
// B-fragments (K / PE-band / V) shared across both 16-row blocks per warp.
// Band uses Qc fragments + precomputed per-PE-row bias (pos-bias folded out).
// Smem (floats): Ks 4096 | Vs 4096 | PEl 320x64=20480 | Bias 320 | Msk 64 |
//                U 8*2688=21504 (Q staging, then per-warp Spos/P slabs)
// Total 50560 floats = 202240 B  -> 1 CTA/SM (8 warps).
// ===========================================================================
#define A3_KS 0
#define A3_VS 4096
#define A3_PE 8192
#define A3_BIAS 28672
#define A3_MSK 28992
#define A3_U 29056
#define A3_SMEM_BYTES (50560 * 4)
#define SPAD 84
#define WSLAB 2688
#define RSLAB 1344

__global__ __launch_bounds__(256, 1)
void attn_mma3_kernel(const float* __restrict__ qkv, const float* __restrict__ pek,
                      const unsigned char* __restrict__ mask,
                      const float* __restrict__ cb, const float* __restrict__ pbias,
                      float* __restrict__ ao) {
    extern __shared__ float sm[];
    float* Ks   = sm + A3_KS;
    float* Vs   = sm + A3_VS;
    float* PEl  = sm + A3_PE;
    float* Bias = sm + A3_BIAS;
    float* Msk  = sm + A3_MSK;
    float* U    = sm + A3_U;

    int tid = threadIdx.x;
    int wid = tid >> 5;
    int lane = tid & 31;
    int g = lane >> 2;
    int tg = lane & 3;
    int qt = blockIdx.x & 3;
    int bh = blockIdx.x >> 2;
    int h  = bh & 15;
    int b  = bh >> 4;
    int q0 = qt * 256;

    const float* cbh = cb + h * DHEAD;
    const float* pbh_bias = pbias + h * 2048;

    // ---- Stage Qc = q + content_bias (256 rows, tf32, swizzled) into U ----
    for (int idx = tid; idx < 4096; idx += 256) {
        int i = idx >> 4, cc = idx & 15;
        int c4 = cc * 4;
        const float* src = qkv + ((size_t)(b * SEQ + q0 + i)) * 3072 + h * 192 + c4;
        float4 v = *(const float4*)src;
        int sa = i * 64 + ((cc ^ (i & 7)) << 2);
        U[sa + 0] = f2tf32f(v.x + cbh[c4 + 0]);
        U[sa + 1] = f2tf32f(v.y + cbh[c4 + 1]);
        U[sa + 2] = f2tf32f(v.z + cbh[c4 + 2]);
        U[sa + 3] = f2tf32f(v.w + cbh[c4 + 3]);
    }
    __syncthreads();

    // ---- Persist Qc fragments: 2 row-blocks x 8 k-steps ----
    uint32_t qcf[2][8][4];
#pragma unroll
    for (int rb = 0; rb < 2; rb++) {
        int r0 = 32 * wid + 16 * rb + g, r1 = r0 + 8;
#pragma unroll
        for (int ks = 0; ks < 8; ks++) {
            int c0 = ks * 8 + tg, c1 = c0 + 4;
            qcf[rb][ks][0] = __float_as_uint(U[swz(r0, c0)]);
            qcf[rb][ks][1] = __float_as_uint(U[swz(r1, c0)]);
            qcf[rb][ks][2] = __float_as_uint(U[swz(r0, c1)]);
            qcf[rb][ks][3] = __float_as_uint(U[swz(r1, c1)]);
        }
    }
    __syncthreads();

    bool z0 = (q0 == 0 && wid == 0 && g == 0);  // global q-row 0 in rb0

    float oac[2][8][4];
#pragma unroll
    for (int rb = 0; rb < 2; rb++)
#pragma unroll
        for (int nt = 0; nt < 8; nt++)
#pragma unroll
            for (int r = 0; r < 4; r++) oac[rb][nt][r] = 0.0f;
    float mrow[2][2], lrow[2][2];
#pragma unroll
    for (int rb = 0; rb < 2; rb++) {
        mrow[rb][0] = mrow[rb][1] = -1e30f;
        lrow[rb][0] = lrow[rb][1] = 0.0f;
    }

    float* sl0 = U + wid * WSLAB;          // rb0 slab: 16 x SPAD
    float* sl1 = sl0 + RSLAB;              // rb1 slab
    int s0base = 28 - 4 * wid;             // band tile origin (union of both rbs)

    for (int kt = 0; kt < 16; kt++) {
        int k0 = kt * 64;
        int lbase = 767 + k0 - q0;
        __syncthreads();   // prior-iter reads of Ks/Vs/PEl/Bias/Msk done

        // ---- Stage K, V (64 rows) ----
        for (int idx = tid; idx < 1024; idx += 256) {
            int i = idx >> 4, cc = idx & 15;
            const float* base = qkv + ((size_t)(b * SEQ + k0 + i)) * 3072 + h * 192;
            float4 kv = *(const float4*)(base + 64 + cc * 4);
            float4 vv = *(const float4*)(base + 128 + cc * 4);
            int sa = i * 64 + ((cc ^ (i & 7)) << 2);
            Ks[sa + 0] = f2tf32f(kv.x); Ks[sa + 1] = f2tf32f(kv.y);
            Ks[sa + 2] = f2tf32f(kv.z); Ks[sa + 3] = f2tf32f(kv.w);
            Vs[sa + 0] = f2tf32f(vv.x); Vs[sa + 1] = f2tf32f(vv.y);
            Vs[sa + 2] = f2tf32f(vv.z); Vs[sa + 3] = f2tf32f(vv.w);
        }
        // ---- Stage PE band (320 rows; OOB rows zeroed) ----
        for (int idx = tid; idx < 5120; idx += 256) {
            int l = idx >> 4, cc = idx & 15;
            int lg = lbase + l;
            float4 v = (lg >= 0 && lg < LPE)
                ? *(const float4*)(pek + (size_t)lg * DMODEL + h * DHEAD + cc * 4)
                : make_float4(0.f, 0.f, 0.f, 0.f);
            int sa = l * 64 + ((cc ^ (l & 7)) << 2);
            PEl[sa + 0] = f2tf32f(v.x); PEl[sa + 1] = f2tf32f(v.y);
            PEl[sa + 2] = f2tf32f(v.z); PEl[sa + 3] = f2tf32f(v.w);
        }
        // ---- Stage bias (320) + mask (64) ----
        {
            int lg = lbase + tid;
            Bias[tid] = (tid < 256 && lg >= 0 && lg < LPE) ? pbh_bias[lg] : 0.0f;
            if (tid < 64) {
                int lg2 = lbase + 256 + tid;
                Bias[256 + tid] = (lg2 >= 0 && lg2 < LPE) ? pbh_bias[lg2] : 0.0f;
                Msk[tid] = mask[b * SEQ + k0 + tid] ? -1e30f : 0.0f;
            }
        }
        __syncthreads();

        // ---- Band: Spos tiles for both rbs, B-frag loaded once per tile ----
#pragma unroll
        for (int tu = 0; tu < 12; tu++) {
            int tr = (s0base + tu) * 8 + g;
            float sp0[4] = {0.f, 0.f, 0.f, 0.f};
            float sp1[4] = {0.f, 0.f, 0.f, 0.f};
#pragma unroll
            for (int ks = 0; ks < 8; ks++) {
                uint32_t bf[2];
                bf[0] = __float_as_uint(PEl[swz(tr, ks * 8 + tg)]);
                bf[1] = __float_as_uint(PEl[swz(tr, ks * 8 + tg + 4)]);
                if (tu >= 2) mma_tf32(sp0, qcf[0][ks], bf);
                if (tu <= 9) mma_tf32(sp1, qcf[1][ks], bf);
            }
            float b0 = Bias[(s0base + tu) * 8 + 2 * tg];
            float b1 = Bias[(s0base + tu) * 8 + 2 * tg + 1];
            if (tu >= 2) {
                int cc0 = 8 * (tu - 2) + 2 * tg;
                sl0[g * SPAD + cc0]           = sp0[0] + b0;
                sl0[g * SPAD + cc0 + 1]       = sp0[1] + b1;
                sl0[(g + 8) * SPAD + cc0]     = sp0[2] + b0;
                sl0[(g + 8) * SPAD + cc0 + 1] = sp0[3] + b1;
            }
            if (tu <= 9) {
                int cc0 = 8 * tu + 2 * tg;
                sl1[g * SPAD + cc0]           = sp1[0] + b0;
                sl1[g * SPAD + cc0 + 1]       = sp1[1] + b1;
                sl1[(g + 8) * SPAD + cc0]     = sp1[2] + b0;
                sl1[(g + 8) * SPAD + cc0 + 1] = sp1[3] + b1;
            }
        }
        __syncwarp();

        // ---- Content scores for both rbs, shared K B-frags ----
        float sc[2][8][4];
#pragma unroll
        for (int nt = 0; nt < 8; nt++) {
            int n0 = nt * 8;
#pragma unroll
            for (int r = 0; r < 4; r++) { sc[0][nt][r] = 0.f; sc[1][nt][r] = 0.f; }
#pragma unroll
            for (int ks = 0; ks < 8; ks++) {
                uint32_t bf[2];
                bf[0] = __float_as_uint(Ks[swz(n0 + g, ks * 8 + tg)]);
                bf[1] = __float_as_uint(Ks[swz(n0 + g, ks * 8 + tg + 4)]);
                mma_tf32(sc[0][nt], qcf[0][ks], bf);
                mma_tf32(sc[1][nt], qcf[1][ks], bf);
            }
        }

        // ---- Gather band diag + combine + softmax + write P (per rb) ----
#pragma unroll
        for (int rb = 0; rb < 2; rb++) {
            float* sl = (rb == 0) ? sl0 : sl1;
            float mt0 = -1e30f, mt1 = -1e30f;
#pragma unroll
            for (int nt = 0; nt < 8; nt++) {
                int j0 = nt * 8 + 2 * tg;
                int c00 = j0 - g + 15;
                int c10 = j0 - g + 7;
                float p0 = sl[g * SPAD + c00];
                float p1 = sl[g * SPAD + c00 + 1];
                float p2 = sl[(g + 8) * SPAD + c10];
                float p3 = sl[(g + 8) * SPAD + c10 + 1];
                if (kt == 0 && nt == 0 && tg == 0) { p0 = 0.0f; p2 = 0.0f; }
                if (z0 && rb == 0) { p0 = 0.0f; p1 = 0.0f; }   // q-row 0 (g==0 in z0)
                float mk0 = Msk[j0], mk1 = Msk[j0 + 1];
                sc[rb][nt][0] = (sc[rb][nt][0] + p0) * 0.125f + mk0;
                sc[rb][nt][1] = (sc[rb][nt][1] + p1) * 0.125f + mk1;
                sc[rb][nt][2] = (sc[rb][nt][2] + p2) * 0.125f + mk0;
                sc[rb][nt][3] = (sc[rb][nt][3] + p3) * 0.125f + mk1;
                mt0 = fmaxf(mt0, fmaxf(sc[rb][nt][0], sc[rb][nt][1]));
                mt1 = fmaxf(mt1, fmaxf(sc[rb][nt][2], sc[rb][nt][3]));
            }
            mt0 = fmaxf(mt0, __shfl_xor_sync(0xffffffffu, mt0, 1));
            mt0 = fmaxf(mt0, __shfl_xor_sync(0xffffffffu, mt0, 2));
            mt1 = fmaxf(mt1, __shfl_xor_sync(0xffffffffu, mt1, 1));
            mt1 = fmaxf(mt1, __shfl_xor_sync(0xffffffffu, mt1, 2));

            float mn0 = fmaxf(mrow[rb][0], mt0), mn1 = fmaxf(mrow[rb][1], mt1);
            float c0 = __expf(mrow[rb][0] - mn0), c1 = __expf(mrow[rb][1] - mn1);
            mrow[rb][0] = mn0; mrow[rb][1] = mn1;
#pragma unroll
            for (int nt = 0; nt < 8; nt++) {
                oac[rb][nt][0] *= c0; oac[rb][nt][1] *= c0;
                oac[rb][nt][2] *= c1; oac[rb][nt][3] *= c1;
            }
            float rs0 = 0.0f, rs1 = 0.0f;
#pragma unroll
            for (int nt = 0; nt < 8; nt++) {
                sc[rb][nt][0] = __expf(sc[rb][nt][0] - mn0);
                sc[rb][nt][1] = __expf(sc[rb][nt][1] - mn0);
                sc[rb][nt][2] = __expf(sc[rb][nt][2] - mn1);
                sc[rb][nt][3] = __expf(sc[rb][nt][3] - mn1);
                rs0 += sc[rb][nt][0] + sc[rb][nt][1];
                rs1 += sc[rb][nt][2] + sc[rb][nt][3];
            }
            rs0 += __shfl_xor_sync(0xffffffffu, rs0, 1);
            rs0 += __shfl_xor_sync(0xffffffffu, rs0, 2);
            rs1 += __shfl_xor_sync(0xffffffffu, rs1, 1);
            rs1 += __shfl_xor_sync(0xffffffffu, rs1, 2);
            lrow[rb][0] = lrow[rb][0] * c0 + rs0;
            lrow[rb][1] = lrow[rb][1] * c1 + rs1;
        }
        __syncwarp();   // all gathers done before P overwrites slabs

#pragma unroll
        for (int rb = 0; rb < 2; rb++) {
            float* sl = (rb == 0) ? sl0 : sl1;
#pragma unroll
            for (int nt = 0; nt < 8; nt++) {
                int j0 = nt * 8 + 2 * tg;
                sl[swz(g, j0)]         = f2tf32f(sc[rb][nt][0]);
                sl[swz(g, j0 + 1)]     = f2tf32f(sc[rb][nt][1]);
                sl[swz(g + 8, j0)]     = f2tf32f(sc[rb][nt][2]);
                sl[swz(g + 8, j0 + 1)] = f2tf32f(sc[rb][nt][3]);
            }
        }
        __syncwarp();

        // ---- PV: shared V B-frags across rbs ----
        uint32_t pf[2][8][4];
#pragma unroll
        for (int rb = 0; rb < 2; rb++) {
            float* sl = (rb == 0) ? sl0 : sl1;
#pragma unroll
            for (int ks = 0; ks < 8; ks++) {
                int c0c = ks * 8 + tg, c1c = c0c + 4;
                pf[rb][ks][0] = __float_as_uint(sl[swz(g, c0c)]);
                pf[rb][ks][1] = __float_as_uint(sl[swz(g + 8, c0c)]);
                pf[rb][ks][2] = __float_as_uint(sl[swz(g, c1c)]);
                pf[rb][ks][3] = __float_as_uint(sl[swz(g + 8, c1c)]);
            }
        }
#pragma unroll
        for (int nt = 0; nt < 8; nt++) {
            int n0 = nt * 8;
#pragma unroll
            for (int ks = 0; ks < 8; ks++) {
                uint32_t bf[2];
                bf[0] = __float_as_uint(Vs[swz(ks * 8 + tg, n0 + g)]);
                bf[1] = __float_as_uint(Vs[swz(ks * 8 + tg + 4, n0 + g)]);
                mma_tf32(oac[0][nt], pf[0][ks], bf);
                mma_tf32(oac[1][nt], pf[1][ks], bf);
            }
        }
    }

    // ---- Epilogue ----
#pragma unroll
    for (int rb = 0; rb < 2; rb++) {
        float inv0 = 1.0f / lrow[rb][0], inv1 = 1.0f / lrow[rb][1];
        int r0 = q0 + 32 * wid + 16 * rb + g, r1 = r0 + 8;
        size_t rowA = ((size_t)(b * SEQ + r0)) * DMODEL + h * DHEAD;
        size_t rowB = ((size_t)(b * SEQ + r1)) * DMODEL + h * DHEAD;
#pragma unroll
        for (int nt = 0; nt < 8; nt++) {
            int col = nt * 8 + 2 * tg;
            *(float2*)(ao + rowA + col) =
                make_float2(oac[rb][nt][0] * inv0, oac[rb][nt][1] * inv0);
            *(float2*)(ao + rowB + col) =
                make_float2(oac[rb][nt][2] * inv1, oac[rb][nt][3] * inv1);
        }
    }
}

// ---------------------------------------------------------------------------
extern "C" void kernel_launch(void* const* d_in, const int* in_sizes, int n_in,
                              void* d_out, int out_size) {
    const float* x          = (const float*)d_in[0];
    const unsigned char* mk = (const unsigned char*)d_in[1];
    const float* Wqkv       = (const float*)d_in[2];
    const float* Wpe        = (const float*)d_in[3];
    const float* Wo         = (const float*)d_in[4];
    const float* cb         = (const float*)d_in[5];
    const float* pb         = (const float*)d_in[6];
    float* out              = (float*)d_out;

    float *qkv, *pe, *pek, *ao, *pbias;
    cudaGetSymbolAddress((void**)&qkv, g_qkv);
    cudaGetSymbolAddress((void**)&pe,  g_pe);
    cudaGetSymbolAddress((void**)&pek, g_pek);
    cudaGetSymbolAddress((void**)&ao,  g_ao);
    cudaGetSymbolAddress((void**)&pbias, g_pbias);

    cudaFuncSetAttribute(gemm_mma_kernel,
                         cudaFuncAttributeMaxDynamicSharedMemorySize,
                         GEMM_SMEM_BYTES);
    cudaFuncSetAttribute(attn_mma3_kernel,
                         cudaFuncAttributeMaxDynamicSharedMemorySize,
                         A3_SMEM_BYTES);

    pegen_kernel<<<(LPE * DMODEL + 255) / 256, 256>>>(pe);

    {
        dim3 grid(3072 / 128, 4096 / 128);
        gemm_mma_kernel<<<grid, 256, GEMM_SMEM_BYTES>>>(x, Wqkv, qkv,
                                                        BSZ * SEQ, 3 * DMODEL, DMODEL);
    }
    {
        dim3 grid(1024 / 128, (LPE + 127) / 128);
        gemm_mma_kernel<<<grid, 256, GEMM_SMEM_BYTES>>>(pe, Wpe, pek,
                                                        LPE, DMODEL, DMODEL);
    }

    pbias_kernel<<<(NHEAD * 2048) / 256, 256>>>(pek, cb, pb, pbias);

    attn_mma3_kernel<<<BSZ * NHEAD * (SEQ / 256), 256, A3_SMEM_BYTES>>>(
        qkv, pek, mk, cb, pbias, ao);

    {
        dim3 grid(1024 / 128, 4096 / 128);
        gemm_mma_kernel<<<grid, 256, GEMM_SMEM_BYTES>>>(ao, Wo, out,
                                                        BSZ * SEQ, DMODEL, DMODEL);
    }
}

// round 8
// speedup vs baseline: 1.1276x; 1.0095x over previous
#include <cuda_runtime.h>
#include <cuda_bf16.h>
#include <cstdint>
#include <math.h>

// Problem constants
#define BSZ 4
#define SEQ 1024
#define DMODEL 1024
#define NHEAD 16
#define DHEAD 64
#define LPE 2045   // 2*s-1, s = 1023

// Scratch
__device__ float g_qkv[BSZ * SEQ * 3 * DMODEL];
__device__ float g_pe [LPE * DMODEL];
__device__ float g_pek[LPE * DMODEL];
__device__ float g_ao [BSZ * SEQ * DMODEL];
__device__ float g_pbias[NHEAD * 2048];   // (pb-cb) . pek[l], per head

// ---------------------------------------------------------------------------
__device__ __forceinline__ uint32_t f2tf32(float x) {
    uint32_t y;
    asm("cvt.rna.tf32.f32 %0, %1;" : "=r"(y) : "f"(x));
    return y;
}
__device__ __forceinline__ float f2tf32f(float x) {
    return __uint_as_float(f2tf32(x));
}

__device__ __forceinline__ void mma_tf32(float* d, const uint32_t* a,
                                         const uint32_t* b) {
    asm volatile(
        "mma.sync.aligned.m16n8k8.row.col.f32.tf32.tf32.f32 "
        "{%0,%1,%2,%3}, {%4,%5,%6,%7}, {%8,%9}, {%0,%1,%2,%3};\n"
        : "+f"(d[0]), "+f"(d[1]), "+f"(d[2]), "+f"(d[3])
        : "r"(a[0]), "r"(a[1]), "r"(a[2]), "r"(a[3]),
          "r"(b[0]), "r"(b[1]));
}

// XOR-swizzled 64-float row layout
__device__ __forceinline__ int swz(int row, int col) {
    return row * 64 + ((((col >> 2) ^ (row & 7)) << 2) | (col & 3));
}

// ---------------------------------------------------------------------------
__global__ void pegen_kernel(float* __restrict__ pe) {
    int idx = blockIdx.x * blockDim.x + threadIdx.x;
    if (idx >= LPE * DMODEL) return;
    int l  = idx >> 10;
    int kk = idx & 1023;
    int p2 = kk & ~1;
    float expnt = (float)p2 / 1024.0f;
    float denom = powf(10000.0f, expnt);
    float t = (float)(l - 1022);
    float ang = t / denom;
    float v = (kk & 1) ? cosf(ang) : sinf(ang);
    pe[idx] = v * 0.03125f;
}

// pbias[h][l] = sum_c (pb[h,c]-cb[h,c]) * pek[l, h*64+c]
__global__ void pbias_kernel(const float* __restrict__ pek,
                             const float* __restrict__ cb,
                             const float* __restrict__ pb,
                             float* __restrict__ pbias) {
    int idx = blockIdx.x * blockDim.x + threadIdx.x;
    if (idx >= NHEAD * 2048) return;
    int h = idx >> 11, l = idx & 2047;
    float s = 0.0f;
    if (l < LPE) {
        const float* row = pek + (size_t)l * DMODEL + h * DHEAD;
#pragma unroll 16
        for (int c = 0; c < DHEAD; c++)
            s += (pb[h * DHEAD + c] - cb[h * DHEAD + c]) * row[c];
    }
    pbias[idx] = s;
}

// ===========================================================================
// TF32 mma.sync GEMM (unchanged from R3)
// ===========================================================================
#define ASTR 36
#define BSTR 136
#define A_STAGE (128 * ASTR)
#define B_STAGE (32 * BSTR)
#define GEMM_SMEM_BYTES ((2 * A_STAGE + 2 * B_STAGE) * 4)

__global__ __launch_bounds__(256)
void gemm_mma_kernel(const float* __restrict__ A, const float* __restrict__ B,
                     float* __restrict__ C, int M, int N, int K) {
    extern __shared__ float sm[];
    float* AsBase = sm;
    float* BsBase = sm + 2 * A_STAGE;

    int tid  = threadIdx.x;
    int wid  = tid >> 5;
    int lane = tid & 31;
    int g    = lane >> 2;
    int tg   = lane & 3;
    int wm0  = (wid >> 2) * 64;
    int wn0  = (wid & 3) * 32;
    int bm = blockIdx.y * 128;
    int bn = blockIdx.x * 128;

    float acc[4][4][4];
#pragma unroll
    for (int mt = 0; mt < 4; mt++)
#pragma unroll
        for (int nt = 0; nt < 4; nt++)
#pragma unroll
            for (int r = 0; r < 4; r++) acc[mt][nt][r] = 0.0f;

    float4 pa[4], pb4[4];

    auto ldTile = [&](int k0) {
#pragma unroll
        for (int it = 0; it < 4; it++) {
            int l = tid + 256 * it;
            int row = l >> 3, c4 = (l & 7) << 2;
            int gr = bm + row;
            pa[it] = (gr < M)
                ? *(const float4*)(A + (size_t)gr * K + k0 + c4)
                : make_float4(0.f, 0.f, 0.f, 0.f);
        }
#pragma unroll
        for (int it = 0; it < 4; it++) {
            int l = tid + 256 * it;
            int kr = l >> 5, n4 = (l & 31) << 2;
            pb4[it] = *(const float4*)(B + (size_t)(k0 + kr) * N + bn + n4);
        }
    };

    auto stsTile = [&](int s) {
        float* as = AsBase + s * A_STAGE;
        float* bs = BsBase + s * B_STAGE;
#pragma unroll
        for (int it = 0; it < 4; it++) {
            int l = tid + 256 * it;
            int row = l >> 3, c4 = (l & 7) << 2;
            uint4 v = make_uint4(f2tf32(pa[it].x), f2tf32(pa[it].y),
                                 f2tf32(pa[it].z), f2tf32(pa[it].w));
            *(uint4*)(as + row * ASTR + c4) = v;
        }
#pragma unroll
        for (int it = 0; it < 4; it++) {
            int l = tid + 256 * it;
            int kr = l >> 5, n4 = (l & 31) << 2;
            uint4 v = make_uint4(f2tf32(pb4[it].x), f2tf32(pb4[it].y),
                                 f2tf32(pb4[it].z), f2tf32(pb4[it].w));
            *(uint4*)(bs + kr * BSTR + n4) = v;
        }
    };

    auto compute = [&](int s) {
        const float* as = AsBase + s * A_STAGE;
        const float* bs = BsBase + s * B_STAGE;
#pragma unroll
        for (int ks = 0; ks < 4; ks++) {
            int k8 = ks * 8;
            uint32_t af[4][4], bf[4][2];
#pragma unroll
            for (int mt = 0; mt < 4; mt++) {
                const float* p = as + (wm0 + mt * 16 + g) * ASTR + k8 + tg;
                af[mt][0] = __float_as_uint(p[0]);
                af[mt][1] = __float_as_uint(p[8 * ASTR]);
                af[mt][2] = __float_as_uint(p[4]);
                af[mt][3] = __float_as_uint(p[8 * ASTR + 4]);
            }
#pragma unroll
            for (int nt = 0; nt < 4; nt++) {
                const float* p = bs + (k8 + tg) * BSTR + wn0 + nt * 8 + g;
                bf[nt][0] = __float_as_uint(p[0]);
                bf[nt][1] = __float_as_uint(p[4 * BSTR]);
            }
#pragma unroll
            for (int mt = 0; mt < 4; mt++)
#pragma unroll
                for (int nt = 0; nt < 4; nt++)
                    mma_tf32(acc[mt][nt], af[mt], bf[nt]);
        }
    };

    int T = K >> 5;
    ldTile(0);
    stsTile(0);
    __syncthreads();

    for (int t = 0; t < T; t++) {
        int s = t & 1;
        if (t + 1 < T) ldTile((t + 1) << 5);
        compute(s);
        if (t + 1 < T) {
            stsTile(s ^ 1);
            __syncthreads();
        }
    }

#pragma unroll
    for (int mt = 0; mt < 4; mt++) {
        int r0 = bm + wm0 + mt * 16 + g;
        int r1 = r0 + 8;
#pragma unroll
        for (int nt = 0; nt < 4; nt++) {
            int col = bn + wn0 + nt * 8 + 2 * tg;
            if (r0 < M)
                *(float2*)(C + (size_t)r0 * N + col) =
                    make_float2(acc[mt][nt][0], acc[mt][nt][1]);
            if (r1 < M)
                *(float2*)(C + (size_t)r1 * N + col) =
                    make_float2(acc[mt][nt][2], acc[mt][nt][3]);
        }
    }
}

// ===========================================================================
// Attention v4: 512 threads, 16 warps x 16 q-rows = 256 q/CTA, 1 CTA/SM.
// PE ring buffer (384 slots, 64 rows staged/kt after prologue, prefetched
// overlapping compute).  Pos-bias folded into precomputed per-row bias.
// Smem (floats): Ks 4096 | Vs 4096 | PEl 384x64=24576 | Bias 384 | Msk 64 |
//                U 16x1344=21504 (Q staging then per-warp Spos/P slabs)
// Total 54720 floats = 218880 B -> 1 CTA/SM.
// ===========================================================================
#define A4_KS 0
#define A4_VS 4096
#define A4_PE 8192
#define A4_BIAS 32768
#define A4_MSK 33152
#define A4_U 33216
#define A4_SMEM_BYTES (54720 * 4)
#define SPAD 84
#define SLAB4 1344

__global__ __launch_bounds__(512, 1)
void attn_mma4_kernel(const float* __restrict__ qkv, const float* __restrict__ pek,
                      const unsigned char* __restrict__ mask,
                      const float* __restrict__ cb, const float* __restrict__ pbias,
                      float* __restrict__ ao) {
    extern __shared__ float sm[];
    float* Ks   = sm + A4_KS;
    float* Vs   = sm + A4_VS;
    float* PEl  = sm + A4_PE;
    float* Bias = sm + A4_BIAS;
    float* Msk  = sm + A4_MSK;
    float* U    = sm + A4_U;

    int tid = threadIdx.x;
    int w = tid >> 5;
    int lane = tid & 31;
    int g = lane >> 2;
    int tg = lane & 3;
    int qt = blockIdx.x & 3;
    int bh = blockIdx.x >> 2;
    int h  = bh & 15;
    int b  = bh >> 4;
    int q0 = qt * 256;

    const float* cbh = cb + h * DHEAD;
    const float* pbh_bias = pbias + h * 2048;
    int lbase0 = 767 - q0;

    // ---- Prologue: stage Qc (256 rows), PE slots [0,320), Bias [0,320) ----
    for (int idx = tid; idx < 4096; idx += 512) {
        int i = idx >> 4, cc = idx & 15;
        int c4 = cc * 4;
        const float* src = qkv + ((size_t)(b * SEQ + q0 + i)) * 3072 + h * 192 + c4;
        float4 v = *(const float4*)src;
        int sa = i * 64 + ((cc ^ (i & 7)) << 2);
        U[sa + 0] = f2tf32f(v.x + cbh[c4 + 0]);
        U[sa + 1] = f2tf32f(v.y + cbh[c4 + 1]);
        U[sa + 2] = f2tf32f(v.z + cbh[c4 + 2]);
        U[sa + 3] = f2tf32f(v.w + cbh[c4 + 3]);
    }
    for (int idx = tid; idx < 5120; idx += 512) {
        int sl_ = idx >> 4, cc = idx & 15;
        int lg = lbase0 + sl_;
        float4 v = (lg >= 0 && lg < LPE)
            ? *(const float4*)(pek + (size_t)lg * DMODEL + h * DHEAD + cc * 4)
            : make_float4(0.f, 0.f, 0.f, 0.f);
        int sa = sl_ * 64 + ((cc ^ (sl_ & 7)) << 2);
        PEl[sa + 0] = f2tf32f(v.x); PEl[sa + 1] = f2tf32f(v.y);
        PEl[sa + 2] = f2tf32f(v.z); PEl[sa + 3] = f2tf32f(v.w);
    }
    if (tid < 320) {
        int lg = lbase0 + tid;
        Bias[tid] = (lg >= 0 && lg < LPE) ? pbh_bias[lg] : 0.0f;
    }
    __syncthreads();

    // ---- Persist Qc fragments (16 rows: g, g+8 within warp window) ----
    uint32_t qcf[8][4];
    int r0l = 16 * w + g, r1l = r0l + 8;
#pragma unroll
    for (int ks = 0; ks < 8; ks++) {
        int c0 = ks * 8 + tg, c1 = c0 + 4;
        qcf[ks][0] = __float_as_uint(U[swz(r0l, c0)]);
        qcf[ks][1] = __float_as_uint(U[swz(r1l, c0)]);
        qcf[ks][2] = __float_as_uint(U[swz(r0l, c1)]);
        qcf[ks][3] = __float_as_uint(U[swz(r1l, c1)]);
    }
    __syncthreads();

    bool zq0 = (q0 == 0 && w == 0 && g == 0);  // global q-row 0

    float oac[8][4];
#pragma unroll
    for (int nt = 0; nt < 8; nt++)
#pragma unroll
        for (int r = 0; r < 4; r++) oac[nt][r] = 0.0f;
    float m0 = -1e30f, m1 = -1e30f, l0 = 0.0f, l1 = 0.0f;

    float* slab = U + w * SLAB4;
    int s0base = 30 - 2 * w;     // first PE tile index (10 tiles per warp)

    for (int kt = 0; kt < 16; kt++) {
        int k0 = kt * 64;
        int ktm = (64 * kt) % 384;
        __syncthreads();   // prior compute reads + prior PE prefetch done

        // ---- Stage K, V (64 rows), mask ----
        for (int idx = tid; idx < 1024; idx += 512) {
            int i = idx >> 4, cc = idx & 15;
            const float* base = qkv + ((size_t)(b * SEQ + k0 + i)) * 3072 + h * 192;
            float4 kv = *(const float4*)(base + 64 + cc * 4);
            float4 vv = *(const float4*)(base + 128 + cc * 4);
            int sa = i * 64 + ((cc ^ (i & 7)) << 2);
            Ks[sa + 0] = f2tf32f(kv.x); Ks[sa + 1] = f2tf32f(kv.y);
            Ks[sa + 2] = f2tf32f(kv.z); Ks[sa + 3] = f2tf32f(kv.w);
            Vs[sa + 0] = f2tf32f(vv.x); Vs[sa + 1] = f2tf32f(vv.y);
            Vs[sa + 2] = f2tf32f(vv.z); Vs[sa + 3] = f2tf32f(vv.w);
        }
        if (tid < 64) Msk[tid] = mask[b * SEQ + k0 + tid] ? -1e30f : 0.0f;
        __syncthreads();

        // ---- PE ring prefetch for kt+1 (slots unread this kt; next
        //      __syncthreads orders completion). Overlaps compute. ----
        if (kt < 15) {
            for (int idx = tid; idx < 1024; idx += 512) {
                int r = idx >> 4, cc = idx & 15;
                int off = 64 * kt + 320 + r;             // absolute band offset
                int slot = off % 384;
                int lg = lbase0 + off;
                float4 v = (lg >= 0 && lg < LPE)
                    ? *(const float4*)(pek + (size_t)lg * DMODEL + h * DHEAD + cc * 4)
                    : make_float4(0.f, 0.f, 0.f, 0.f);
                int sa = slot * 64 + ((cc ^ (slot & 7)) << 2);
                PEl[sa + 0] = f2tf32f(v.x); PEl[sa + 1] = f2tf32f(v.y);
                PEl[sa + 2] = f2tf32f(v.z); PEl[sa + 3] = f2tf32f(v.w);
            }
            if (tid < 64) {
                int off = 64 * kt + 320 + tid;
                int lg = lbase0 + off;
                Bias[off % 384] = (lg >= 0 && lg < LPE) ? pbh_bias[lg] : 0.0f;
            }
        }

        // ---- Band: Spos = Qc @ PE^T + bias (10 tiles) ----
#pragma unroll
        for (int t = 0; t < 10; t++) {
            int m = s0base + t;
            int sr = ktm + 8 * m; if (sr >= 384) sr -= 384;
            int br = sr + g;
            float sp[4] = {0.f, 0.f, 0.f, 0.f};
#pragma unroll
            for (int ks = 0; ks < 8; ks++) {
                uint32_t bf[2];
                bf[0] = __float_as_uint(PEl[swz(br, ks * 8 + tg)]);
                bf[1] = __float_as_uint(PEl[swz(br, ks * 8 + tg + 4)]);
                mma_tf32(sp, qcf[ks], bf);
            }
            int bidx = ktm + 8 * m + 2 * tg; if (bidx >= 384) bidx -= 384;
            float b0 = Bias[bidx], b1 = Bias[bidx + 1];
            int cc0 = 8 * t + 2 * tg;
            slab[g * SPAD + cc0]           = sp[0] + b0;
            slab[g * SPAD + cc0 + 1]       = sp[1] + b1;
            slab[(g + 8) * SPAD + cc0]     = sp[2] + b0;
            slab[(g + 8) * SPAD + cc0 + 1] = sp[3] + b1;
        }
        __syncwarp();

        // ---- Content scores: Qc @ K^T ----
        float sc[8][4];
#pragma unroll
        for (int nt = 0; nt < 8; nt++) {
            int n0 = nt * 8;
            sc[nt][0] = sc[nt][1] = sc[nt][2] = sc[nt][3] = 0.0f;
#pragma unroll
            for (int ks = 0; ks < 8; ks++) {
                uint32_t bf[2];
                bf[0] = __float_as_uint(Ks[swz(n0 + g, ks * 8 + tg)]);
                bf[1] = __float_as_uint(Ks[swz(n0 + g, ks * 8 + tg + 4)]);
                mma_tf32(sc[nt], qcf[ks], bf);
            }
        }

        // ---- Gather band diag + combine + mask + row max ----
        float mt0 = -1e30f, mt1 = -1e30f;
#pragma unroll
        for (int nt = 0; nt < 8; nt++) {
            int j0 = nt * 8 + 2 * tg;
            int c00 = j0 - g + 15;
            int c10 = j0 - g + 7;
            float p0 = slab[g * SPAD + c00];
            float p1 = slab[g * SPAD + c00 + 1];
            float p2 = slab[(g + 8) * SPAD + c10];
            float p3 = slab[(g + 8) * SPAD + c10 + 1];
            if (kt == 0 && nt == 0 && tg == 0) { p0 = 0.0f; p2 = 0.0f; } // key 0
            if (zq0) { p0 = 0.0f; p1 = 0.0f; }                           // q-row 0
            float mk0 = Msk[j0], mk1 = Msk[j0 + 1];
            sc[nt][0] = (sc[nt][0] + p0) * 0.125f + mk0;
            sc[nt][1] = (sc[nt][1] + p1) * 0.125f + mk1;
            sc[nt][2] = (sc[nt][2] + p2) * 0.125f + mk0;
            sc[nt][3] = (sc[nt][3] + p3) * 0.125f + mk1;
            mt0 = fmaxf(mt0, fmaxf(sc[nt][0], sc[nt][1]));
            mt1 = fmaxf(mt1, fmaxf(sc[nt][2], sc[nt][3]));
        }
        mt0 = fmaxf(mt0, __shfl_xor_sync(0xffffffffu, mt0, 1));
        mt0 = fmaxf(mt0, __shfl_xor_sync(0xffffffffu, mt0, 2));
        mt1 = fmaxf(mt1, __shfl_xor_sync(0xffffffffu, mt1, 1));
        mt1 = fmaxf(mt1, __shfl_xor_sync(0xffffffffu, mt1, 2));

        // ---- Online softmax ----
        float mn0 = fmaxf(m0, mt0), mn1 = fmaxf(m1, mt1);
        float c0 = __expf(m0 - mn0), c1 = __expf(m1 - mn1);
        m0 = mn0; m1 = mn1;
#pragma unroll
        for (int nt = 0; nt < 8; nt++) {
            oac[nt][0] *= c0; oac[nt][1] *= c0;
            oac[nt][2] *= c1; oac[nt][3] *= c1;
        }
        float rs0 = 0.0f, rs1 = 0.0f;
#pragma unroll
        for (int nt = 0; nt < 8; nt++) {
            sc[nt][0] = __expf(sc[nt][0] - mn0);
            sc[nt][1] = __expf(sc[nt][1] - mn0);
            sc[nt][2] = __expf(sc[nt][2] - mn1);
            sc[nt][3] = __expf(sc[nt][3] - mn1);
            rs0 += sc[nt][0] + sc[nt][1];
            rs1 += sc[nt][2] + sc[nt][3];
        }
        rs0 += __shfl_xor_sync(0xffffffffu, rs0, 1);
        rs0 += __shfl_xor_sync(0xffffffffu, rs0, 2);
        rs1 += __shfl_xor_sync(0xffffffffu, rs1, 1);
        rs1 += __shfl_xor_sync(0xffffffffu, rs1, 2);
        l0 = l0 * c0 + rs0;
        l1 = l1 * c1 + rs1;

        __syncwarp();   // gathers done before P overwrites slab

        // ---- Write P (16 rows, swizzled, tf32) ----
#pragma unroll
        for (int nt = 0; nt < 8; nt++) {
            int j0 = nt * 8 + 2 * tg;
            slab[swz(g, j0)]         = f2tf32f(sc[nt][0]);
            slab[swz(g, j0 + 1)]     = f2tf32f(sc[nt][1]);
            slab[swz(g + 8, j0)]     = f2tf32f(sc[nt][2]);
            slab[swz(g + 8, j0 + 1)] = f2tf32f(sc[nt][3]);
        }
        __syncwarp();

        // ---- O += P @ V ----
        uint32_t pf[8][4];
#pragma unroll
        for (int ks = 0; ks < 8; ks++) {
            int c0c = ks * 8 + tg, c1c = c0c + 4;
            pf[ks][0] = __float_as_uint(slab[swz(g, c0c)]);
            pf[ks][1] = __float_as_uint(slab[swz(g + 8, c0c)]);
            pf[ks][2] = __float_as_uint(slab[swz(g, c1c)]);
            pf[ks][3] = __float_as_uint(slab[swz(g + 8, c1c)]);
        }
#pragma unroll
        for (int nt = 0; nt < 8; nt++) {
            int n0 = nt * 8;
#pragma unroll
            for (int ks = 0; ks < 8; ks++) {
                uint32_t bf[2];
                bf[0] = __float_as_uint(Vs[swz(ks * 8 + tg, n0 + g)]);
                bf[1] = __float_as_uint(Vs[swz(ks * 8 + tg + 4, n0 + g)]);
                mma_tf32(oac[nt], pf[ks], bf);
            }
        }
    }

    // ---- Epilogue ----
    float inv0 = 1.0f / l0, inv1 = 1.0f / l1;
    int r0 = q0 + r0l, r1 = q0 + r1l;
    size_t rowA = ((size_t)(b * SEQ + r0)) * DMODEL + h * DHEAD;
    size_t rowB = ((size_t)(b * SEQ + r1)) * DMODEL + h * DHEAD;
#pragma unroll
    for (int nt = 0; nt < 8; nt++) {
        int col = nt * 8 + 2 * tg;
        *(float2*)(ao + rowA + col) =
            make_float2(oac[nt][0] * inv0, oac[nt][1] * inv0);
        *(float2*)(ao + rowB + col) =
            make_float2(oac[nt][2] * inv1, oac[nt][3] * inv1);
    }
}

// ---------------------------------------------------------------------------
extern "C" void kernel_launch(void* const* d_in, const int* in_sizes, int n_in,
                              void* d_out, int out_size) {
    const float* x          = (const float*)d_in[0];
    const unsigned char* mk = (const unsigned char*)d_in[1];
    const float* Wqkv       = (const float*)d_in[2];
    const float* Wpe        = (const float*)d_in[3];
    const float* Wo         = (const float*)d_in[4];
    const float* cb         = (const float*)d_in[5];
    const float* pb         = (const float*)d_in[6];
    float* out              = (float*)d_out;

    float *qkv, *pe, *pek, *ao, *pbias;
    cudaGetSymbolAddress((void**)&qkv, g_qkv);
    cudaGetSymbolAddress((void**)&pe,  g_pe);
    cudaGetSymbolAddress((void**)&pek, g_pek);
    cudaGetSymbolAddress((void**)&ao,  g_ao);
    cudaGetSymbolAddress((void**)&pbias, g_pbias);

    cudaFuncSetAttribute(gemm_mma_kernel,
                         cudaFuncAttributeMaxDynamicSharedMemorySize,
                         GEMM_SMEM_BYTES);
    cudaFuncSetAttribute(attn_mma4_kernel,
                         cudaFuncAttributeMaxDynamicSharedMemorySize,
                         A4_SMEM_BYTES);

    pegen_kernel<<<(LPE * DMODEL + 255) / 256, 256>>>(pe);

    {
        dim3 grid(3072 / 128, 4096 / 128);
        gemm_mma_kernel<<<grid, 256, GEMM_SMEM_BYTES>>>(x, Wqkv, qkv,
                                                        BSZ * SEQ, 3 * DMODEL, DMODEL);
    }
    {
        dim3 grid(1024 / 128, (LPE + 127) / 128);
        gemm_mma_kernel<<<grid, 256, GEMM_SMEM_BYTES>>>(pe, Wpe, pek,
                                                        LPE, DMODEL, DMODEL);
    }

    pbias_kernel<<<(NHEAD * 2048) / 256, 256>>>(pek, cb, pb, pbias);

    attn_mma4_kernel<<<BSZ * NHEAD * (SEQ / 256), 512, A4_SMEM_BYTES>>>(
        qkv, pek, mk, cb, pbias, ao);

    {
        dim3 grid(1024 / 128, 4096 / 128);
        gemm_mma_kernel<<<grid, 256, GEMM_SMEM_BYTES>>>(ao, Wo, out,
                                                        BSZ * SEQ, DMODEL, DMODEL);
    }
}

// round 9
// speedup vs baseline: 1.2347x; 1.0950x over previous
#include <cuda_runtime.h>
#include <cuda_bf16.h>
#include <cuda_fp16.h>
#include <cstdint>
#include <math.h>

// Problem constants
#define BSZ 4
#define SEQ 1024
#define DMODEL 1024
#define NHEAD 16
#define DHEAD 64
#define LPE 2045   // 2*s-1, s = 1023

// Scratch
__device__ float g_qkv[BSZ * SEQ * 3 * DMODEL];
__device__ float g_pe [LPE * DMODEL];
__device__ float g_pek[LPE * DMODEL];
__device__ float g_ao [BSZ * SEQ * DMODEL];
__device__ float g_pbias[NHEAD * 2048];   // (pb-cb) . pek[l], per head

// ---------------------------------------------------------------------------
__device__ __forceinline__ uint32_t f2tf32(float x) {
    uint32_t y;
    asm("cvt.rna.tf32.f32 %0, %1;" : "=r"(y) : "f"(x));
    return y;
}

__device__ __forceinline__ void mma_tf32(float* d, const uint32_t* a,
                                         const uint32_t* b) {
    asm volatile(
        "mma.sync.aligned.m16n8k8.row.col.f32.tf32.tf32.f32 "
        "{%0,%1,%2,%3}, {%4,%5,%6,%7}, {%8,%9}, {%0,%1,%2,%3};\n"
        : "+f"(d[0]), "+f"(d[1]), "+f"(d[2]), "+f"(d[3])
        : "r"(a[0]), "r"(a[1]), "r"(a[2]), "r"(a[3]),
          "r"(b[0]), "r"(b[1]));
}

// fp16 m16n8k16, fp32 accumulate
__device__ __forceinline__ void mma_f16(float* d, const uint32_t* a,
                                        const uint32_t* b) {
    asm volatile(
        "mma.sync.aligned.m16n8k16.row.col.f32.f16.f16.f32 "
        "{%0,%1,%2,%3}, {%4,%5,%6,%7}, {%8,%9}, {%0,%1,%2,%3};\n"
        : "+f"(d[0]), "+f"(d[1]), "+f"(d[2]), "+f"(d[3])
        : "r"(a[0]), "r"(a[1]), "r"(a[2]), "r"(a[3]),
          "r"(b[0]), "r"(b[1]));
}

__device__ __forceinline__ uint32_t pack_h2(float x, float y) {
    __half2 h = __floats2half2_rn(x, y);
    return *(uint32_t*)&h;
}

// XOR-swizzled 32-u32 (128B) row layout for fp16 tiles
__device__ __forceinline__ int swz32(int row, int cp) {
    return row * 32 + ((((cp >> 2) ^ (row & 7)) << 2) | (cp & 3));
}

// ---------------------------------------------------------------------------
__global__ void pegen_kernel(float* __restrict__ pe) {
    int idx = blockIdx.x * blockDim.x + threadIdx.x;
    if (idx >= LPE * DMODEL) return;
    int l  = idx >> 10;
    int kk = idx & 1023;
    int p2 = kk & ~1;
    float expnt = (float)p2 / 1024.0f;
    float denom = powf(10000.0f, expnt);
    float t = (float)(l - 1022);
    float ang = t / denom;
    float v = (kk & 1) ? cosf(ang) : sinf(ang);
    pe[idx] = v * 0.03125f;
}

// pbias[h][l] = sum_c (pb[h,c]-cb[h,c]) * pek[l, h*64+c]
__global__ void pbias_kernel(const float* __restrict__ pek,
                             const float* __restrict__ cb,
                             const float* __restrict__ pb,
                             float* __restrict__ pbias) {
    int idx = blockIdx.x * blockDim.x + threadIdx.x;
    if (idx >= NHEAD * 2048) return;
    int h = idx >> 11, l = idx & 2047;
    float s = 0.0f;
    if (l < LPE) {
        const float* row = pek + (size_t)l * DMODEL + h * DHEAD;
#pragma unroll 16
        for (int c = 0; c < DHEAD; c++)
            s += (pb[h * DHEAD + c] - cb[h * DHEAD + c]) * row[c];
    }
    pbias[idx] = s;
}

// ===========================================================================
// TF32 mma.sync GEMM (unchanged, passing at 4.5e-4)
// ===========================================================================
#define ASTR 36
#define BSTR 136
#define A_STAGE (128 * ASTR)
#define B_STAGE (32 * BSTR)
#define GEMM_SMEM_BYTES ((2 * A_STAGE + 2 * B_STAGE) * 4)

__global__ __launch_bounds__(256)
void gemm_mma_kernel(const float* __restrict__ A, const float* __restrict__ B,
                     float* __restrict__ C, int M, int N, int K) {
    extern __shared__ float sm[];
    float* AsBase = sm;
    float* BsBase = sm + 2 * A_STAGE;

    int tid  = threadIdx.x;
    int wid  = tid >> 5;
    int lane = tid & 31;
    int g    = lane >> 2;
    int tg   = lane & 3;
    int wm0  = (wid >> 2) * 64;
    int wn0  = (wid & 3) * 32;
    int bm = blockIdx.y * 128;
    int bn = blockIdx.x * 128;

    float acc[4][4][4];
#pragma unroll
    for (int mt = 0; mt < 4; mt++)
#pragma unroll
        for (int nt = 0; nt < 4; nt++)
#pragma unroll
            for (int r = 0; r < 4; r++) acc[mt][nt][r] = 0.0f;

    float4 pa[4], pb4[4];

    auto ldTile = [&](int k0) {
#pragma unroll
        for (int it = 0; it < 4; it++) {
            int l = tid + 256 * it;
            int row = l >> 3, c4 = (l & 7) << 2;
            int gr = bm + row;
            pa[it] = (gr < M)
                ? *(const float4*)(A + (size_t)gr * K + k0 + c4)
                : make_float4(0.f, 0.f, 0.f, 0.f);
        }
#pragma unroll
        for (int it = 0; it < 4; it++) {
            int l = tid + 256 * it;
            int kr = l >> 5, n4 = (l & 31) << 2;
            pb4[it] = *(const float4*)(B + (size_t)(k0 + kr) * N + bn + n4);
        }
    };

    auto stsTile = [&](int s) {
        float* as = AsBase + s * A_STAGE;
        float* bs = BsBase + s * B_STAGE;
#pragma unroll
        for (int it = 0; it < 4; it++) {
            int l = tid + 256 * it;
            int row = l >> 3, c4 = (l & 7) << 2;
            uint4 v = make_uint4(f2tf32(pa[it].x), f2tf32(pa[it].y),
                                 f2tf32(pa[it].z), f2tf32(pa[it].w));
            *(uint4*)(as + row * ASTR + c4) = v;
        }
#pragma unroll
        for (int it = 0; it < 4; it++) {
            int l = tid + 256 * it;
            int kr = l >> 5, n4 = (l & 31) << 2;
            uint4 v = make_uint4(f2tf32(pb4[it].x), f2tf32(pb4[it].y),
                                 f2tf32(pb4[it].z), f2tf32(pb4[it].w));
            *(uint4*)(bs + kr * BSTR + n4) = v;
        }
    };

    auto compute = [&](int s) {
        const float* as = AsBase + s * A_STAGE;
        const float* bs = BsBase + s * B_STAGE;
#pragma unroll
        for (int ks = 0; ks < 4; ks++) {
            int k8 = ks * 8;
            uint32_t af[4][4], bf[4][2];
#pragma unroll
            for (int mt = 0; mt < 4; mt++) {
                const float* p = as + (wm0 + mt * 16 + g) * ASTR + k8 + tg;
                af[mt][0] = __float_as_uint(p[0]);
                af[mt][1] = __float_as_uint(p[8 * ASTR]);
                af[mt][2] = __float_as_uint(p[4]);
                af[mt][3] = __float_as_uint(p[8 * ASTR + 4]);
            }
#pragma unroll
            for (int nt = 0; nt < 4; nt++) {
                const float* p = bs + (k8 + tg) * BSTR + wn0 + nt * 8 + g;
                bf[nt][0] = __float_as_uint(p[0]);
                bf[nt][1] = __float_as_uint(p[4 * BSTR]);
            }
#pragma unroll
            for (int mt = 0; mt < 4; mt++)
#pragma unroll
                for (int nt = 0; nt < 4; nt++)
                    mma_tf32(acc[mt][nt], af[mt], bf[nt]);
        }
    };

    int T = K >> 5;
    ldTile(0);
    stsTile(0);
    __syncthreads();

    for (int t = 0; t < T; t++) {
        int s = t & 1;
        if (t + 1 < T) ldTile((t + 1) << 5);
        compute(s);
        if (t + 1 < T) {
            stsTile(s ^ 1);
            __syncthreads();
        }
    }

#pragma unroll
    for (int mt = 0; mt < 4; mt++) {
        int r0 = bm + wm0 + mt * 16 + g;
        int r1 = r0 + 8;
#pragma unroll
        for (int nt = 0; nt < 4; nt++) {
            int col = bn + wn0 + nt * 8 + 2 * tg;
            if (r0 < M)
                *(float2*)(C + (size_t)r0 * N + col) =
                    make_float2(acc[mt][nt][0], acc[mt][nt][1]);
            if (r1 < M)
                *(float2*)(C + (size_t)r1 * N + col) =
                    make_float2(acc[mt][nt][2], acc[mt][nt][3]);
        }
    }
}

// ===========================================================================
// Attention v5: fp16 m16n8k16.  512 threads, 16 warps x 16 q-rows, 1 CTA/SM.
// All tiles half2-packed in 128B XOR-swizzled rows (32 u32/row).
// V staged transposed (Vt[c][jp], key-pairs) for the PV B-fragment.
// Smem (u32): Ks 2048 | Vt 2048 | PEl 384x32=12288 | Bias 384 | Msk 64 |
//             U 21504 (Q staging 8192 u32, then per-warp 1344-float slabs)
// Total 38336 u32 = 153344 B -> 1 CTA/SM.
// ===========================================================================
#define A5_KS 0
#define A5_VT 2048
#define A5_PE 4096
#define A5_BIAS 16384
#define A5_MSK 16768
#define A5_U 16832
#define A5_SMEM_BYTES (38336 * 4)
#define SPAD 84
#define SLAB5 1344

__global__ __launch_bounds__(512, 1)
void attn_mma5_kernel(const float* __restrict__ qkv, const float* __restrict__ pek,
                      const unsigned char* __restrict__ mask,
                      const float* __restrict__ cb, const float* __restrict__ pbias,
                      float* __restrict__ ao) {
    extern __shared__ float sm[];
    uint32_t* Ksu  = (uint32_t*)sm + A5_KS;
    uint32_t* Vtu  = (uint32_t*)sm + A5_VT;
    uint32_t* PElu = (uint32_t*)sm + A5_PE;
    float* Bias = sm + A5_BIAS;
    float* Msk  = sm + A5_MSK;
    float* U    = sm + A5_U;
    uint32_t* Qs = (uint32_t*)U;

    int tid = threadIdx.x;
    int w = tid >> 5;
    int lane = tid & 31;
    int g = lane >> 2;
    int tg = lane & 3;
    int qt = blockIdx.x & 3;
    int bh = blockIdx.x >> 2;
    int h  = bh & 15;
    int b  = bh >> 4;
    int q0 = qt * 256;

    const float* cbh = cb + h * DHEAD;
    const float* pbh_bias = pbias + h * 2048;
    int lbase0 = 767 - q0;

    // ---- Prologue: stage Qc (256 rows, fp16), PE slots [0,320), Bias ----
    for (int idx = tid; idx < 2048; idx += 512) {
        int i = idx >> 3, gq = idx & 7;
        int c8 = gq * 8;
        const float* src = qkv + ((size_t)(b * SEQ + q0 + i)) * 3072 + h * 192 + c8;
        float4 v0 = *(const float4*)src;
        float4 v1 = *(const float4*)(src + 4);
        uint4 o;
        o.x = pack_h2(v0.x + cbh[c8 + 0], v0.y + cbh[c8 + 1]);
        o.y = pack_h2(v0.z + cbh[c8 + 2], v0.w + cbh[c8 + 3]);
        o.z = pack_h2(v1.x + cbh[c8 + 4], v1.y + cbh[c8 + 5]);
        o.w = pack_h2(v1.z + cbh[c8 + 6], v1.w + cbh[c8 + 7]);
        *(uint4*)(Qs + i * 32 + ((gq ^ (i & 7)) << 2)) = o;
    }
    for (int idx = tid; idx < 2560; idx += 512) {
        int sl_ = idx >> 3, gq = idx & 7;
        int lg = lbase0 + sl_;
        float4 v0, v1;
        if (lg >= 0 && lg < LPE) {
            const float* p = pek + (size_t)lg * DMODEL + h * DHEAD + gq * 8;
            v0 = *(const float4*)p; v1 = *(const float4*)(p + 4);
        } else {
            v0 = make_float4(0.f, 0.f, 0.f, 0.f); v1 = v0;
        }
        uint4 o;
        o.x = pack_h2(v0.x, v0.y); o.y = pack_h2(v0.z, v0.w);
        o.z = pack_h2(v1.x, v1.y); o.w = pack_h2(v1.z, v1.w);
        *(uint4*)(PElu + sl_ * 32 + ((gq ^ (sl_ & 7)) << 2)) = o;
    }
    if (tid < 320) {
        int lg = lbase0 + tid;
        Bias[tid] = (lg >= 0 && lg < LPE) ? pbh_bias[lg] : 0.0f;
    }
    __syncthreads();

    // ---- Persist Qc fragments (rows g, g+8 of this warp's 16) ----
    uint32_t qcf[4][4];
    int r0l = 16 * w + g, r1l = r0l + 8;
#pragma unroll
    for (int kc = 0; kc < 4; kc++) {
        qcf[kc][0] = Qs[swz32(r0l, 8 * kc + tg)];
        qcf[kc][1] = Qs[swz32(r1l, 8 * kc + tg)];
        qcf[kc][2] = Qs[swz32(r0l, 8 * kc + tg + 4)];
        qcf[kc][3] = Qs[swz32(r1l, 8 * kc + tg + 4)];
    }
    __syncthreads();

    bool zq0 = (q0 == 0 && w == 0 && g == 0);  // global q-row 0

    float oac[8][4];
#pragma unroll
    for (int nt = 0; nt < 8; nt++)
#pragma unroll
        for (int r = 0; r < 4; r++) oac[nt][r] = 0.0f;
    float m0 = -1e30f, m1 = -1e30f, l0 = 0.0f, l1 = 0.0f;

    float* slab = U + w * SLAB5;
    uint32_t* P32 = (uint32_t*)slab;
    int s0base = 30 - 2 * w;

    for (int kt = 0; kt < 16; kt++) {
        int k0 = kt * 64;
        int ktm = (64 * kt) % 384;
        __syncthreads();   // prior compute reads + prior PE prefetch done

        // ---- Stage K (row-major halves) ----
        {
            int i = tid >> 3, gq = tid & 7;
            const float* base = qkv + ((size_t)(b * SEQ + k0 + i)) * 3072
                                + h * 192 + 64 + gq * 8;
            float4 v0 = *(const float4*)base;
            float4 v1 = *(const float4*)(base + 4);
            uint4 o;
            o.x = pack_h2(v0.x, v0.y); o.y = pack_h2(v0.z, v0.w);
            o.z = pack_h2(v1.x, v1.y); o.w = pack_h2(v1.z, v1.w);
            *(uint4*)(Ksu + i * 32 + ((gq ^ (i & 7)) << 2)) = o;
        }
        // ---- Stage V transposed: Vt[c][jp] = {V[2jp][c], V[2jp+1][c]} ----
        for (int idx = tid; idx < 2048; idx += 512) {
            int jp = idx >> 6, c = idx & 63;
            const float* vsrc = qkv + ((size_t)(b * SEQ + k0 + 2 * jp)) * 3072
                                + h * 192 + 128 + c;
            Vtu[swz32(c, jp)] = pack_h2(vsrc[0], vsrc[3072]);
        }
        if (tid < 64) Msk[tid] = mask[b * SEQ + k0 + tid] ? -1e30f : 0.0f;
        __syncthreads();

        // ---- PE ring prefetch for kt+1 (overlaps compute) ----
        if (kt < 15) {
            {
                int r = tid >> 3, gq = tid & 7;
                int off = 64 * kt + 320 + r;
                int slot = off % 384;
                int lg = lbase0 + off;
                float4 v0, v1;
                if (lg >= 0 && lg < LPE) {
                    const float* p = pek + (size_t)lg * DMODEL + h * DHEAD + gq * 8;
                    v0 = *(const float4*)p; v1 = *(const float4*)(p + 4);
                } else {
                    v0 = make_float4(0.f, 0.f, 0.f, 0.f); v1 = v0;
                }
                uint4 o;
                o.x = pack_h2(v0.x, v0.y); o.y = pack_h2(v0.z, v0.w);
                o.z = pack_h2(v1.x, v1.y); o.w = pack_h2(v1.z, v1.w);
                *(uint4*)(PElu + slot * 32 + ((gq ^ (slot & 7)) << 2)) = o;
            }
            if (tid < 64) {
                int off = 64 * kt + 320 + tid;
                int lg = lbase0 + off;
                Bias[off % 384] = (lg >= 0 && lg < LPE) ? pbh_bias[lg] : 0.0f;
            }
        }

        // ---- Band: Spos = Qc @ PE^T + bias (10 tiles, 4 kc each) ----
#pragma unroll
        for (int t = 0; t < 10; t++) {
            int m = s0base + t;
            int sr = ktm + 8 * m; if (sr >= 384) sr -= 384;
            int br = sr + g;
            float sp[4] = {0.f, 0.f, 0.f, 0.f};
#pragma unroll
            for (int kc = 0; kc < 4; kc++) {
                uint32_t bf[2];
                bf[0] = PElu[swz32(br, 8 * kc + tg)];
                bf[1] = PElu[swz32(br, 8 * kc + tg + 4)];
                mma_f16(sp, qcf[kc], bf);
            }
            int bidx = ktm + 8 * m + 2 * tg; if (bidx >= 384) bidx -= 384;
            float b0 = Bias[bidx], b1 = Bias[bidx + 1];
            int cc0 = 8 * t + 2 * tg;
            slab[g * SPAD + cc0]           = sp[0] + b0;
            slab[g * SPAD + cc0 + 1]       = sp[1] + b1;
            slab[(g + 8) * SPAD + cc0]     = sp[2] + b0;
            slab[(g + 8) * SPAD + cc0 + 1] = sp[3] + b1;
        }
        __syncwarp();

        // ---- Content scores: Qc @ K^T ----
        float sc[8][4];
#pragma unroll
        for (int nt = 0; nt < 8; nt++) {
            int n0 = nt * 8;
            sc[nt][0] = sc[nt][1] = sc[nt][2] = sc[nt][3] = 0.0f;
#pragma unroll
            for (int kc = 0; kc < 4; kc++) {
                uint32_t bf[2];
                bf[0] = Ksu[swz32(n0 + g, 8 * kc + tg)];
                bf[1] = Ksu[swz32(n0 + g, 8 * kc + tg + 4)];
                mma_f16(sc[nt], qcf[kc], bf);
            }
        }

        // ---- Gather band diag + combine + mask + row max ----
        float mt0 = -1e30f, mt1 = -1e30f;
#pragma unroll
        for (int nt = 0; nt < 8; nt++) {
            int j0 = nt * 8 + 2 * tg;
            int c00 = j0 - g + 15;
            int c10 = j0 - g + 7;
            float p0 = slab[g * SPAD + c00];
            float p1 = slab[g * SPAD + c00 + 1];
            float p2 = slab[(g + 8) * SPAD + c10];
            float p3 = slab[(g + 8) * SPAD + c10 + 1];
            if (kt == 0 && nt == 0 && tg == 0) { p0 = 0.0f; p2 = 0.0f; } // key 0
            if (zq0) { p0 = 0.0f; p1 = 0.0f; }                           // q-row 0
            float mk0 = Msk[j0], mk1 = Msk[j0 + 1];
            sc[nt][0] = (sc[nt][0] + p0) * 0.125f + mk0;
            sc[nt][1] = (sc[nt][1] + p1) * 0.125f + mk1;
            sc[nt][2] = (sc[nt][2] + p2) * 0.125f + mk0;
            sc[nt][3] = (sc[nt][3] + p3) * 0.125f + mk1;
            mt0 = fmaxf(mt0, fmaxf(sc[nt][0], sc[nt][1]));
            mt1 = fmaxf(mt1, fmaxf(sc[nt][2], sc[nt][3]));
        }
        mt0 = fmaxf(mt0, __shfl_xor_sync(0xffffffffu, mt0, 1));
        mt0 = fmaxf(mt0, __shfl_xor_sync(0xffffffffu, mt0, 2));
        mt1 = fmaxf(mt1, __shfl_xor_sync(0xffffffffu, mt1, 1));
        mt1 = fmaxf(mt1, __shfl_xor_sync(0xffffffffu, mt1, 2));

        // ---- Online softmax ----
        float mn0 = fmaxf(m0, mt0), mn1 = fmaxf(m1, mt1);
        float c0 = __expf(m0 - mn0), c1 = __expf(m1 - mn1);
        m0 = mn0; m1 = mn1;
#pragma unroll
        for (int nt = 0; nt < 8; nt++) {
            oac[nt][0] *= c0; oac[nt][1] *= c0;
            oac[nt][2] *= c1; oac[nt][3] *= c1;
        }
        float rs0 = 0.0f, rs1 = 0.0f;
#pragma unroll
        for (int nt = 0; nt < 8; nt++) {
            sc[nt][0] = __expf(sc[nt][0] - mn0);
            sc[nt][1] = __expf(sc[nt][1] - mn0);
            sc[nt][2] = __expf(sc[nt][2] - mn1);
            sc[nt][3] = __expf(sc[nt][3] - mn1);
            rs0 += sc[nt][0] + sc[nt][1];
            rs1 += sc[nt][2] + sc[nt][3];
        }
        rs0 += __shfl_xor_sync(0xffffffffu, rs0, 1);
        rs0 += __shfl_xor_sync(0xffffffffu, rs0, 2);
        rs1 += __shfl_xor_sync(0xffffffffu, rs1, 1);
        rs1 += __shfl_xor_sync(0xffffffffu, rs1, 2);
        l0 = l0 * c0 + rs0;
        l1 = l1 * c1 + rs1;

        __syncwarp();   // gathers done before P overwrites slab

        // ---- Write P (fp16 half2 pairs, swizzled 32-u32 rows) ----
#pragma unroll
        for (int nt = 0; nt < 8; nt++) {
            P32[swz32(g,     4 * nt + tg)] = pack_h2(sc[nt][0], sc[nt][1]);
            P32[swz32(g + 8, 4 * nt + tg)] = pack_h2(sc[nt][2], sc[nt][3]);
        }
        __syncwarp();

        // ---- O += P @ V ----
        uint32_t pf[4][4];
#pragma unroll
        for (int kc = 0; kc < 4; kc++) {
            pf[kc][0] = P32[swz32(g,     8 * kc + tg)];
            pf[kc][1] = P32[swz32(g + 8, 8 * kc + tg)];
            pf[kc][2] = P32[swz32(g,     8 * kc + tg + 4)];
            pf[kc][3] = P32[swz32(g + 8, 8 * kc + tg + 4)];
        }
#pragma unroll
        for (int nt = 0; nt < 8; nt++) {
            int n0 = nt * 8;
#pragma unroll
            for (int kc = 0; kc < 4; kc++) {
                uint32_t bf[2];
                bf[0] = Vtu[swz32(n0 + g, 8 * kc + tg)];
                bf[1] = Vtu[swz32(n0 + g, 8 * kc + tg + 4)];
                mma_f16(oac[nt], pf[kc], bf);
            }
        }
    }

    // ---- Epilogue ----
    float inv0 = 1.0f / l0, inv1 = 1.0f / l1;
    int r0 = q0 + r0l, r1 = q0 + r1l;
    size_t rowA = ((size_t)(b * SEQ + r0)) * DMODEL + h * DHEAD;
    size_t rowB = ((size_t)(b * SEQ + r1)) * DMODEL + h * DHEAD;
#pragma unroll
    for (int nt = 0; nt < 8; nt++) {
        int col = nt * 8 + 2 * tg;
        *(float2*)(ao + rowA + col) =
            make_float2(oac[nt][0] * inv0, oac[nt][1] * inv0);
        *(float2*)(ao + rowB + col) =
            make_float2(oac[nt][2] * inv1, oac[nt][3] * inv1);
    }
}

// ---------------------------------------------------------------------------
extern "C" void kernel_launch(void* const* d_in, const int* in_sizes, int n_in,
                              void* d_out, int out_size) {
    const float* x          = (const float*)d_in[0];
    const unsigned char* mk = (const unsigned char*)d_in[1];
    const float* Wqkv       = (const float*)d_in[2];
    const float* Wpe        = (const float*)d_in[3];
    const float* Wo         = (const float*)d_in[4];
    const float* cb         = (const float*)d_in[5];
    const float* pb         = (const float*)d_in[6];
    float* out              = (float*)d_out;

    float *qkv, *pe, *pek, *ao, *pbias;
    cudaGetSymbolAddress((void**)&qkv, g_qkv);
    cudaGetSymbolAddress((void**)&pe,  g_pe);
    cudaGetSymbolAddress((void**)&pek, g_pek);
    cudaGetSymbolAddress((void**)&ao,  g_ao);
    cudaGetSymbolAddress((void**)&pbias, g_pbias);

    cudaFuncSetAttribute(gemm_mma_kernel,
                         cudaFuncAttributeMaxDynamicSharedMemorySize,
                         GEMM_SMEM_BYTES);
    cudaFuncSetAttribute(attn_mma5_kernel,
                         cudaFuncAttributeMaxDynamicSharedMemorySize,
                         A5_SMEM_BYTES);

    pegen_kernel<<<(LPE * DMODEL + 255) / 256, 256>>>(pe);

    {
        dim3 grid(3072 / 128, 4096 / 128);
        gemm_mma_kernel<<<grid, 256, GEMM_SMEM_BYTES>>>(x, Wqkv, qkv,
                                                        BSZ * SEQ, 3 * DMODEL, DMODEL);
    }
    {
        dim3 grid(1024 / 128, (LPE + 127) / 128);
        gemm_mma_kernel<<<grid, 256, GEMM_SMEM_BYTES>>>(pe, Wpe, pek,
                                                        LPE, DMODEL, DMODEL);
    }

    pbias_kernel<<<(NHEAD * 2048) / 256, 256>>>(pek, cb, pb, pbias);

    attn_mma5_kernel<<<BSZ * NHEAD * (SEQ / 256), 512, A5_SMEM_BYTES>>>(
        qkv, pek, mk, cb, pbias, ao);

    {
        dim3 grid(1024 / 128, 4096 / 128);
        gemm_mma_kernel<<<grid, 256, GEMM_SMEM_BYTES>>>(ao, Wo, out,
                                                        BSZ * SEQ, DMODEL, DMODEL);
    }
}

// round 10
// speedup vs baseline: 1.4777x; 1.1968x over previous
#include <cuda_runtime.h>
#include <cuda_bf16.h>
#include <cuda_fp16.h>
#include <cstdint>
#include <math.h>

// Problem constants
#define BSZ 4
#define SEQ 1024
#define DMODEL 1024
#define NHEAD 16
#define DHEAD 64
#define LPE 2045   // 2*s-1, s = 1023

// Scratch
__device__ float g_qkv[BSZ * SEQ * 3 * DMODEL];
__device__ float g_pe [LPE * DMODEL];
__device__ float g_pek[LPE * DMODEL];
__device__ float g_ao [BSZ * SEQ * DMODEL];
__device__ float g_pbias[NHEAD * 2048];   // (pb-cb) . pek[l], per head

// ---------------------------------------------------------------------------
// fp16 m16n8k16, fp32 accumulate
__device__ __forceinline__ void mma_f16(float* d, const uint32_t* a,
                                        const uint32_t* b) {
    asm volatile(
        "mma.sync.aligned.m16n8k16.row.col.f32.f16.f16.f32 "
        "{%0,%1,%2,%3}, {%4,%5,%6,%7}, {%8,%9}, {%0,%1,%2,%3};\n"
        : "+f"(d[0]), "+f"(d[1]), "+f"(d[2]), "+f"(d[3])
        : "r"(a[0]), "r"(a[1]), "r"(a[2]), "r"(a[3]),
          "r"(b[0]), "r"(b[1]));
}

__device__ __forceinline__ uint32_t pack_h2(float x, float y) {
    __half2 h = __floats2half2_rn(x, y);
    return *(uint32_t*)&h;
}

// XOR-swizzled 32-u32 (128B) row layout for fp16 tiles
__device__ __forceinline__ int swz32(int row, int cp) {
    return row * 32 + ((((cp >> 2) ^ (row & 7)) << 2) | (cp & 3));
}

// ---------------------------------------------------------------------------
__global__ void pegen_kernel(float* __restrict__ pe) {
    int idx = blockIdx.x * blockDim.x + threadIdx.x;
    if (idx >= LPE * DMODEL) return;
    int l  = idx >> 10;
    int kk = idx & 1023;
    int p2 = kk & ~1;
    float expnt = (float)p2 / 1024.0f;
    float denom = powf(10000.0f, expnt);
    float t = (float)(l - 1022);
    float ang = t / denom;
    float v = (kk & 1) ? cosf(ang) : sinf(ang);
    pe[idx] = v * 0.03125f;
}

// pbias[h][l] = sum_c (pb[h,c]-cb[h,c]) * pek[l, h*64+c]
__global__ void pbias_kernel(const float* __restrict__ pek,
                             const float* __restrict__ cb,
                             const float* __restrict__ pb,
                             float* __restrict__ pbias) {
    int idx = blockIdx.x * blockDim.x + threadIdx.x;
    if (idx >= NHEAD * 2048) return;
    int h = idx >> 11, l = idx & 2047;
    float s = 0.0f;
    if (l < LPE) {
        const float* row = pek + (size_t)l * DMODEL + h * DHEAD;
#pragma unroll 16
        for (int c = 0; c < DHEAD; c++)
            s += (pb[h * DHEAD + c] - cb[h * DHEAD + c]) * row[c];
    }
    pbias[idx] = s;
}

// ===========================================================================
// FP16 mma.sync GEMM: C[M,N] = A[M,K] @ B[K,N], row-major fp32 in/out.
// BM=128, BN=128, BK=64 (4 x k16), 256 threads = 8 warps (2m x 4n),
// warp tile 64x32.  Half2-packed XOR-swizzled 128B-row tiles, double buffer.
// Requirements: N % 128 == 0, K % 64 == 0; M guarded.
// ===========================================================================
#define F_STAGE 4096   // u32 per stage (128 rows x 32 u32)
#define GEMM16_SMEM_BYTES (4 * F_STAGE * 4)   // 64 KB

__global__ __launch_bounds__(256)
void gemm_f16_kernel(const float* __restrict__ A, const float* __restrict__ B,
                     float* __restrict__ C, int M, int N, int K) {
    extern __shared__ uint32_t smu[];
    uint32_t* AsBase = smu;                 // [2][F_STAGE]
    uint32_t* BsBase = smu + 2 * F_STAGE;   // [2][F_STAGE]

    int tid  = threadIdx.x;
    int wid  = tid >> 5;
    int lane = tid & 31;
    int g    = lane >> 2;
    int tg   = lane & 3;
    int wm0  = (wid >> 2) * 64;
    int wn0  = (wid & 3) * 32;
    int bm = blockIdx.y * 128;
    int bn = blockIdx.x * 128;

    float acc[4][4][4];
#pragma unroll
    for (int mt = 0; mt < 4; mt++)
#pragma unroll
        for (int nt = 0; nt < 4; nt++)
#pragma unroll
            for (int r = 0; r < 4; r++) acc[mt][nt][r] = 0.0f;

    // Prefetch registers
    float4 pa[4][2];      // A: 4 uint4-chunks x 8 floats
    float pbv[4][8];      // B: 4 uint4-chunks x 8 scalars

    auto ldTile = [&](int k0) {
#pragma unroll
        for (int it = 0; it < 4; it++) {
            int idx = tid + 256 * it;
            int i = idx >> 3, gq = idx & 7;          // row i, uint4-chunk gq
            int gr = bm + i;
            if (gr < M) {
                const float* p = A + (size_t)gr * K + k0 + 8 * gq;
                pa[it][0] = *(const float4*)p;
                pa[it][1] = *(const float4*)(p + 4);
            } else {
                pa[it][0] = make_float4(0.f, 0.f, 0.f, 0.f);
                pa[it][1] = pa[it][0];
            }
        }
#pragma unroll
        for (int it = 0; it < 4; it++) {
            int idx = tid + 256 * it;
            int n = idx & 127, jq = idx >> 7;        // n row, uint4-chunk jq
            const float* p = B + (size_t)(k0 + 8 * jq) * N + bn + n;
#pragma unroll
            for (int e = 0; e < 8; e++)
                pbv[it][e] = p[(size_t)e * N];
        }
    };

    auto stsTile = [&](int s) {
        uint32_t* as = AsBase + s * F_STAGE;
        uint32_t* bs = BsBase + s * F_STAGE;
#pragma unroll
        for (int it = 0; it < 4; it++) {
            int idx = tid + 256 * it;
            int i = idx >> 3, gq = idx & 7;
            uint4 o;
            o.x = pack_h2(pa[it][0].x, pa[it][0].y);
            o.y = pack_h2(pa[it][0].z, pa[it][0].w);
            o.z = pack_h2(pa[it][1].x, pa[it][1].y);
            o.w = pack_h2(pa[it][1].z, pa[it][1].w);
            *(uint4*)(as + i * 32 + ((gq ^ (i & 7)) << 2)) = o;
        }
#pragma unroll
        for (int it = 0; it < 4; it++) {
            int idx = tid + 256 * it;
            int n = idx & 127, jq = idx >> 7;
            uint4 o;
            o.x = pack_h2(pbv[it][0], pbv[it][1]);
            o.y = pack_h2(pbv[it][2], pbv[it][3]);
            o.z = pack_h2(pbv[it][4], pbv[it][5]);
            o.w = pack_h2(pbv[it][6], pbv[it][7]);
            *(uint4*)(bs + n * 32 + ((jq ^ (n & 7)) << 2)) = o;
        }
    };

    auto compute = [&](int s) {
        const uint32_t* as = AsBase + s * F_STAGE;
        const uint32_t* bs = BsBase + s * F_STAGE;
#pragma unroll
        for (int kc = 0; kc < 4; kc++) {
            uint32_t af[4][4], bf[4][2];
#pragma unroll
            for (int mt = 0; mt < 4; mt++) {
                int r0 = wm0 + 16 * mt + g, r1 = r0 + 8;
                af[mt][0] = as[swz32(r0, 8 * kc + tg)];
                af[mt][1] = as[swz32(r1, 8 * kc + tg)];
                af[mt][2] = as[swz32(r0, 8 * kc + tg + 4)];
                af[mt][3] = as[swz32(r1, 8 * kc + tg + 4)];
            }
#pragma unroll
            for (int nt = 0; nt < 4; nt++) {
                int nr = wn0 + 8 * nt + g;
                bf[nt][0] = bs[swz32(nr, 8 * kc + tg)];
                bf[nt][1] = bs[swz32(nr, 8 * kc + tg + 4)];
            }
#pragma unroll
            for (int mt = 0; mt < 4; mt++)
#pragma unroll
                for (int nt = 0; nt < 4; nt++)
                    mma_f16(acc[mt][nt], af[mt], bf[nt]);
        }
    };

    int T = K >> 6;
    ldTile(0);
    stsTile(0);
    __syncthreads();

    for (int t = 0; t < T; t++) {
        int s = t & 1;
        if (t + 1 < T) ldTile((t + 1) << 6);
        compute(s);
        if (t + 1 < T) {
            stsTile(s ^ 1);
            __syncthreads();
        }
    }

#pragma unroll
    for (int mt = 0; mt < 4; mt++) {
        int r0 = bm + wm0 + mt * 16 + g;
        int r1 = r0 + 8;
#pragma unroll
        for (int nt = 0; nt < 4; nt++) {
            int col = bn + wn0 + nt * 8 + 2 * tg;
            if (r0 < M)
                *(float2*)(C + (size_t)r0 * N + col) =
                    make_float2(acc[mt][nt][0], acc[mt][nt][1]);
            if (r1 < M)
                *(float2*)(C + (size_t)r1 * N + col) =
                    make_float2(acc[mt][nt][2], acc[mt][nt][3]);
        }
    }
}

// ===========================================================================
// Attention v5 (unchanged from R9, passing): fp16 m16n8k16, 512 threads,
// 16 warps x 16 q-rows, PE ring buffer, pos-bias folded.
// ===========================================================================
#define A5_KS 0
#define A5_VT 2048
#define A5_PE 4096
#define A5_BIAS 16384
#define A5_MSK 16768
#define A5_U 16832
#define A5_SMEM_BYTES (38336 * 4)
#define SPAD 84
#define SLAB5 1344

__global__ __launch_bounds__(512, 1)
void attn_mma5_kernel(const float* __restrict__ qkv, const float* __restrict__ pek,
                      const unsigned char* __restrict__ mask,
                      const float* __restrict__ cb, const float* __restrict__ pbias,
                      float* __restrict__ ao) {
    extern __shared__ float sm[];
    uint32_t* Ksu  = (uint32_t*)sm + A5_KS;
    uint32_t* Vtu  = (uint32_t*)sm + A5_VT;
    uint32_t* PElu = (uint32_t*)sm + A5_PE;
    float* Bias = sm + A5_BIAS;
    float* Msk  = sm + A5_MSK;
    float* U    = sm + A5_U;
    uint32_t* Qs = (uint32_t*)U;

    int tid = threadIdx.x;
    int w = tid >> 5;
    int lane = tid & 31;
    int g = lane >> 2;
    int tg = lane & 3;
    int qt = blockIdx.x & 3;
    int bh = blockIdx.x >> 2;
    int h  = bh & 15;
    int b  = bh >> 4;
    int q0 = qt * 256;

    const float* cbh = cb + h * DHEAD;
    const float* pbh_bias = pbias + h * 2048;
    int lbase0 = 767 - q0;

    // ---- Prologue: stage Qc (256 rows, fp16), PE slots [0,320), Bias ----
    for (int idx = tid; idx < 2048; idx += 512) {
        int i = idx >> 3, gq = idx & 7;
        int c8 = gq * 8;
        const float* src = qkv + ((size_t)(b * SEQ + q0 + i)) * 3072 + h * 192 + c8;
        float4 v0 = *(const float4*)src;
        float4 v1 = *(const float4*)(src + 4);
        uint4 o;
        o.x = pack_h2(v0.x + cbh[c8 + 0], v0.y + cbh[c8 + 1]);
        o.y = pack_h2(v0.z + cbh[c8 + 2], v0.w + cbh[c8 + 3]);
        o.z = pack_h2(v1.x + cbh[c8 + 4], v1.y + cbh[c8 + 5]);
        o.w = pack_h2(v1.z + cbh[c8 + 6], v1.w + cbh[c8 + 7]);
        *(uint4*)(Qs + i * 32 + ((gq ^ (i & 7)) << 2)) = o;
    }
    for (int idx = tid; idx < 2560; idx += 512) {
        int sl_ = idx >> 3, gq = idx & 7;
        int lg = lbase0 + sl_;
        float4 v0, v1;
        if (lg >= 0 && lg < LPE) {
            const float* p = pek + (size_t)lg * DMODEL + h * DHEAD + gq * 8;
            v0 = *(const float4*)p; v1 = *(const float4*)(p + 4);
        } else {
            v0 = make_float4(0.f, 0.f, 0.f, 0.f); v1 = v0;
        }
        uint4 o;
        o.x = pack_h2(v0.x, v0.y); o.y = pack_h2(v0.z, v0.w);
        o.z = pack_h2(v1.x, v1.y); o.w = pack_h2(v1.z, v1.w);
        *(uint4*)(PElu + sl_ * 32 + ((gq ^ (sl_ & 7)) << 2)) = o;
    }
    if (tid < 320) {
        int lg = lbase0 + tid;
        Bias[tid] = (lg >= 0 && lg < LPE) ? pbh_bias[lg] : 0.0f;
    }
    __syncthreads();

    // ---- Persist Qc fragments (rows g, g+8 of this warp's 16) ----
    uint32_t qcf[4][4];
    int r0l = 16 * w + g, r1l = r0l + 8;
#pragma unroll
    for (int kc = 0; kc < 4; kc++) {
        qcf[kc][0] = Qs[swz32(r0l, 8 * kc + tg)];
        qcf[kc][1] = Qs[swz32(r1l, 8 * kc + tg)];
        qcf[kc][2] = Qs[swz32(r0l, 8 * kc + tg + 4)];
        qcf[kc][3] = Qs[swz32(r1l, 8 * kc + tg + 4)];
    }
    __syncthreads();

    bool zq0 = (q0 == 0 && w == 0 && g == 0);  // global q-row 0

    float oac[8][4];
#pragma unroll
    for (int nt = 0; nt < 8; nt++)
#pragma unroll
        for (int r = 0; r < 4; r++) oac[nt][r] = 0.0f;
    float m0 = -1e30f, m1 = -1e30f, l0 = 0.0f, l1 = 0.0f;

    float* slab = U + w * SLAB5;
    uint32_t* P32 = (uint32_t*)slab;
    int s0base = 30 - 2 * w;

    for (int kt = 0; kt < 16; kt++) {
        int k0 = kt * 64;
        int ktm = (64 * kt) % 384;
        __syncthreads();   // prior compute reads + prior PE prefetch done

        // ---- Stage K (row-major halves) ----
        {
            int i = tid >> 3, gq = tid & 7;
            const float* base = qkv + ((size_t)(b * SEQ + k0 + i)) * 3072
                                + h * 192 + 64 + gq * 8;
            float4 v0 = *(const float4*)base;
            float4 v1 = *(const float4*)(base + 4);
            uint4 o;
            o.x = pack_h2(v0.x, v0.y); o.y = pack_h2(v0.z, v0.w);
            o.z = pack_h2(v1.x, v1.y); o.w = pack_h2(v1.z, v1.w);
            *(uint4*)(Ksu + i * 32 + ((gq ^ (i & 7)) << 2)) = o;
        }
        // ---- Stage V transposed: Vt[c][jp] = {V[2jp][c], V[2jp+1][c]} ----
        for (int idx = tid; idx < 2048; idx += 512) {
            int jp = idx >> 6, c = idx & 63;
            const float* vsrc = qkv + ((size_t)(b * SEQ + k0 + 2 * jp)) * 3072
                                + h * 192 + 128 + c;
            Vtu[swz32(c, jp)] = pack_h2(vsrc[0], vsrc[3072]);
        }
        if (tid < 64) Msk[tid] = mask[b * SEQ + k0 + tid] ? -1e30f : 0.0f;
        __syncthreads();

        // ---- PE ring prefetch for kt+1 (overlaps compute) ----
        if (kt < 15) {
            {
                int r = tid >> 3, gq = tid & 7;
                int off = 64 * kt + 320 + r;
                int slot = off % 384;
                int lg = lbase0 + off;
                float4 v0, v1;
                if (lg >= 0 && lg < LPE) {
                    const float* p = pek + (size_t)lg * DMODEL + h * DHEAD + gq * 8;
                    v0 = *(const float4*)p; v1 = *(const float4*)(p + 4);
                } else {
                    v0 = make_float4(0.f, 0.f, 0.f, 0.f); v1 = v0;
                }
                uint4 o;
                o.x = pack_h2(v0.x, v0.y); o.y = pack_h2(v0.z, v0.w);
                o.z = pack_h2(v1.x, v1.y); o.w = pack_h2(v1.z, v1.w);
                *(uint4*)(PElu + slot * 32 + ((gq ^ (slot & 7)) << 2)) = o;
            }
            if (tid < 64) {
                int off = 64 * kt + 320 + tid;
                int lg = lbase0 + off;
                Bias[off % 384] = (lg >= 0 && lg < LPE) ? pbh_bias[lg] : 0.0f;
            }
        }

        // ---- Band: Spos = Qc @ PE^T + bias (10 tiles, 4 kc each) ----
#pragma unroll
        for (int t = 0; t < 10; t++) {
            int m = s0base + t;
            int sr = ktm + 8 * m; if (sr >= 384) sr -= 384;
            int br = sr + g;
            float sp[4] = {0.f, 0.f, 0.f, 0.f};
#pragma unroll
            for (int kc = 0; kc < 4; kc++) {
                uint32_t bf[2];
                bf[0] = PElu[swz32(br, 8 * kc + tg)];
                bf[1] = PElu[swz32(br, 8 * kc + tg + 4)];
                mma_f16(sp, qcf[kc], bf);
            }
            int bidx = ktm + 8 * m + 2 * tg; if (bidx >= 384) bidx -= 384;
            float b0 = Bias[bidx], b1 = Bias[bidx + 1];
            int cc0 = 8 * t + 2 * tg;
            slab[g * SPAD + cc0]           = sp[0] + b0;
            slab[g * SPAD + cc0 + 1]       = sp[1] + b1;
            slab[(g + 8) * SPAD + cc0]     = sp[2] + b0;
            slab[(g + 8) * SPAD + cc0 + 1] = sp[3] + b1;
        }
        __syncwarp();

        // ---- Content scores: Qc @ K^T ----
        float sc[8][4];
#pragma unroll
        for (int nt = 0; nt < 8; nt++) {
            int n0 = nt * 8;
            sc[nt][0] = sc[nt][1] = sc[nt][2] = sc[nt][3] = 0.0f;
#pragma unroll
            for (int kc = 0; kc < 4; kc++) {
                uint32_t bf[2];
                bf[0] = Ksu[swz32(n0 + g, 8 * kc + tg)];
                bf[1] = Ksu[swz32(n0 + g, 8 * kc + tg + 4)];
                mma_f16(sc[nt], qcf[kc], bf);
            }
        }

        // ---- Gather band diag + combine + mask + row max ----
        float mt0 = -1e30f, mt1 = -1e30f;
#pragma unroll
        for (int nt = 0; nt < 8; nt++) {
            int j0 = nt * 8 + 2 * tg;
            int c00 = j0 - g + 15;
            int c10 = j0 - g + 7;
            float p0 = slab[g * SPAD + c00];
            float p1 = slab[g * SPAD + c00 + 1];
            float p2 = slab[(g + 8) * SPAD + c10];
            float p3 = slab[(g + 8) * SPAD + c10 + 1];
            if (kt == 0 && nt == 0 && tg == 0) { p0 = 0.0f; p2 = 0.0f; } // key 0
            if (zq0) { p0 = 0.0f; p1 = 0.0f; }                           // q-row 0
            float mk0 = Msk[j0], mk1 = Msk[j0 + 1];
            sc[nt][0] = (sc[nt][0] + p0) * 0.125f + mk0;
            sc[nt][1] = (sc[nt][1] + p1) * 0.125f + mk1;
            sc[nt][2] = (sc[nt][2] + p2) * 0.125f + mk0;
            sc[nt][3] = (sc[nt][3] + p3) * 0.125f + mk1;
            mt0 = fmaxf(mt0, fmaxf(sc[nt][0], sc[nt][1]));
            mt1 = fmaxf(mt1, fmaxf(sc[nt][2], sc[nt][3]));
        }
        mt0 = fmaxf(mt0, __shfl_xor_sync(0xffffffffu, mt0, 1));
        mt0 = fmaxf(mt0, __shfl_xor_sync(0xffffffffu, mt0, 2));
        mt1 = fmaxf(mt1, __shfl_xor_sync(0xffffffffu, mt1, 1));
        mt1 = fmaxf(mt1, __shfl_xor_sync(0xffffffffu, mt1, 2));

        // ---- Online softmax ----
        float mn0 = fmaxf(m0, mt0), mn1 = fmaxf(m1, mt1);
        float c0 = __expf(m0 - mn0), c1 = __expf(m1 - mn1);
        m0 = mn0; m1 = mn1;
#pragma unroll
        for (int nt = 0; nt < 8; nt++) {
            oac[nt][0] *= c0; oac[nt][1] *= c0;
            oac[nt][2] *= c1; oac[nt][3] *= c1;
        }
        float rs0 = 0.0f, rs1 = 0.0f;
#pragma unroll
        for (int nt = 0; nt < 8; nt++) {
            sc[nt][0] = __expf(sc[nt][0] - mn0);
            sc[nt][1] = __expf(sc[nt][1] - mn0);
            sc[nt][2] = __expf(sc[nt][2] - mn1);
            sc[nt][3] = __expf(sc[nt][3] - mn1);
            rs0 += sc[nt][0] + sc[nt][1];
            rs1 += sc[nt][2] + sc[nt][3];
        }
        rs0 += __shfl_xor_sync(0xffffffffu, rs0, 1);
        rs0 += __shfl_xor_sync(0xffffffffu, rs0, 2);
        rs1 += __shfl_xor_sync(0xffffffffu, rs1, 1);
        rs1 += __shfl_xor_sync(0xffffffffu, rs1, 2);
        l0 = l0 * c0 + rs0;
        l1 = l1 * c1 + rs1;

        __syncwarp();   // gathers done before P overwrites slab

        // ---- Write P (fp16 half2 pairs, swizzled 32-u32 rows) ----
#pragma unroll
        for (int nt = 0; nt < 8; nt++) {
            P32[swz32(g,     4 * nt + tg)] = pack_h2(sc[nt][0], sc[nt][1]);
            P32[swz32(g + 8, 4 * nt + tg)] = pack_h2(sc[nt][2], sc[nt][3]);
        }
        __syncwarp();

        // ---- O += P @ V ----
        uint32_t pf[4][4];
#pragma unroll
        for (int kc = 0; kc < 4; kc++) {
            pf[kc][0] = P32[swz32(g,     8 * kc + tg)];
            pf[kc][1] = P32[swz32(g + 8, 8 * kc + tg)];
            pf[kc][2] = P32[swz32(g,     8 * kc + tg + 4)];
            pf[kc][3] = P32[swz32(g + 8, 8 * kc + tg + 4)];
        }
#pragma unroll
        for (int nt = 0; nt < 8; nt++) {
            int n0 = nt * 8;
#pragma unroll
            for (int kc = 0; kc < 4; kc++) {
                uint32_t bf[2];
                bf[0] = Vtu[swz32(n0 + g, 8 * kc + tg)];
                bf[1] = Vtu[swz32(n0 + g, 8 * kc + tg + 4)];
                mma_f16(oac[nt], pf[kc], bf);
            }
        }
    }

    // ---- Epilogue ----
    float inv0 = 1.0f / l0, inv1 = 1.0f / l1;
    int r0 = q0 + r0l, r1 = q0 + r1l;
    size_t rowA = ((size_t)(b * SEQ + r0)) * DMODEL + h * DHEAD;
    size_t rowB = ((size_t)(b * SEQ + r1)) * DMODEL + h * DHEAD;
#pragma unroll
    for (int nt = 0; nt < 8; nt++) {
        int col = nt * 8 + 2 * tg;
        *(float2*)(ao + rowA + col) =
            make_float2(oac[nt][0] * inv0, oac[nt][1] * inv0);
        *(float2*)(ao + rowB + col) =
            make_float2(oac[nt][2] * inv1, oac[nt][3] * inv1);
    }
}

// ---------------------------------------------------------------------------
extern "C" void kernel_launch(void* const* d_in, const int* in_sizes, int n_in,
                              void* d_out, int out_size) {
    const float* x          = (const float*)d_in[0];
    const unsigned char* mk = (const unsigned char*)d_in[1];
    const float* Wqkv       = (const float*)d_in[2];
    const float* Wpe        = (const float*)d_in[3];
    const float* Wo         = (const float*)d_in[4];
    const float* cb         = (const float*)d_in[5];
    const float* pb         = (const float*)d_in[6];
    float* out              = (float*)d_out;

    float *qkv, *pe, *pek, *ao, *pbias;
    cudaGetSymbolAddress((void**)&qkv, g_qkv);
    cudaGetSymbolAddress((void**)&pe,  g_pe);
    cudaGetSymbolAddress((void**)&pek, g_pek);
    cudaGetSymbolAddress((void**)&ao,  g_ao);
    cudaGetSymbolAddress((void**)&pbias, g_pbias);

    cudaFuncSetAttribute(gemm_f16_kernel,
                         cudaFuncAttributeMaxDynamicSharedMemorySize,
                         GEMM16_SMEM_BYTES);
    cudaFuncSetAttribute(attn_mma5_kernel,
                         cudaFuncAttributeMaxDynamicSharedMemorySize,
                         A5_SMEM_BYTES);

    pegen_kernel<<<(LPE * DMODEL + 255) / 256, 256>>>(pe);

    {
        dim3 grid(3072 / 128, 4096 / 128);
        gemm_f16_kernel<<<grid, 256, GEMM16_SMEM_BYTES>>>(x, Wqkv, qkv,
                                                          BSZ * SEQ, 3 * DMODEL, DMODEL);
    }
    {
        dim3 grid(1024 / 128, (LPE + 127) / 128);
        gemm_f16_kernel<<<grid, 256, GEMM16_SMEM_BYTES>>>(pe, Wpe, pek,
                                                          LPE, DMODEL, DMODEL);
    }

    pbias_kernel<<<(NHEAD * 2048) / 256, 256>>>(pek, cb, pb, pbias);

    attn_mma5_kernel<<<BSZ * NHEAD * (SEQ / 256), 512, A5_SMEM_BYTES>>>(
        qkv, pek, mk, cb, pbias, ao);

    {
        dim3 grid(1024 / 128, 4096 / 128);
        gemm_f16_kernel<<<grid, 256, GEMM16_SMEM_BYTES>>>(ao, Wo, out,
                                                          BSZ * SEQ, DMODEL, DMODEL);
    }
}

// round 11
// speedup vs baseline: 1.6372x; 1.1080x over previous
#include <cuda_runtime.h>
#include <cuda_bf16.h>
#include <cuda_fp16.h>
#include <cstdint>
#include <math.h>

// Problem constants
#define BSZ 4
#define SEQ 1024
#define DMODEL 1024
#define NHEAD 16
#define DHEAD 64
#define LPE 2045   // 2*s-1, s = 1023

// Scratch (intermediates now fp16)
__device__ __half g_qkvh[BSZ * SEQ * 3 * DMODEL];   // (4096, 3072) half
__device__ float  g_pe  [LPE * DMODEL];              // fp32 GEMM input
__device__ __half g_pekh[LPE * DMODEL];              // (2045, 1024) half
__device__ __half g_aoh [BSZ * SEQ * DMODEL];        // attention out, half
__device__ float  g_pbias[NHEAD * 2048];             // (pb-cb) . pek[l]

// ---------------------------------------------------------------------------
// fp16 m16n8k16, fp32 accumulate
__device__ __forceinline__ void mma_f16(float* d, const uint32_t* a,
                                        const uint32_t* b) {
    asm volatile(
        "mma.sync.aligned.m16n8k16.row.col.f32.f16.f16.f32 "
        "{%0,%1,%2,%3}, {%4,%5,%6,%7}, {%8,%9}, {%0,%1,%2,%3};\n"
        : "+f"(d[0]), "+f"(d[1]), "+f"(d[2]), "+f"(d[3])
        : "r"(a[0]), "r"(a[1]), "r"(a[2]), "r"(a[3]),
          "r"(b[0]), "r"(b[1]));
}

__device__ __forceinline__ uint32_t pack_h2(float x, float y) {
    __half2 h = __floats2half2_rn(x, y);
    return *(uint32_t*)&h;
}

// XOR-swizzled 32-u32 (128B) row layout for fp16 tiles
__device__ __forceinline__ int swz32(int row, int cp) {
    return row * 32 + ((((cp >> 2) ^ (row & 7)) << 2) | (cp & 3));
}

// ---------------------------------------------------------------------------
__global__ void pegen_kernel(float* __restrict__ pe) {
    int idx = blockIdx.x * blockDim.x + threadIdx.x;
    if (idx >= LPE * DMODEL) return;
    int l  = idx >> 10;
    int kk = idx & 1023;
    int p2 = kk & ~1;
    float expnt = (float)p2 / 1024.0f;
    float denom = powf(10000.0f, expnt);
    float t = (float)(l - 1022);
    float ang = t / denom;
    float v = (kk & 1) ? cosf(ang) : sinf(ang);
    pe[idx] = v * 0.03125f;
}

// pbias[h][l] = sum_c (pb[h,c]-cb[h,c]) * pek[l, h*64+c]; warp per (h,l)
__global__ void pbias_kernel(const __half* __restrict__ pek,
                             const float* __restrict__ cb,
                             const float* __restrict__ pb,
                             float* __restrict__ pbias) {
    int gw = (blockIdx.x * blockDim.x + threadIdx.x) >> 5;
    int lane = threadIdx.x & 31;
    if (gw >= NHEAD * 2048) return;
    int h = gw >> 11, l = gw & 2047;
    float s = 0.0f;
    if (l < LPE) {
        const __half* row = pek + (size_t)l * DMODEL + h * DHEAD;
        float d0 = pb[h * DHEAD + lane]      - cb[h * DHEAD + lane];
        float d1 = pb[h * DHEAD + 32 + lane] - cb[h * DHEAD + 32 + lane];
        s = d0 * __half2float(row[lane]) + d1 * __half2float(row[32 + lane]);
#pragma unroll
        for (int off = 16; off; off >>= 1)
            s += __shfl_xor_sync(0xffffffffu, s, off);
    }
    if (lane == 0) pbias[gw] = s;
}

// ===========================================================================
// FP16 mma.sync GEMM: C[M,N] = A[M,K] @ B[K,N].
// A_HALF: A is packed half (row-major); else fp32.  C_HALF: C written packed
// half; else fp32.  B always fp32.  BM=128, BN=128, BK=64 (4 x k16),
// 256 threads = 8 warps (2m x 4n), warp tile 64x32.  Double-buffered smem.
// Requirements: N % 128 == 0, K % 64 == 0; M guarded.
// ===========================================================================
#define F_STAGE 4096   // u32 per stage (128 rows x 32 u32)
#define GEMM16_SMEM_BYTES (4 * F_STAGE * 4)   // 64 KB

template <bool A_HALF, bool C_HALF>
__global__ __launch_bounds__(256)
void gemm_f16_kernel(const void* __restrict__ Av, const float* __restrict__ B,
                     void* __restrict__ Cv, int M, int N, int K) {
    extern __shared__ uint32_t smu[];
    uint32_t* AsBase = smu;
    uint32_t* BsBase = smu + 2 * F_STAGE;

    const float*  Af = (const float*)Av;
    const __half* Ah = (const __half*)Av;
    float*  Cf = (float*)Cv;
    __half* Ch = (__half*)Cv;

    int tid  = threadIdx.x;
    int wid  = tid >> 5;
    int lane = tid & 31;
    int g    = lane >> 2;
    int tg   = lane & 3;
    int wm0  = (wid >> 2) * 64;
    int wn0  = (wid & 3) * 32;
    int bm = blockIdx.y * 128;
    int bn = blockIdx.x * 128;

    float acc[4][4][4];
#pragma unroll
    for (int mt = 0; mt < 4; mt++)
#pragma unroll
        for (int nt = 0; nt < 4; nt++)
#pragma unroll
            for (int r = 0; r < 4; r++) acc[mt][nt][r] = 0.0f;

    float4 pa[4][2];
    uint4  pau[4];
    float  pbv[4][8];

    auto ldTile = [&](int k0) {
#pragma unroll
        for (int it = 0; it < 4; it++) {
            int idx = tid + 256 * it;
            int i = idx >> 3, gq = idx & 7;
            int gr = bm + i;
            if (A_HALF) {
                pau[it] = (gr < M)
                    ? *(const uint4*)(Ah + (size_t)gr * K + k0 + 8 * gq)
                    : make_uint4(0u, 0u, 0u, 0u);
            } else {
                if (gr < M) {
                    const float* p = Af + (size_t)gr * K + k0 + 8 * gq;
                    pa[it][0] = *(const float4*)p;
                    pa[it][1] = *(const float4*)(p + 4);
                } else {
                    pa[it][0] = make_float4(0.f, 0.f, 0.f, 0.f);
                    pa[it][1] = pa[it][0];
                }
            }
        }
#pragma unroll
        for (int it = 0; it < 4; it++) {
            int idx = tid + 256 * it;
            int n = idx & 127, jq = idx >> 7;
            const float* p = B + (size_t)(k0 + 8 * jq) * N + bn + n;
#pragma unroll
            for (int e = 0; e < 8; e++)
                pbv[it][e] = p[(size_t)e * N];
        }
    };

    auto stsTile = [&](int s) {
        uint32_t* as = AsBase + s * F_STAGE;
        uint32_t* bs = BsBase + s * F_STAGE;
#pragma unroll
        for (int it = 0; it < 4; it++) {
            int idx = tid + 256 * it;
            int i = idx >> 3, gq = idx & 7;
            uint4 o;
            if (A_HALF) {
                o = pau[it];
            } else {
                o.x = pack_h2(pa[it][0].x, pa[it][0].y);
                o.y = pack_h2(pa[it][0].z, pa[it][0].w);
                o.z = pack_h2(pa[it][1].x, pa[it][1].y);
                o.w = pack_h2(pa[it][1].z, pa[it][1].w);
            }
            *(uint4*)(as + i * 32 + ((gq ^ (i & 7)) << 2)) = o;
        }
#pragma unroll
        for (int it = 0; it < 4; it++) {
            int idx = tid + 256 * it;
            int n = idx & 127, jq = idx >> 7;
            uint4 o;
            o.x = pack_h2(pbv[it][0], pbv[it][1]);
            o.y = pack_h2(pbv[it][2], pbv[it][3]);
            o.z = pack_h2(pbv[it][4], pbv[it][5]);
            o.w = pack_h2(pbv[it][6], pbv[it][7]);
            *(uint4*)(bs + n * 32 + ((jq ^ (n & 7)) << 2)) = o;
        }
    };

    auto compute = [&](int s) {
        const uint32_t* as = AsBase + s * F_STAGE;
        const uint32_t* bs = BsBase + s * F_STAGE;
#pragma unroll
        for (int kc = 0; kc < 4; kc++) {
            uint32_t af[4][4], bf[4][2];
#pragma unroll
            for (int mt = 0; mt < 4; mt++) {
                int r0 = wm0 + 16 * mt + g, r1 = r0 + 8;
                af[mt][0] = as[swz32(r0, 8 * kc + tg)];
                af[mt][1] = as[swz32(r1, 8 * kc + tg)];
                af[mt][2] = as[swz32(r0, 8 * kc + tg + 4)];
                af[mt][3] = as[swz32(r1, 8 * kc + tg + 4)];
            }
#pragma unroll
            for (int nt = 0; nt < 4; nt++) {
                int nr = wn0 + 8 * nt + g;
                bf[nt][0] = bs[swz32(nr, 8 * kc + tg)];
                bf[nt][1] = bs[swz32(nr, 8 * kc + tg + 4)];
            }
#pragma unroll
            for (int mt = 0; mt < 4; mt++)
#pragma unroll
                for (int nt = 0; nt < 4; nt++)
                    mma_f16(acc[mt][nt], af[mt], bf[nt]);
        }
    };

    int T = K >> 6;
    ldTile(0);
    stsTile(0);
    __syncthreads();

    for (int t = 0; t < T; t++) {
        int s = t & 1;
        if (t + 1 < T) ldTile((t + 1) << 6);
        compute(s);
        if (t + 1 < T) {
            stsTile(s ^ 1);
            __syncthreads();
        }
    }

#pragma unroll
    for (int mt = 0; mt < 4; mt++) {
        int r0 = bm + wm0 + mt * 16 + g;
        int r1 = r0 + 8;
#pragma unroll
        for (int nt = 0; nt < 4; nt++) {
            int col = bn + wn0 + nt * 8 + 2 * tg;
            if (C_HALF) {
                if (r0 < M)
                    *(uint32_t*)(Ch + (size_t)r0 * N + col) =
                        pack_h2(acc[mt][nt][0], acc[mt][nt][1]);
                if (r1 < M)
                    *(uint32_t*)(Ch + (size_t)r1 * N + col) =
                        pack_h2(acc[mt][nt][2], acc[mt][nt][3]);
            } else {
                if (r0 < M)
                    *(float2*)(Cf + (size_t)r0 * N + col) =
                        make_float2(acc[mt][nt][0], acc[mt][nt][1]);
                if (r1 < M)
                    *(float2*)(Cf + (size_t)r1 * N + col) =
                        make_float2(acc[mt][nt][2], acc[mt][nt][3]);
            }
        }
    }
}

// ===========================================================================
// Attention v6: fp16 inputs (qkv/pek half), fp16 output (ao half).
// 512 threads, 16 warps x 16 q-rows, PE ring buffer, pos-bias folded.
// K/PE staging: pure swizzled uint4 copies (no conversion).
// ===========================================================================
#define A5_KS 0
#define A5_VT 2048
#define A5_PE 4096
#define A5_BIAS 16384
#define A5_MSK 16768
#define A5_U 16832
#define A5_SMEM_BYTES (38336 * 4)
#define SPAD 84
#define SLAB5 1344

__global__ __launch_bounds__(512, 1)
void attn_mma6_kernel(const __half* __restrict__ qkvh,
                      const __half* __restrict__ pekh,
                      const unsigned char* __restrict__ mask,
                      const float* __restrict__ cb,
                      const float* __restrict__ pbias,
                      __half* __restrict__ aoh) {
    extern __shared__ float sm[];
    uint32_t* Ksu  = (uint32_t*)sm + A5_KS;
    uint32_t* Vtu  = (uint32_t*)sm + A5_VT;
    uint32_t* PElu = (uint32_t*)sm + A5_PE;
    float* Bias = sm + A5_BIAS;
    float* Msk  = sm + A5_MSK;
    float* U    = sm + A5_U;
    uint32_t* Qs = (uint32_t*)U;

    int tid = threadIdx.x;
    int w = tid >> 5;
    int lane = tid & 31;
    int g = lane >> 2;
    int tg = lane & 3;
    int qt = blockIdx.x & 3;
    int bh = blockIdx.x >> 2;
    int h  = bh & 15;
    int b  = bh >> 4;
    int q0 = qt * 256;

    const float* cbh = cb + h * DHEAD;
    const float* pbh_bias = pbias + h * 2048;
    int lbase0 = 767 - q0;

    // ---- Prologue: Qc (half in, +bias, half out), PE [0,320) copy, Bias ----
    for (int idx = tid; idx < 2048; idx += 512) {
        int i = idx >> 3, gq = idx & 7;
        int c8 = gq * 8;
        uint4 v = *(const uint4*)(qkvh + ((size_t)(b * SEQ + q0 + i)) * 3072
                                  + h * 192 + c8);
        __half2* hp = (__half2*)&v;
        uint4 o;
#pragma unroll
        for (int e = 0; e < 4; e++) {
            float2 f = __half22float2(hp[e]);
            ((uint32_t*)&o)[e] = pack_h2(f.x + cbh[c8 + 2 * e],
                                         f.y + cbh[c8 + 2 * e + 1]);
        }
        *(uint4*)(Qs + i * 32 + ((gq ^ (i & 7)) << 2)) = o;
    }
    for (int idx = tid; idx < 2560; idx += 512) {
        int sl_ = idx >> 3, gq = idx & 7;
        int lg = lbase0 + sl_;
        uint4 v = (lg >= 0 && lg < LPE)
            ? *(const uint4*)(pekh + (size_t)lg * DMODEL + h * DHEAD + 8 * gq)
            : make_uint4(0u, 0u, 0u, 0u);
        *(uint4*)(PElu + sl_ * 32 + ((gq ^ (sl_ & 7)) << 2)) = v;
    }
    if (tid < 320) {
        int lg = lbase0 + tid;
        Bias[tid] = (lg >= 0 && lg < LPE) ? pbh_bias[lg] : 0.0f;
    }
    __syncthreads();

    // ---- Persist Qc fragments ----
    uint32_t qcf[4][4];
    int r0l = 16 * w + g, r1l = r0l + 8;
#pragma unroll
    for (int kc = 0; kc < 4; kc++) {
        qcf[kc][0] = Qs[swz32(r0l, 8 * kc + tg)];
        qcf[kc][1] = Qs[swz32(r1l, 8 * kc + tg)];
        qcf[kc][2] = Qs[swz32(r0l, 8 * kc + tg + 4)];
        qcf[kc][3] = Qs[swz32(r1l, 8 * kc + tg + 4)];
    }
    __syncthreads();

    bool zq0 = (q0 == 0 && w == 0 && g == 0);  // global q-row 0

    float oac[8][4];
#pragma unroll
    for (int nt = 0; nt < 8; nt++)
#pragma unroll
        for (int r = 0; r < 4; r++) oac[nt][r] = 0.0f;
    float m0 = -1e30f, m1 = -1e30f, l0 = 0.0f, l1 = 0.0f;

    float* slab = U + w * SLAB5;
    uint32_t* P32 = (uint32_t*)slab;
    int s0base = 30 - 2 * w;

    for (int kt = 0; kt < 16; kt++) {
        int k0 = kt * 64;
        int ktm = (64 * kt) % 384;
        __syncthreads();

        // ---- Stage K (pure swizzled copy) ----
        {
            int i = tid >> 3, gq = tid & 7;
            uint4 v = *(const uint4*)(qkvh + ((size_t)(b * SEQ + k0 + i)) * 3072
                                      + h * 192 + 64 + 8 * gq);
            *(uint4*)(Ksu + i * 32 + ((gq ^ (i & 7)) << 2)) = v;
        }
        // ---- Stage V transposed: Vt[c][jp] = {V[2jp][c], V[2jp+1][c]} ----
        for (int idx = tid; idx < 2048; idx += 512) {
            int jp = idx >> 6, c = idx & 63;
            const __half* vsrc = qkvh + ((size_t)(b * SEQ + k0 + 2 * jp)) * 3072
                                 + h * 192 + 128 + c;
            __half2 hv = __halves2half2(vsrc[0], vsrc[3072]);
            Vtu[swz32(c, jp)] = *(uint32_t*)&hv;
        }
        if (tid < 64) Msk[tid] = mask[b * SEQ + k0 + tid] ? -1e30f : 0.0f;
        __syncthreads();

        // ---- PE ring prefetch for kt+1 (overlaps compute) ----
        if (kt < 15) {
            {
                int r = tid >> 3, gq = tid & 7;
                int off = 64 * kt + 320 + r;
                int slot = off % 384;
                int lg = lbase0 + off;
                uint4 v = (lg >= 0 && lg < LPE)
                    ? *(const uint4*)(pekh + (size_t)lg * DMODEL + h * DHEAD + 8 * gq)
                    : make_uint4(0u, 0u, 0u, 0u);
                *(uint4*)(PElu + slot * 32 + ((gq ^ (slot & 7)) << 2)) = v;
            }
            if (tid < 64) {
                int off = 64 * kt + 320 + tid;
                int lg = lbase0 + off;
                Bias[off % 384] = (lg >= 0 && lg < LPE) ? pbh_bias[lg] : 0.0f;
            }
        }

        // ---- Band: Spos = Qc @ PE^T + bias (10 tiles) ----
#pragma unroll
        for (int t = 0; t < 10; t++) {
            int m = s0base + t;
            int sr = ktm + 8 * m; if (sr >= 384) sr -= 384;
            int br = sr + g;
            float sp[4] = {0.f, 0.f, 0.f, 0.f};
#pragma unroll
            for (int kc = 0; kc < 4; kc++) {
                uint32_t bf[2];
                bf[0] = PElu[swz32(br, 8 * kc + tg)];
                bf[1] = PElu[swz32(br, 8 * kc + tg + 4)];
                mma_f16(sp, qcf[kc], bf);
            }
            int bidx = ktm + 8 * m + 2 * tg; if (bidx >= 384) bidx -= 384;
            float b0 = Bias[bidx], b1 = Bias[bidx + 1];
            int cc0 = 8 * t + 2 * tg;
            slab[g * SPAD + cc0]           = sp[0] + b0;
            slab[g * SPAD + cc0 + 1]       = sp[1] + b1;
            slab[(g + 8) * SPAD + cc0]     = sp[2] + b0;
            slab[(g + 8) * SPAD + cc0 + 1] = sp[3] + b1;
        }
        __syncwarp();

        // ---- Content scores: Qc @ K^T ----
        float sc[8][4];
#pragma unroll
        for (int nt = 0; nt < 8; nt++) {
            int n0 = nt * 8;
            sc[nt][0] = sc[nt][1] = sc[nt][2] = sc[nt][3] = 0.0f;
#pragma unroll
            for (int kc = 0; kc < 4; kc++) {
                uint32_t bf[2];
                bf[0] = Ksu[swz32(n0 + g, 8 * kc + tg)];
                bf[1] = Ksu[swz32(n0 + g, 8 * kc + tg + 4)];
                mma_f16(sc[nt], qcf[kc], bf);
            }
        }

        // ---- Gather band diag + combine + mask + row max ----
        float mt0 = -1e30f, mt1 = -1e30f;
#pragma unroll
        for (int nt = 0; nt < 8; nt++) {
            int j0 = nt * 8 + 2 * tg;
            int c00 = j0 - g + 15;
            int c10 = j0 - g + 7;
            float p0 = slab[g * SPAD + c00];
            float p1 = slab[g * SPAD + c00 + 1];
            float p2 = slab[(g + 8) * SPAD + c10];
            float p3 = slab[(g + 8) * SPAD + c10 + 1];
            if (kt == 0 && nt == 0 && tg == 0) { p0 = 0.0f; p2 = 0.0f; } // key 0
            if (zq0) { p0 = 0.0f; p1 = 0.0f; }                           // q-row 0
            float mk0 = Msk[j0], mk1 = Msk[j0 + 1];
            sc[nt][0] = (sc[nt][0] + p0) * 0.125f + mk0;
            sc[nt][1] = (sc[nt][1] + p1) * 0.125f + mk1;
            sc[nt][2] = (sc[nt][2] + p2) * 0.125f + mk0;
            sc[nt][3] = (sc[nt][3] + p3) * 0.125f + mk1;
            mt0 = fmaxf(mt0, fmaxf(sc[nt][0], sc[nt][1]));
            mt1 = fmaxf(mt1, fmaxf(sc[nt][2], sc[nt][3]));
        }
        mt0 = fmaxf(mt0, __shfl_xor_sync(0xffffffffu, mt0, 1));
        mt0 = fmaxf(mt0, __shfl_xor_sync(0xffffffffu, mt0, 2));
        mt1 = fmaxf(mt1, __shfl_xor_sync(0xffffffffu, mt1, 1));
        mt1 = fmaxf(mt1, __shfl_xor_sync(0xffffffffu, mt1, 2));

        // ---- Online softmax ----
        float mn0 = fmaxf(m0, mt0), mn1 = fmaxf(m1, mt1);
        float c0 = __expf(m0 - mn0), c1 = __expf(m1 - mn1);
        m0 = mn0; m1 = mn1;
#pragma unroll
        for (int nt = 0; nt < 8; nt++) {
            oac[nt][0] *= c0; oac[nt][1] *= c0;
            oac[nt][2] *= c1; oac[nt][3] *= c1;
        }
        float rs0 = 0.0f, rs1 = 0.0f;
#pragma unroll
        for (int nt = 0; nt < 8; nt++) {
            sc[nt][0] = __expf(sc[nt][0] - mn0);
            sc[nt][1] = __expf(sc[nt][1] - mn0);
            sc[nt][2] = __expf(sc[nt][2] - mn1);
            sc[nt][3] = __expf(sc[nt][3] - mn1);
            rs0 += sc[nt][0] + sc[nt][1];
            rs1 += sc[nt][2] + sc[nt][3];
        }
        rs0 += __shfl_xor_sync(0xffffffffu, rs0, 1);
        rs0 += __shfl_xor_sync(0xffffffffu, rs0, 2);
        rs1 += __shfl_xor_sync(0xffffffffu, rs1, 1);
        rs1 += __shfl_xor_sync(0xffffffffu, rs1, 2);
        l0 = l0 * c0 + rs0;
        l1 = l1 * c1 + rs1;

        __syncwarp();

        // ---- Write P (fp16 half2 pairs) ----
#pragma unroll
        for (int nt = 0; nt < 8; nt++) {
            P32[swz32(g,     4 * nt + tg)] = pack_h2(sc[nt][0], sc[nt][1]);
            P32[swz32(g + 8, 4 * nt + tg)] = pack_h2(sc[nt][2], sc[nt][3]);
        }
        __syncwarp();

        // ---- O += P @ V ----
        uint32_t pf[4][4];
#pragma unroll
        for (int kc = 0; kc < 4; kc++) {
            pf[kc][0] = P32[swz32(g,     8 * kc + tg)];
            pf[kc][1] = P32[swz32(g + 8, 8 * kc + tg)];
            pf[kc][2] = P32[swz32(g,     8 * kc + tg + 4)];
            pf[kc][3] = P32[swz32(g + 8, 8 * kc + tg + 4)];
        }
#pragma unroll
        for (int nt = 0; nt < 8; nt++) {
            int n0 = nt * 8;
#pragma unroll
            for (int kc = 0; kc < 4; kc++) {
                uint32_t bf[2];
                bf[0] = Vtu[swz32(n0 + g, 8 * kc + tg)];
                bf[1] = Vtu[swz32(n0 + g, 8 * kc + tg + 4)];
                mma_f16(oac[nt], pf[kc], bf);
            }
        }
    }

    // ---- Epilogue (half out) ----
    float inv0 = 1.0f / l0, inv1 = 1.0f / l1;
    int r0 = q0 + r0l, r1 = q0 + r1l;
    size_t rowA = ((size_t)(b * SEQ + r0)) * DMODEL + h * DHEAD;
    size_t rowB = ((size_t)(b * SEQ + r1)) * DMODEL + h * DHEAD;
#pragma unroll
    for (int nt = 0; nt < 8; nt++) {
        int col = nt * 8 + 2 * tg;
        *(uint32_t*)(aoh + rowA + col) =
            pack_h2(oac[nt][0] * inv0, oac[nt][1] * inv0);
        *(uint32_t*)(aoh + rowB + col) =
            pack_h2(oac[nt][2] * inv1, oac[nt][3] * inv1);
    }
}

// ---------------------------------------------------------------------------
extern "C" void kernel_launch(void* const* d_in, const int* in_sizes, int n_in,
                              void* d_out, int out_size) {
    const float* x          = (const float*)d_in[0];
    const unsigned char* mk = (const unsigned char*)d_in[1];
    const float* Wqkv       = (const float*)d_in[2];
    const float* Wpe        = (const float*)d_in[3];
    const float* Wo         = (const float*)d_in[4];
    const float* cb         = (const float*)d_in[5];
    const float* pb         = (const float*)d_in[6];
    float* out              = (float*)d_out;

    __half *qkvh, *pekh, *aoh;
    float *pe, *pbias;
    cudaGetSymbolAddress((void**)&qkvh, g_qkvh);
    cudaGetSymbolAddress((void**)&pe,   g_pe);
    cudaGetSymbolAddress((void**)&pekh, g_pekh);
    cudaGetSymbolAddress((void**)&aoh,  g_aoh);
    cudaGetSymbolAddress((void**)&pbias, g_pbias);

    cudaFuncSetAttribute(gemm_f16_kernel<false, true>,
                         cudaFuncAttributeMaxDynamicSharedMemorySize,
                         GEMM16_SMEM_BYTES);
    cudaFuncSetAttribute(gemm_f16_kernel<true, false>,
                         cudaFuncAttributeMaxDynamicSharedMemorySize,
                         GEMM16_SMEM_BYTES);
    cudaFuncSetAttribute(attn_mma6_kernel,
                         cudaFuncAttributeMaxDynamicSharedMemorySize,
                         A5_SMEM_BYTES);

    pegen_kernel<<<(LPE * DMODEL + 255) / 256, 256>>>(pe);

    // qkv (half out)
    {
        dim3 grid(3072 / 128, 4096 / 128);
        gemm_f16_kernel<false, true><<<grid, 256, GEMM16_SMEM_BYTES>>>(
            x, Wqkv, qkvh, BSZ * SEQ, 3 * DMODEL, DMODEL);
    }
    // pe_key (half out)
    {
        dim3 grid(1024 / 128, (LPE + 127) / 128);
        gemm_f16_kernel<false, true><<<grid, 256, GEMM16_SMEM_BYTES>>>(
            pe, Wpe, pekh, LPE, DMODEL, DMODEL);
    }

    // pbias: warp per (h,l)
    pbias_kernel<<<(NHEAD * 2048 * 32) / 256, 256>>>(pekh, cb, pb, pbias);

    attn_mma6_kernel<<<BSZ * NHEAD * (SEQ / 256), 512, A5_SMEM_BYTES>>>(
        qkvh, pekh, mk, cb, pbias, aoh);

    // out = ao @ W_o (half A in, fp32 out)
    {
        dim3 grid(1024 / 128, 4096 / 128);
        gemm_f16_kernel<true, false><<<grid, 256, GEMM16_SMEM_BYTES>>>(
            aoh, Wo, out, BSZ * SEQ, DMODEL, DMODEL);
    }
}

// round 12
// speedup vs baseline: 2.1661x; 1.3230x over previous
#include <cuda_runtime.h>
#include <cuda_bf16.h>
#include <cuda_fp16.h>
#include <cstdint>
#include <math.h>

// Problem constants
#define BSZ 4
#define SEQ 1024
#define DMODEL 1024
#define NHEAD 16
#define DHEAD 64
#define LPE 2045   // 2*s-1, s = 1023

// Scratch (all intermediates fp16)
__device__ __half g_qkvh[BSZ * SEQ * 3 * DMODEL];
__device__ __half g_peh [LPE * DMODEL];
__device__ __half g_pekh[LPE * DMODEL];
__device__ __half g_aoh [BSZ * SEQ * DMODEL];
__device__ float  g_pbias[NHEAD * 2048];

// ---------------------------------------------------------------------------
__device__ __forceinline__ void mma_f16(float* d, const uint32_t* a,
                                        const uint32_t* b) {
    asm volatile(
        "mma.sync.aligned.m16n8k16.row.col.f32.f16.f16.f32 "
        "{%0,%1,%2,%3}, {%4,%5,%6,%7}, {%8,%9}, {%0,%1,%2,%3};\n"
        : "+f"(d[0]), "+f"(d[1]), "+f"(d[2]), "+f"(d[3])
        : "r"(a[0]), "r"(a[1]), "r"(a[2]), "r"(a[3]),
          "r"(b[0]), "r"(b[1]));
}

__device__ __forceinline__ uint32_t pack_h2(float x, float y) {
    __half2 h = __floats2half2_rn(x, y);
    return *(uint32_t*)&h;
}

__device__ __forceinline__ uint32_t cvta_smem(const void* p) {
    uint32_t a;
    asm("{ .reg .u64 t; cvta.to.shared.u64 t, %1; cvt.u32.u64 %0, t; }"
        : "=r"(a) : "l"(p));
    return a;
}

__device__ __forceinline__ void ldsm_x4(uint32_t* r, uint32_t a) {
    asm volatile("ldmatrix.sync.aligned.m8n8.x4.shared.b16 {%0,%1,%2,%3}, [%4];"
                 : "=r"(r[0]), "=r"(r[1]), "=r"(r[2]), "=r"(r[3]) : "r"(a));
}
__device__ __forceinline__ void ldsm_x4_t(uint32_t* r, uint32_t a) {
    asm volatile("ldmatrix.sync.aligned.m8n8.x4.trans.shared.b16 {%0,%1,%2,%3}, [%4];"
                 : "=r"(r[0]), "=r"(r[1]), "=r"(r[2]), "=r"(r[3]) : "r"(a));
}
__device__ __forceinline__ void ldsm_x2(uint32_t* r, uint32_t a) {
    asm volatile("ldmatrix.sync.aligned.m8n8.x2.shared.b16 {%0,%1}, [%2];"
                 : "=r"(r[0]), "=r"(r[1]) : "r"(a));
}

// XOR-swizzled 32-u32 (128B) row layout for fp16 tiles
__device__ __forceinline__ int swz32(int row, int cp) {
    return row * 32 + ((((cp >> 2) ^ (row & 7)) << 2) | (cp & 3));
}

// ---------------------------------------------------------------------------
__global__ void pegen_kernel(__half* __restrict__ peh) {
    int idx = blockIdx.x * blockDim.x + threadIdx.x;
    if (idx >= LPE * DMODEL) return;
    int l  = idx >> 10;
    int kk = idx & 1023;
    int p2 = kk & ~1;
    float expnt = (float)p2 / 1024.0f;
    float denom = powf(10000.0f, expnt);
    float t = (float)(l - 1022);
    float ang = t / denom;
    float v = (kk & 1) ? cosf(ang) : sinf(ang);
    peh[idx] = __float2half_rn(v * 0.03125f);
}

// pbias[h][l]; warp per (h,l)
__global__ void pbias_kernel(const __half* __restrict__ pek,
                             const float* __restrict__ cb,
                             const float* __restrict__ pb,
                             float* __restrict__ pbias) {
    int gw = (blockIdx.x * blockDim.x + threadIdx.x) >> 5;
    int lane = threadIdx.x & 31;
    if (gw >= NHEAD * 2048) return;
    int h = gw >> 11, l = gw & 2047;
    float s = 0.0f;
    if (l < LPE) {
        const __half* row = pek + (size_t)l * DMODEL + h * DHEAD;
        float d0 = pb[h * DHEAD + lane]      - cb[h * DHEAD + lane];
        float d1 = pb[h * DHEAD + 32 + lane] - cb[h * DHEAD + 32 + lane];
        s = d0 * __half2float(row[lane]) + d1 * __half2float(row[32 + lane]);
#pragma unroll
        for (int off = 16; off; off >>= 1)
            s += __shfl_xor_sync(0xffffffffu, s, off);
    }
    if (lane == 0) pbias[gw] = s;
}

// ===========================================================================
// FP16 mma.sync GEMM with ldmatrix fragment loads.
// A_HALF / C_HALF template as in R11.  BM=128, BN=128, BK=64, 256 threads.
// ===========================================================================
#define F_STAGE 4096
#define GEMM16_SMEM_BYTES (4 * F_STAGE * 4)

template <bool A_HALF, bool C_HALF>
__global__ __launch_bounds__(256)
void gemm_f16_kernel(const void* __restrict__ Av, const float* __restrict__ B,
                     void* __restrict__ Cv, int M, int N, int K) {
    extern __shared__ uint32_t smu[];
    uint32_t* AsBase = smu;
    uint32_t* BsBase = smu + 2 * F_STAGE;
    uint32_t smemb = cvta_smem(smu);

    const float*  Af = (const float*)Av;
    const __half* Ah = (const __half*)Av;
    float*  Cf = (float*)Cv;
    __half* Ch = (__half*)Cv;

    int tid  = threadIdx.x;
    int wid  = tid >> 5;
    int lane = tid & 31;
    int g    = lane >> 2;
    int tg   = lane & 3;
    int wm0  = (wid >> 2) * 64;
    int wn0  = (wid & 3) * 32;
    int bm = blockIdx.y * 128;
    int bn = blockIdx.x * 128;

    // ldmatrix lane address components
    int rA = (lane & 7) + 8 * ((lane >> 3) & 1);   // A/P-style row
    int cA = 4 * (lane >> 4);                      // A-style k-chunk offset
    int rB = 8 * (lane >> 4) + (lane & 7);         // B-style row (n dim)
    int cB = 4 * ((lane >> 3) & 1);                // B-style k-chunk offset

    float acc[4][4][4];
#pragma unroll
    for (int mt = 0; mt < 4; mt++)
#pragma unroll
        for (int nt = 0; nt < 4; nt++)
#pragma unroll
            for (int r = 0; r < 4; r++) acc[mt][nt][r] = 0.0f;

    float4 pa[4][2];
    uint4  pau[4];
    float  pbv[4][8];

    auto ldTile = [&](int k0) {
#pragma unroll
        for (int it = 0; it < 4; it++) {
            int idx = tid + 256 * it;
            int i = idx >> 3, gq = idx & 7;
            int gr = bm + i;
            if (A_HALF) {
                pau[it] = (gr < M)
                    ? *(const uint4*)(Ah + (size_t)gr * K + k0 + 8 * gq)
                    : make_uint4(0u, 0u, 0u, 0u);
            } else {
                if (gr < M) {
                    const float* p = Af + (size_t)gr * K + k0 + 8 * gq;
                    pa[it][0] = *(const float4*)p;
                    pa[it][1] = *(const float4*)(p + 4);
                } else {
                    pa[it][0] = make_float4(0.f, 0.f, 0.f, 0.f);
                    pa[it][1] = pa[it][0];
                }
            }
        }
#pragma unroll
        for (int it = 0; it < 4; it++) {
            int idx = tid + 256 * it;
            int n = idx & 127, jq = idx >> 7;
            const float* p = B + (size_t)(k0 + 8 * jq) * N + bn + n;
#pragma unroll
            for (int e = 0; e < 8; e++)
                pbv[it][e] = p[(size_t)e * N];
        }
    };

    auto stsTile = [&](int s) {
        uint32_t* as = AsBase + s * F_STAGE;
        uint32_t* bs = BsBase + s * F_STAGE;
#pragma unroll
        for (int it = 0; it < 4; it++) {
            int idx = tid + 256 * it;
            int i = idx >> 3, gq = idx & 7;
            uint4 o;
            if (A_HALF) {
                o = pau[it];
            } else {
                o.x = pack_h2(pa[it][0].x, pa[it][0].y);
                o.y = pack_h2(pa[it][0].z, pa[it][0].w);
                o.z = pack_h2(pa[it][1].x, pa[it][1].y);
                o.w = pack_h2(pa[it][1].z, pa[it][1].w);
            }
            *(uint4*)(as + i * 32 + ((gq ^ (i & 7)) << 2)) = o;
        }
#pragma unroll
        for (int it = 0; it < 4; it++) {
            int idx = tid + 256 * it;
            int n = idx & 127, jq = idx >> 7;
            uint4 o;
            o.x = pack_h2(pbv[it][0], pbv[it][1]);
            o.y = pack_h2(pbv[it][2], pbv[it][3]);
            o.z = pack_h2(pbv[it][4], pbv[it][5]);
            o.w = pack_h2(pbv[it][6], pbv[it][7]);
            *(uint4*)(bs + n * 32 + ((jq ^ (n & 7)) << 2)) = o;
        }
    };

    auto compute = [&](int s) {
        uint32_t asB = smemb + (s * F_STAGE) * 4;
        uint32_t bsB = smemb + ((2 + s) * F_STAGE) * 4;
#pragma unroll
        for (int kc = 0; kc < 4; kc++) {
            uint32_t af[4][4], bf[2][4];
#pragma unroll
            for (int mt = 0; mt < 4; mt++)
                ldsm_x4(af[mt], asB + 4 * swz32(wm0 + 16 * mt + rA, 8 * kc + cA));
#pragma unroll
            for (int np = 0; np < 2; np++)
                ldsm_x4(bf[np], bsB + 4 * swz32(wn0 + 16 * np + rB, 8 * kc + cB));
#pragma unroll
            for (int mt = 0; mt < 4; mt++)
#pragma unroll
                for (int np = 0; np < 2; np++) {
                    mma_f16(acc[mt][2 * np],     af[mt], bf[np]);
                    mma_f16(acc[mt][2 * np + 1], af[mt], bf[np] + 2);
                }
        }
    };

    int T = K >> 6;
    ldTile(0);
    stsTile(0);
    __syncthreads();

    for (int t = 0; t < T; t++) {
        int s = t & 1;
        if (t + 1 < T) ldTile((t + 1) << 6);
        compute(s);
        if (t + 1 < T) {
            stsTile(s ^ 1);
            __syncthreads();
        }
    }

#pragma unroll
    for (int mt = 0; mt < 4; mt++) {
        int r0 = bm + wm0 + mt * 16 + g;
        int r1 = r0 + 8;
#pragma unroll
        for (int nt = 0; nt < 4; nt++) {
            int col = bn + wn0 + nt * 8 + 2 * tg;
            if (C_HALF) {
                if (r0 < M)
                    *(uint32_t*)(Ch + (size_t)r0 * N + col) =
                        pack_h2(acc[mt][nt][0], acc[mt][nt][1]);
                if (r1 < M)
                    *(uint32_t*)(Ch + (size_t)r1 * N + col) =
                        pack_h2(acc[mt][nt][2], acc[mt][nt][3]);
            } else {
                if (r0 < M)
                    *(float2*)(Cf + (size_t)r0 * N + col) =
                        make_float2(acc[mt][nt][0], acc[mt][nt][1]);
                if (r1 < M)
                    *(float2*)(Cf + (size_t)r1 * N + col) =
                        make_float2(acc[mt][nt][2], acc[mt][nt][3]);
            }
        }
    }
}

// ===========================================================================
// Attention v7: ldmatrix fragment loads, V staged row-major + x4.trans.
// 512 threads, 16 warps x 16 q-rows, PE ring, pos-bias folded.
// ===========================================================================
#define A5_KS 0
#define A5_VS 2048
#define A5_PE 4096
#define A5_BIAS 16384
#define A5_MSK 16768
#define A5_U 16832
#define A5_SMEM_BYTES (38336 * 4)
#define SPAD 84
#define SLAB5 1344

__global__ __launch_bounds__(512, 1)
void attn_mma7_kernel(const __half* __restrict__ qkvh,
                      const __half* __restrict__ pekh,
                      const unsigned char* __restrict__ mask,
                      const float* __restrict__ cb,
                      const float* __restrict__ pbias,
                      __half* __restrict__ aoh) {
    extern __shared__ float sm[];
    uint32_t* Ksu  = (uint32_t*)sm + A5_KS;
    uint32_t* Vsu  = (uint32_t*)sm + A5_VS;
    uint32_t* PElu = (uint32_t*)sm + A5_PE;
    float* Bias = sm + A5_BIAS;
    float* Msk  = sm + A5_MSK;
    float* U    = sm + A5_U;
    uint32_t* Qs = (uint32_t*)U;
    uint32_t smemb = cvta_smem(sm);

    int tid = threadIdx.x;
    int w = tid >> 5;
    int lane = tid & 31;
    int g = lane >> 2;
    int tg = lane & 3;
    int qt = blockIdx.x & 3;
    int bh = blockIdx.x >> 2;
    int h  = bh & 15;
    int b  = bh >> 4;
    int q0 = qt * 256;

    uint32_t ksB = smemb;                       // K tile byte base
    uint32_t vsB = smemb + A5_VS * 4;
    uint32_t peB = smemb + A5_PE * 4;
    uint32_t pB  = smemb + (A5_U + w * SLAB5) * 4;

    // ldmatrix lane address components
    int rA = (lane & 7) + 8 * ((lane >> 3) & 1);   // A-frag rows (P)
    int cA = 4 * (lane >> 4);
    int rB = 8 * (lane >> 4) + (lane & 7);         // B-frag rows (K)
    int cB = 4 * ((lane >> 3) & 1);
    int rV = lane & 15;                            // V trans k-rows
    int cV = 4 * (lane >> 4);                      // V trans n-chunk

    const float* cbh = cb + h * DHEAD;
    const float* pbh_bias = pbias + h * 2048;
    int lbase0 = 767 - q0;

    // ---- Prologue: Qc, PE [0,320), Bias ----
    for (int idx = tid; idx < 2048; idx += 512) {
        int i = idx >> 3, gq = idx & 7;
        int c8 = gq * 8;
        uint4 v = *(const uint4*)(qkvh + ((size_t)(b * SEQ + q0 + i)) * 3072
                                  + h * 192 + c8);
        __half2* hp = (__half2*)&v;
        uint4 o;
#pragma unroll
        for (int e = 0; e < 4; e++) {
            float2 f = __half22float2(hp[e]);
            ((uint32_t*)&o)[e] = pack_h2(f.x + cbh[c8 + 2 * e],
                                         f.y + cbh[c8 + 2 * e + 1]);
        }
        *(uint4*)(Qs + i * 32 + ((gq ^ (i & 7)) << 2)) = o;
    }
    for (int idx = tid; idx < 2560; idx += 512) {
        int sl_ = idx >> 3, gq = idx & 7;
        int lg = lbase0 + sl_;
        uint4 v = (lg >= 0 && lg < LPE)
            ? *(const uint4*)(pekh + (size_t)lg * DMODEL + h * DHEAD + 8 * gq)
            : make_uint4(0u, 0u, 0u, 0u);
        *(uint4*)(PElu + sl_ * 32 + ((gq ^ (sl_ & 7)) << 2)) = v;
    }
    if (tid < 320) {
        int lg = lbase0 + tid;
        Bias[tid] = (lg >= 0 && lg < LPE) ? pbh_bias[lg] : 0.0f;
    }
    __syncthreads();

    // ---- Persist Qc fragments ----
    uint32_t qcf[4][4];
    int r0l = 16 * w + g, r1l = r0l + 8;
#pragma unroll
    for (int kc = 0; kc < 4; kc++) {
        qcf[kc][0] = Qs[swz32(r0l, 8 * kc + tg)];
        qcf[kc][1] = Qs[swz32(r1l, 8 * kc + tg)];
        qcf[kc][2] = Qs[swz32(r0l, 8 * kc + tg + 4)];
        qcf[kc][3] = Qs[swz32(r1l, 8 * kc + tg + 4)];
    }
    __syncthreads();

    bool zq0 = (q0 == 0 && w == 0 && g == 0);

    float oac[8][4];
#pragma unroll
    for (int nt = 0; nt < 8; nt++)
#pragma unroll
        for (int r = 0; r < 4; r++) oac[nt][r] = 0.0f;
    float m0 = -1e30f, m1 = -1e30f, l0 = 0.0f, l1 = 0.0f;

    float* slab = U + w * SLAB5;
    uint32_t* P32 = (uint32_t*)slab;
    int s0base = 30 - 2 * w;

    for (int kt = 0; kt < 16; kt++) {
        int k0 = kt * 64;
        int ktm = (64 * kt) % 384;
        __syncthreads();

        // ---- Stage K and V (pure swizzled uint4 copies) ----
        {
            int i = tid >> 3, gq = tid & 7;
            size_t base = ((size_t)(b * SEQ + k0 + i)) * 3072 + h * 192;
            uint4 kv = *(const uint4*)(qkvh + base + 64 + 8 * gq);
            uint4 vv = *(const uint4*)(qkvh + base + 128 + 8 * gq);
            int sa = i * 32 + ((gq ^ (i & 7)) << 2);
            *(uint4*)(Ksu + sa) = kv;
            *(uint4*)(Vsu + sa) = vv;
        }
        if (tid < 64) Msk[tid] = mask[b * SEQ + k0 + tid] ? -1e30f : 0.0f;
        __syncthreads();

        // ---- PE ring prefetch for kt+1 (overlaps compute) ----
        if (kt < 15) {
            {
                int r = tid >> 3, gq = tid & 7;
                int off = 64 * kt + 320 + r;
                int slot = off % 384;
                int lg = lbase0 + off;
                uint4 v = (lg >= 0 && lg < LPE)
                    ? *(const uint4*)(pekh + (size_t)lg * DMODEL + h * DHEAD + 8 * gq)
                    : make_uint4(0u, 0u, 0u, 0u);
                *(uint4*)(PElu + slot * 32 + ((gq ^ (slot & 7)) << 2)) = v;
            }
            if (tid < 64) {
                int off = 64 * kt + 320 + tid;
                int lg = lbase0 + off;
                Bias[off % 384] = (lg >= 0 && lg < LPE) ? pbh_bias[lg] : 0.0f;
            }
        }

        // ---- Band: Spos = Qc @ PE^T + bias (10 tiles, x2 ldmatrix) ----
#pragma unroll
        for (int t = 0; t < 10; t++) {
            int m = s0base + t;
            int sr = ktm + 8 * m; if (sr >= 384) sr -= 384;
            float sp[4] = {0.f, 0.f, 0.f, 0.f};
            int rowP = sr + (lane & 7);
#pragma unroll
            for (int kc = 0; kc < 4; kc++) {
                uint32_t bf[2];
                ldsm_x2(bf, peB + 4 * swz32(rowP, 8 * kc + cB));
                mma_f16(sp, qcf[kc], bf);
            }
            int bidx = ktm + 8 * m + 2 * tg; if (bidx >= 384) bidx -= 384;
            float b0 = Bias[bidx], b1 = Bias[bidx + 1];
            int cc0 = 8 * t + 2 * tg;
            slab[g * SPAD + cc0]           = sp[0] + b0;
            slab[g * SPAD + cc0 + 1]       = sp[1] + b1;
            slab[(g + 8) * SPAD + cc0]     = sp[2] + b0;
            slab[(g + 8) * SPAD + cc0 + 1] = sp[3] + b1;
        }
        __syncwarp();

        // ---- Content scores: Qc @ K^T (x4 ldmatrix, 2 n-tiles/instr) ----
        float sc[8][4];
#pragma unroll
        for (int nt = 0; nt < 8; nt++)
#pragma unroll
            for (int r = 0; r < 4; r++) sc[nt][r] = 0.0f;
#pragma unroll
        for (int ntp = 0; ntp < 4; ntp++) {
            int rowK = 16 * ntp + rB;
#pragma unroll
            for (int kc = 0; kc < 4; kc++) {
                uint32_t r[4];
                ldsm_x4(r, ksB + 4 * swz32(rowK, 8 * kc + cB));
                mma_f16(sc[2 * ntp],     qcf[kc], r);
                mma_f16(sc[2 * ntp + 1], qcf[kc], r + 2);
            }
        }

        // ---- Gather band diag + combine + mask + row max ----
        float mt0 = -1e30f, mt1 = -1e30f;
#pragma unroll
        for (int nt = 0; nt < 8; nt++) {
            int j0 = nt * 8 + 2 * tg;
            int c00 = j0 - g + 15;
            int c10 = j0 - g + 7;
            float p0 = slab[g * SPAD + c00];
            float p1 = slab[g * SPAD + c00 + 1];
            float p2 = slab[(g + 8) * SPAD + c10];
            float p3 = slab[(g + 8) * SPAD + c10 + 1];
            if (kt == 0 && nt == 0 && tg == 0) { p0 = 0.0f; p2 = 0.0f; }
            if (zq0) { p0 = 0.0f; p1 = 0.0f; }
            float mk0 = Msk[j0], mk1 = Msk[j0 + 1];
            sc[nt][0] = (sc[nt][0] + p0) * 0.125f + mk0;
            sc[nt][1] = (sc[nt][1] + p1) * 0.125f + mk1;
            sc[nt][2] = (sc[nt][2] + p2) * 0.125f + mk0;
            sc[nt][3] = (sc[nt][3] + p3) * 0.125f + mk1;
            mt0 = fmaxf(mt0, fmaxf(sc[nt][0], sc[nt][1]));
            mt1 = fmaxf(mt1, fmaxf(sc[nt][2], sc[nt][3]));
        }
        mt0 = fmaxf(mt0, __shfl_xor_sync(0xffffffffu, mt0, 1));
        mt0 = fmaxf(mt0, __shfl_xor_sync(0xffffffffu, mt0, 2));
        mt1 = fmaxf(mt1, __shfl_xor_sync(0xffffffffu, mt1, 1));
        mt1 = fmaxf(mt1, __shfl_xor_sync(0xffffffffu, mt1, 2));

        // ---- Online softmax ----
        float mn0 = fmaxf(m0, mt0), mn1 = fmaxf(m1, mt1);
        float c0 = __expf(m0 - mn0), c1 = __expf(m1 - mn1);
        m0 = mn0; m1 = mn1;
#pragma unroll
        for (int nt = 0; nt < 8; nt++) {
            oac[nt][0] *= c0; oac[nt][1] *= c0;
            oac[nt][2] *= c1; oac[nt][3] *= c1;
        }
        float rs0 = 0.0f, rs1 = 0.0f;
#pragma unroll
        for (int nt = 0; nt < 8; nt++) {
            sc[nt][0] = __expf(sc[nt][0] - mn0);
            sc[nt][1] = __expf(sc[nt][1] - mn0);
            sc[nt][2] = __expf(sc[nt][2] - mn1);
            sc[nt][3] = __expf(sc[nt][3] - mn1);
            rs0 += sc[nt][0] + sc[nt][1];
            rs1 += sc[nt][2] + sc[nt][3];
        }
        rs0 += __shfl_xor_sync(0xffffffffu, rs0, 1);
        rs0 += __shfl_xor_sync(0xffffffffu, rs0, 2);
        rs1 += __shfl_xor_sync(0xffffffffu, rs1, 1);
        rs1 += __shfl_xor_sync(0xffffffffu, rs1, 2);
        l0 = l0 * c0 + rs0;
        l1 = l1 * c1 + rs1;

        __syncwarp();

        // ---- Write P (fp16 half2 pairs) ----
#pragma unroll
        for (int nt = 0; nt < 8; nt++) {
            P32[swz32(g,     4 * nt + tg)] = pack_h2(sc[nt][0], sc[nt][1]);
            P32[swz32(g + 8, 4 * nt + tg)] = pack_h2(sc[nt][2], sc[nt][3]);
        }
        __syncwarp();

        // ---- O += P @ V (A-frags x4, B-frags x4.trans) ----
        uint32_t pf[4][4];
#pragma unroll
        for (int kc = 0; kc < 4; kc++)
            ldsm_x4(pf[kc], pB + 4 * swz32(rA, 8 * kc + cA));
#pragma unroll
        for (int ntp = 0; ntp < 4; ntp++) {
            int cpV = 8 * ntp + cV;
#pragma unroll
            for (int kc = 0; kc < 4; kc++) {
                uint32_t r[4];
                ldsm_x4_t(r, vsB + 4 * swz32(16 * kc + rV, cpV));
                mma_f16(oac[2 * ntp],     pf[kc], r);
                mma_f16(oac[2 * ntp + 1], pf[kc], r + 2);
            }
        }
    }

    // ---- Epilogue (half out) ----
    float inv0 = 1.0f / l0, inv1 = 1.0f / l1;
    int r0 = q0 + r0l, r1 = q0 + r1l;
    size_t rowA = ((size_t)(b * SEQ + r0)) * DMODEL + h * DHEAD;
    size_t rowB = ((size_t)(b * SEQ + r1)) * DMODEL + h * DHEAD;
#pragma unroll
    for (int nt = 0; nt < 8; nt++) {
        int col = nt * 8 + 2 * tg;
        *(uint32_t*)(aoh + rowA + col) =
            pack_h2(oac[nt][0] * inv0, oac[nt][1] * inv0);
        *(uint32_t*)(aoh + rowB + col) =
            pack_h2(oac[nt][2] * inv1, oac[nt][3] * inv1);
    }
}

// ---------------------------------------------------------------------------
extern "C" void kernel_launch(void* const* d_in, const int* in_sizes, int n_in,
                              void* d_out, int out_size) {
    const float* x          = (const float*)d_in[0];
    const unsigned char* mk = (const unsigned char*)d_in[1];
    const float* Wqkv       = (const float*)d_in[2];
    const float* Wpe        = (const float*)d_in[3];
    const float* Wo         = (const float*)d_in[4];
    const float* cb         = (const float*)d_in[5];
    const float* pb         = (const float*)d_in[6];
    float* out              = (float*)d_out;

    __half *qkvh, *peh, *pekh, *aoh;
    float *pbias;
    cudaGetSymbolAddress((void**)&qkvh, g_qkvh);
    cudaGetSymbolAddress((void**)&peh,  g_peh);
    cudaGetSymbolAddress((void**)&pekh, g_pekh);
    cudaGetSymbolAddress((void**)&aoh,  g_aoh);
    cudaGetSymbolAddress((void**)&pbias, g_pbias);

    cudaFuncSetAttribute(gemm_f16_kernel<false, true>,
                         cudaFuncAttributeMaxDynamicSharedMemorySize,
                         GEMM16_SMEM_BYTES);
    cudaFuncSetAttribute(gemm_f16_kernel<true, true>,
                         cudaFuncAttributeMaxDynamicSharedMemorySize,
                         GEMM16_SMEM_BYTES);
    cudaFuncSetAttribute(gemm_f16_kernel<true, false>,
                         cudaFuncAttributeMaxDynamicSharedMemorySize,
                         GEMM16_SMEM_BYTES);
    cudaFuncSetAttribute(attn_mma7_kernel,
                         cudaFuncAttributeMaxDynamicSharedMemorySize,
                         A5_SMEM_BYTES);

    pegen_kernel<<<(LPE * DMODEL + 255) / 256, 256>>>(peh);

    // qkv = x @ W_qkv (fp32 A, half C)
    {
        dim3 grid(3072 / 128, 4096 / 128);
        gemm_f16_kernel<false, true><<<grid, 256, GEMM16_SMEM_BYTES>>>(
            x, Wqkv, qkvh, BSZ * SEQ, 3 * DMODEL, DMODEL);
    }
    // pe_key = pe @ W_pe (half A, half C)
    {
        dim3 grid(1024 / 128, (LPE + 127) / 128);
        gemm_f16_kernel<true, true><<<grid, 256, GEMM16_SMEM_BYTES>>>(
            peh, Wpe, pekh, LPE, DMODEL, DMODEL);
    }

    pbias_kernel<<<(NHEAD * 2048 * 32) / 256, 256>>>(pekh, cb, pb, pbias);

    attn_mma7_kernel<<<BSZ * NHEAD * (SEQ / 256), 512, A5_SMEM_BYTES>>>(
        qkvh, pekh, mk, cb, pbias, aoh);

    // out = ao @ W_o (half A, fp32 C)
    {
        dim3 grid(1024 / 128, 4096 / 128);
        gemm_f16_kernel<true, false><<<grid, 256, GEMM16_SMEM_BYTES>>>(
            aoh, Wo, out, BSZ * SEQ, DMODEL, DMODEL);
    }
}

// round 13
// speedup vs baseline: 2.6386x; 1.2181x over previous
#include <cuda_runtime.h>
#include <cuda_bf16.h>
#include <cuda_fp16.h>
#include <cstdint>
#include <math.h>

// Problem constants
#define BSZ 4
#define SEQ 1024
#define DMODEL 1024
#define NHEAD 16
#define DHEAD 64
#define LPE 2045   // 2*s-1, s = 1023

// Scratch (all operands fp16)
__device__ __half g_xh  [BSZ * SEQ * DMODEL];
__device__ __half g_wqkvh[DMODEL * 3 * DMODEL];
__device__ __half g_wpeh [DMODEL * DMODEL];
__device__ __half g_woh  [DMODEL * DMODEL];
__device__ __half g_qkvh[BSZ * SEQ * 3 * DMODEL];
__device__ __half g_peh [LPE * DMODEL];
__device__ __half g_pekh[LPE * DMODEL];
__device__ __half g_aoh [BSZ * SEQ * DMODEL];
__device__ float  g_pbias[NHEAD * 2048];

// ---------------------------------------------------------------------------
__device__ __forceinline__ void mma_f16(float* d, const uint32_t* a,
                                        const uint32_t* b) {
    asm volatile(
        "mma.sync.aligned.m16n8k16.row.col.f32.f16.f16.f32 "
        "{%0,%1,%2,%3}, {%4,%5,%6,%7}, {%8,%9}, {%0,%1,%2,%3};\n"
        : "+f"(d[0]), "+f"(d[1]), "+f"(d[2]), "+f"(d[3])
        : "r"(a[0]), "r"(a[1]), "r"(a[2]), "r"(a[3]),
          "r"(b[0]), "r"(b[1]));
}

__device__ __forceinline__ uint32_t pack_h2(float x, float y) {
    __half2 h = __floats2half2_rn(x, y);
    return *(uint32_t*)&h;
}

__device__ __forceinline__ uint32_t cvta_smem(const void* p) {
    uint32_t a;
    asm("{ .reg .u64 t; cvta.to.shared.u64 t, %1; cvt.u32.u64 %0, t; }"
        : "=r"(a) : "l"(p));
    return a;
}

__device__ __forceinline__ void ldsm_x4(uint32_t* r, uint32_t a) {
    asm volatile("ldmatrix.sync.aligned.m8n8.x4.shared.b16 {%0,%1,%2,%3}, [%4];"
                 : "=r"(r[0]), "=r"(r[1]), "=r"(r[2]), "=r"(r[3]) : "r"(a));
}
__device__ __forceinline__ void ldsm_x4_t(uint32_t* r, uint32_t a) {
    asm volatile("ldmatrix.sync.aligned.m8n8.x4.trans.shared.b16 {%0,%1,%2,%3}, [%4];"
                 : "=r"(r[0]), "=r"(r[1]), "=r"(r[2]), "=r"(r[3]) : "r"(a));
}
__device__ __forceinline__ void ldsm_x2(uint32_t* r, uint32_t a) {
    asm volatile("ldmatrix.sync.aligned.m8n8.x2.shared.b16 {%0,%1}, [%2];"
                 : "=r"(r[0]), "=r"(r[1]) : "r"(a));
}

__device__ __forceinline__ void cp16(uint32_t dst, const void* src, int nbytes) {
    asm volatile("cp.async.cg.shared.global [%0], [%1], 16, %2;"
                 :: "r"(dst), "l"(src), "r"(nbytes));
}
#define CP_COMMIT asm volatile("cp.async.commit_group;")
#define CP_WAIT0  asm volatile("cp.async.wait_group 0;")

// XOR-swizzled row layouts
__device__ __forceinline__ int swz32(int row, int cp) {       // 32-u32 rows
    return row * 32 + ((((cp >> 2) ^ (row & 7)) << 2) | (cp & 3));
}
__device__ __forceinline__ int swz64(int row, int cp) {       // 64-u32 rows
    return row * 64 + ((((cp >> 2) ^ (row & 7)) << 2) | (cp & 3));
}

// ---------------------------------------------------------------------------
__global__ void f2h_kernel(const float* __restrict__ in, __half* __restrict__ out,
                           int n) {
    int i = (blockIdx.x * blockDim.x + threadIdx.x) * 4;
    if (i >= n) return;
    float4 v = *(const float4*)(in + i);
    uint2 o;
    o.x = pack_h2(v.x, v.y);
    o.y = pack_h2(v.z, v.w);
    *(uint2*)(out + i) = o;
}

__global__ void pegen_kernel(__half* __restrict__ peh) {
    int idx = blockIdx.x * blockDim.x + threadIdx.x;
    if (idx >= LPE * DMODEL) return;
    int l  = idx >> 10;
    int kk = idx & 1023;
    int p2 = kk & ~1;
    float expnt = (float)p2 / 1024.0f;
    float denom = powf(10000.0f, expnt);
    float t = (float)(l - 1022);
    float ang = t / denom;
    float v = (kk & 1) ? cosf(ang) : sinf(ang);
    peh[idx] = __float2half_rn(v * 0.03125f);
}

// pbias[h][l]; warp per (h,l)
__global__ void pbias_kernel(const __half* __restrict__ pek,
                             const float* __restrict__ cb,
                             const float* __restrict__ pb,
                             float* __restrict__ pbias) {
    int gw = (blockIdx.x * blockDim.x + threadIdx.x) >> 5;
    int lane = threadIdx.x & 31;
    if (gw >= NHEAD * 2048) return;
    int h = gw >> 11, l = gw & 2047;
    float s = 0.0f;
    if (l < LPE) {
        const __half* row = pek + (size_t)l * DMODEL + h * DHEAD;
        float d0 = pb[h * DHEAD + lane]      - cb[h * DHEAD + lane];
        float d1 = pb[h * DHEAD + 32 + lane] - cb[h * DHEAD + 32 + lane];
        s = d0 * __half2float(row[lane]) + d1 * __half2float(row[32 + lane]);
#pragma unroll
        for (int off = 16; off; off >>= 1)
            s += __shfl_xor_sync(0xffffffffu, s, off);
    }
    if (lane == 0) pbias[gw] = s;
}

// ===========================================================================
// All-half GEMM with cp.async staging + ldmatrix fragments.
// C[M,N] = A[M,K] @ B[K,N], A/B half row-major.  BM=128, BN=128, BK=64.
// A tile: 128 x 32u32 swz32.  B tile: 64 k-rows x 64u32 swz64 (natural
// layout, fragments via ldmatrix.x4.trans).  256 threads, double buffer.
// ===========================================================================
#define F_STAGE 4096
#define GEMMH_SMEM_BYTES (4 * F_STAGE * 4)   // 64 KB

template <bool C_HALF>
__global__ __launch_bounds__(256)
void gemm_h_kernel(const __half* __restrict__ A, const __half* __restrict__ B,
                   void* __restrict__ Cv, int M, int N, int K) {
    extern __shared__ uint32_t smu[];
    uint32_t smemb = cvta_smem(smu);

    float*  Cf = (float*)Cv;
    __half* Ch = (__half*)Cv;

    int tid  = threadIdx.x;
    int wid  = tid >> 5;
    int lane = tid & 31;
    int g    = lane >> 2;
    int tg   = lane & 3;
    int wm0  = (wid >> 2) * 64;
    int wn0  = (wid & 3) * 32;
    int bm = blockIdx.y * 128;
    int bn = blockIdx.x * 128;

    // ldmatrix lane address components
    int rA = (lane & 7) + 8 * ((lane >> 3) & 1);
    int cA = 4 * (lane >> 4);
    int rV = lane & 15;            // trans: k-rows
    int cV = 4 * (lane >> 4);      // trans: n-chunk offset (u32)

    float acc[4][4][4];
#pragma unroll
    for (int mt = 0; mt < 4; mt++)
#pragma unroll
        for (int nt = 0; nt < 4; nt++)
#pragma unroll
            for (int r = 0; r < 4; r++) acc[mt][nt][r] = 0.0f;

    // cp.async staging: A 4x16B + B 4x16B per thread
    auto stage = [&](int s, int k0) {
        uint32_t asB = smemb + (s * F_STAGE) * 4;
        uint32_t bsB = smemb + ((2 + s) * F_STAGE) * 4;
#pragma unroll
        for (int it = 0; it < 4; it++) {
            int idx = tid + 256 * it;
            int i = idx >> 3, gq = idx & 7;
            int gr = bm + i;
            uint32_t dst = asB + 4 * (i * 32 + ((gq ^ (i & 7)) << 2));
            cp16(dst, A + (size_t)gr * K + k0 + 8 * gq, gr < M ? 16 : 0);
        }
#pragma unroll
        for (int it = 0; it < 4; it++) {
            int idx = tid + 256 * it;
            int kr = idx >> 4, cq = idx & 15;
            uint32_t dst = bsB + 4 * (kr * 64 + ((cq ^ (kr & 7)) << 2));
            cp16(dst, B + (size_t)(k0 + kr) * N + bn + 8 * cq, 16);
        }
    };

    auto compute = [&](int s) {
        uint32_t asB = smemb + (s * F_STAGE) * 4;
        uint32_t bsB = smemb + ((2 + s) * F_STAGE) * 4;
#pragma unroll
        for (int kc = 0; kc < 4; kc++) {
            uint32_t af[4][4], bf[2][4];
#pragma unroll
            for (int mt = 0; mt < 4; mt++)
                ldsm_x4(af[mt], asB + 4 * swz32(wm0 + 16 * mt + rA, 8 * kc + cA));
#pragma unroll
            for (int np = 0; np < 2; np++)
                ldsm_x4_t(bf[np], bsB + 4 * swz64(16 * kc + rV,
                                                  wn0 / 2 + 8 * np + cV));
#pragma unroll
            for (int mt = 0; mt < 4; mt++)
#pragma unroll
                for (int np = 0; np < 2; np++) {
                    mma_f16(acc[mt][2 * np],     af[mt], bf[np]);
                    mma_f16(acc[mt][2 * np + 1], af[mt], bf[np] + 2);
                }
        }
    };

    int T = K >> 6;
    stage(0, 0);
    CP_COMMIT;

    for (int t = 0; t < T; t++) {
        CP_WAIT0;
        __syncthreads();
        if (t + 1 < T) {
            stage((t + 1) & 1, (t + 1) << 6);
            CP_COMMIT;
        }
        compute(t & 1);
    }

#pragma unroll
    for (int mt = 0; mt < 4; mt++) {
        int r0 = bm + wm0 + mt * 16 + g;
        int r1 = r0 + 8;
#pragma unroll
        for (int nt = 0; nt < 4; nt++) {
            int col = bn + wn0 + nt * 8 + 2 * tg;
            if (C_HALF) {
                if (r0 < M)
                    *(uint32_t*)(Ch + (size_t)r0 * N + col) =
                        pack_h2(acc[mt][nt][0], acc[mt][nt][1]);
                if (r1 < M)
                    *(uint32_t*)(Ch + (size_t)r1 * N + col) =
                        pack_h2(acc[mt][nt][2], acc[mt][nt][3]);
            } else {
                if (r0 < M)
                    *(float2*)(Cf + (size_t)r0 * N + col) =
                        make_float2(acc[mt][nt][0], acc[mt][nt][1]);
                if (r1 < M)
                    *(float2*)(Cf + (size_t)r1 * N + col) =
                        make_float2(acc[mt][nt][2], acc[mt][nt][3]);
            }
        }
    }
}

// ===========================================================================
// Attention v7 (unchanged from R12, passing): ldmatrix loads, PE ring.
// ===========================================================================
#define A5_KS 0
#define A5_VS 2048
#define A5_PE 4096
#define A5_BIAS 16384
#define A5_MSK 16768
#define A5_U 16832
#define A5_SMEM_BYTES (38336 * 4)
#define SPAD 84
#define SLAB5 1344

__global__ __launch_bounds__(512, 1)
void attn_mma7_kernel(const __half* __restrict__ qkvh,
                      const __half* __restrict__ pekh,
                      const unsigned char* __restrict__ mask,
                      const float* __restrict__ cb,
                      const float* __restrict__ pbias,
                      __half* __restrict__ aoh) {
    extern __shared__ float sm[];
    uint32_t* Ksu  = (uint32_t*)sm + A5_KS;
    uint32_t* Vsu  = (uint32_t*)sm + A5_VS;
    uint32_t* PElu = (uint32_t*)sm + A5_PE;
    float* Bias = sm + A5_BIAS;
    float* Msk  = sm + A5_MSK;
    float* U    = sm + A5_U;
    uint32_t* Qs = (uint32_t*)U;
    uint32_t smemb = cvta_smem(sm);

    int tid = threadIdx.x;
    int w = tid >> 5;
    int lane = tid & 31;
    int g = lane >> 2;
    int tg = lane & 3;
    int qt = blockIdx.x & 3;
    int bh = blockIdx.x >> 2;
    int h  = bh & 15;
    int b  = bh >> 4;
    int q0 = qt * 256;

    uint32_t ksB = smemb;
    uint32_t vsB = smemb + A5_VS * 4;
    uint32_t peB = smemb + A5_PE * 4;
    uint32_t pB  = smemb + (A5_U + w * SLAB5) * 4;

    int rA = (lane & 7) + 8 * ((lane >> 3) & 1);
    int cA = 4 * (lane >> 4);
    int rB = 8 * (lane >> 4) + (lane & 7);
    int cB = 4 * ((lane >> 3) & 1);
    int rV = lane & 15;
    int cV = 4 * (lane >> 4);

    const float* cbh = cb + h * DHEAD;
    const float* pbh_bias = pbias + h * 2048;
    int lbase0 = 767 - q0;

    for (int idx = tid; idx < 2048; idx += 512) {
        int i = idx >> 3, gq = idx & 7;
        int c8 = gq * 8;
        uint4 v = *(const uint4*)(qkvh + ((size_t)(b * SEQ + q0 + i)) * 3072
                                  + h * 192 + c8);
        __half2* hp = (__half2*)&v;
        uint4 o;
#pragma unroll
        for (int e = 0; e < 4; e++) {
            float2 f = __half22float2(hp[e]);
            ((uint32_t*)&o)[e] = pack_h2(f.x + cbh[c8 + 2 * e],
                                         f.y + cbh[c8 + 2 * e + 1]);
        }
        *(uint4*)(Qs + i * 32 + ((gq ^ (i & 7)) << 2)) = o;
    }
    for (int idx = tid; idx < 2560; idx += 512) {
        int sl_ = idx >> 3, gq = idx & 7;
        int lg = lbase0 + sl_;
        uint4 v = (lg >= 0 && lg < LPE)
            ? *(const uint4*)(pekh + (size_t)lg * DMODEL + h * DHEAD + 8 * gq)
            : make_uint4(0u, 0u, 0u, 0u);
        *(uint4*)(PElu + sl_ * 32 + ((gq ^ (sl_ & 7)) << 2)) = v;
    }
    if (tid < 320) {
        int lg = lbase0 + tid;
        Bias[tid] = (lg >= 0 && lg < LPE) ? pbh_bias[lg] : 0.0f;
    }
    __syncthreads();

    uint32_t qcf[4][4];
    int r0l = 16 * w + g, r1l = r0l + 8;
#pragma unroll
    for (int kc = 0; kc < 4; kc++) {
        qcf[kc][0] = Qs[swz32(r0l, 8 * kc + tg)];
        qcf[kc][1] = Qs[swz32(r1l, 8 * kc + tg)];
        qcf[kc][2] = Qs[swz32(r0l, 8 * kc + tg + 4)];
        qcf[kc][3] = Qs[swz32(r1l, 8 * kc + tg + 4)];
    }
    __syncthreads();

    bool zq0 = (q0 == 0 && w == 0 && g == 0);

    float oac[8][4];
#pragma unroll
    for (int nt = 0; nt < 8; nt++)
#pragma unroll
        for (int r = 0; r < 4; r++) oac[nt][r] = 0.0f;
    float m0 = -1e30f, m1 = -1e30f, l0 = 0.0f, l1 = 0.0f;

    float* slab = U + w * SLAB5;
    uint32_t* P32 = (uint32_t*)slab;
    int s0base = 30 - 2 * w;

    for (int kt = 0; kt < 16; kt++) {
        int k0 = kt * 64;
        int ktm = (64 * kt) % 384;
        __syncthreads();

        {
            int i = tid >> 3, gq = tid & 7;
            size_t base = ((size_t)(b * SEQ + k0 + i)) * 3072 + h * 192;
            uint4 kv = *(const uint4*)(qkvh + base + 64 + 8 * gq);
            uint4 vv = *(const uint4*)(qkvh + base + 128 + 8 * gq);
            int sa = i * 32 + ((gq ^ (i & 7)) << 2);
            *(uint4*)(Ksu + sa) = kv;
            *(uint4*)(Vsu + sa) = vv;
        }
        if (tid < 64) Msk[tid] = mask[b * SEQ + k0 + tid] ? -1e30f : 0.0f;
        __syncthreads();

        if (kt < 15) {
            {
                int r = tid >> 3, gq = tid & 7;
                int off = 64 * kt + 320 + r;
                int slot = off % 384;
                int lg = lbase0 + off;
                uint4 v = (lg >= 0 && lg < LPE)
                    ? *(const uint4*)(pekh + (size_t)lg * DMODEL + h * DHEAD + 8 * gq)
                    : make_uint4(0u, 0u, 0u, 0u);
                *(uint4*)(PElu + slot * 32 + ((gq ^ (slot & 7)) << 2)) = v;
            }
            if (tid < 64) {
                int off = 64 * kt + 320 + tid;
                int lg = lbase0 + off;
                Bias[off % 384] = (lg >= 0 && lg < LPE) ? pbh_bias[lg] : 0.0f;
            }
        }

#pragma unroll
        for (int t = 0; t < 10; t++) {
            int m = s0base + t;
            int sr = ktm + 8 * m; if (sr >= 384) sr -= 384;
            float sp[4] = {0.f, 0.f, 0.f, 0.f};
            int rowP = sr + (lane & 7);
#pragma unroll
            for (int kc = 0; kc < 4; kc++) {
                uint32_t bf[2];
                ldsm_x2(bf, peB + 4 * swz32(rowP, 8 * kc + cB));
                mma_f16(sp, qcf[kc], bf);
            }
            int bidx = ktm + 8 * m + 2 * tg; if (bidx >= 384) bidx -= 384;
            float b0 = Bias[bidx], b1 = Bias[bidx + 1];
            int cc0 = 8 * t + 2 * tg;
            slab[g * SPAD + cc0]           = sp[0] + b0;
            slab[g * SPAD + cc0 + 1]       = sp[1] + b1;
            slab[(g + 8) * SPAD + cc0]     = sp[2] + b0;
            slab[(g + 8) * SPAD + cc0 + 1] = sp[3] + b1;
        }
        __syncwarp();

        float sc[8][4];
#pragma unroll
        for (int nt = 0; nt < 8; nt++)
#pragma unroll
            for (int r = 0; r < 4; r++) sc[nt][r] = 0.0f;
#pragma unroll
        for (int ntp = 0; ntp < 4; ntp++) {
            int rowK = 16 * ntp + rB;
#pragma unroll
            for (int kc = 0; kc < 4; kc++) {
                uint32_t r[4];
                ldsm_x4(r, ksB + 4 * swz32(rowK, 8 * kc + cB));
                mma_f16(sc[2 * ntp],     qcf[kc], r);
                mma_f16(sc[2 * ntp + 1], qcf[kc], r + 2);
            }
        }

        float mt0 = -1e30f, mt1 = -1e30f;
#pragma unroll
        for (int nt = 0; nt < 8; nt++) {
            int j0 = nt * 8 + 2 * tg;
            int c00 = j0 - g + 15;
            int c10 = j0 - g + 7;
            float p0 = slab[g * SPAD + c00];
            float p1 = slab[g * SPAD + c00 + 1];
            float p2 = slab[(g + 8) * SPAD + c10];
            float p3 = slab[(g + 8) * SPAD + c10 + 1];
            if (kt == 0 && nt == 0 && tg == 0) { p0 = 0.0f; p2 = 0.0f; }
            if (zq0) { p0 = 0.0f; p1 = 0.0f; }
            float mk0 = Msk[j0], mk1 = Msk[j0 + 1];
            sc[nt][0] = (sc[nt][0] + p0) * 0.125f + mk0;
            sc[nt][1] = (sc[nt][1] + p1) * 0.125f + mk1;
            sc[nt][2] = (sc[nt][2] + p2) * 0.125f + mk0;
            sc[nt][3] = (sc[nt][3] + p3) * 0.125f + mk1;
            mt0 = fmaxf(mt0, fmaxf(sc[nt][0], sc[nt][1]));
            mt1 = fmaxf(mt1, fmaxf(sc[nt][2], sc[nt][3]));
        }
        mt0 = fmaxf(mt0, __shfl_xor_sync(0xffffffffu, mt0, 1));
        mt0 = fmaxf(mt0, __shfl_xor_sync(0xffffffffu, mt0, 2));
        mt1 = fmaxf(mt1, __shfl_xor_sync(0xffffffffu, mt1, 1));
        mt1 = fmaxf(mt1, __shfl_xor_sync(0xffffffffu, mt1, 2));

        float mn0 = fmaxf(m0, mt0), mn1 = fmaxf(m1, mt1);
        float c0 = __expf(m0 - mn0), c1 = __expf(m1 - mn1);
        m0 = mn0; m1 = mn1;
#pragma unroll
        for (int nt = 0; nt < 8; nt++) {
            oac[nt][0] *= c0; oac[nt][1] *= c0;
            oac[nt][2] *= c1; oac[nt][3] *= c1;
        }
        float rs0 = 0.0f, rs1 = 0.0f;
#pragma unroll
        for (int nt = 0; nt < 8; nt++) {
            sc[nt][0] = __expf(sc[nt][0] - mn0);
            sc[nt][1] = __expf(sc[nt][1] - mn0);
            sc[nt][2] = __expf(sc[nt][2] - mn1);
            sc[nt][3] = __expf(sc[nt][3] - mn1);
            rs0 += sc[nt][0] + sc[nt][1];
            rs1 += sc[nt][2] + sc[nt][3];
        }
        rs0 += __shfl_xor_sync(0xffffffffu, rs0, 1);
        rs0 += __shfl_xor_sync(0xffffffffu, rs0, 2);
        rs1 += __shfl_xor_sync(0xffffffffu, rs1, 1);
        rs1 += __shfl_xor_sync(0xffffffffu, rs1, 2);
        l0 = l0 * c0 + rs0;
        l1 = l1 * c1 + rs1;

        __syncwarp();

#pragma unroll
        for (int nt = 0; nt < 8; nt++) {
            P32[swz32(g,     4 * nt + tg)] = pack_h2(sc[nt][0], sc[nt][1]);
            P32[swz32(g + 8, 4 * nt + tg)] = pack_h2(sc[nt][2], sc[nt][3]);
        }
        __syncwarp();

        uint32_t pf[4][4];
#pragma unroll
        for (int kc = 0; kc < 4; kc++)
            ldsm_x4(pf[kc], pB + 4 * swz32(rA, 8 * kc + cA));
#pragma unroll
        for (int ntp = 0; ntp < 4; ntp++) {
            int cpV = 8 * ntp + cV;
#pragma unroll
            for (int kc = 0; kc < 4; kc++) {
                uint32_t r[4];
                ldsm_x4_t(r, vsB + 4 * swz32(16 * kc + rV, cpV));
                mma_f16(oac[2 * ntp],     pf[kc], r);
                mma_f16(oac[2 * ntp + 1], pf[kc], r + 2);
            }
        }
    }

    float inv0 = 1.0f / l0, inv1 = 1.0f / l1;
    int r0 = q0 + r0l, r1 = q0 + r1l;
    size_t rowA = ((size_t)(b * SEQ + r0)) * DMODEL + h * DHEAD;
    size_t rowB = ((size_t)(b * SEQ + r1)) * DMODEL + h * DHEAD;
#pragma unroll
    for (int nt = 0; nt < 8; nt++) {
        int col = nt * 8 + 2 * tg;
        *(uint32_t*)(aoh + rowA + col) =
            pack_h2(oac[nt][0] * inv0, oac[nt][1] * inv0);
        *(uint32_t*)(aoh + rowB + col) =
            pack_h2(oac[nt][2] * inv1, oac[nt][3] * inv1);
    }
}

// ---------------------------------------------------------------------------
extern "C" void kernel_launch(void* const* d_in, const int* in_sizes, int n_in,
                              void* d_out, int out_size) {
    const float* x          = (const float*)d_in[0];
    const unsigned char* mk = (const unsigned char*)d_in[1];
    const float* Wqkv       = (const float*)d_in[2];
    const float* Wpe        = (const float*)d_in[3];
    const float* Wo         = (const float*)d_in[4];
    const float* cb         = (const float*)d_in[5];
    const float* pb         = (const float*)d_in[6];
    float* out              = (float*)d_out;

    __half *xh, *wqkvh, *wpeh, *woh, *qkvh, *peh, *pekh, *aoh;
    float *pbias;
    cudaGetSymbolAddress((void**)&xh,    g_xh);
    cudaGetSymbolAddress((void**)&wqkvh, g_wqkvh);
    cudaGetSymbolAddress((void**)&wpeh,  g_wpeh);
    cudaGetSymbolAddress((void**)&woh,   g_woh);
    cudaGetSymbolAddress((void**)&qkvh,  g_qkvh);
    cudaGetSymbolAddress((void**)&peh,   g_peh);
    cudaGetSymbolAddress((void**)&pekh,  g_pekh);
    cudaGetSymbolAddress((void**)&aoh,   g_aoh);
    cudaGetSymbolAddress((void**)&pbias, g_pbias);

    cudaFuncSetAttribute(gemm_h_kernel<true>,
                         cudaFuncAttributeMaxDynamicSharedMemorySize,
                         GEMMH_SMEM_BYTES);
    cudaFuncSetAttribute(gemm_h_kernel<false>,
                         cudaFuncAttributeMaxDynamicSharedMemorySize,
                         GEMMH_SMEM_BYTES);
    cudaFuncSetAttribute(attn_mma7_kernel,
                         cudaFuncAttributeMaxDynamicSharedMemorySize,
                         A5_SMEM_BYTES);

    // Convert inputs/weights to half; generate pe (half)
    f2h_kernel<<<(BSZ * SEQ * DMODEL / 4 + 255) / 256, 256>>>(x, xh,
                                                              BSZ * SEQ * DMODEL);
    f2h_kernel<<<(DMODEL * 3 * DMODEL / 4 + 255) / 256, 256>>>(Wqkv, wqkvh,
                                                               DMODEL * 3 * DMODEL);
    f2h_kernel<<<(DMODEL * DMODEL / 4 + 255) / 256, 256>>>(Wpe, wpeh,
                                                           DMODEL * DMODEL);
    f2h_kernel<<<(DMODEL * DMODEL / 4 + 255) / 256, 256>>>(Wo, woh,
                                                           DMODEL * DMODEL);
    pegen_kernel<<<(LPE * DMODEL + 255) / 256, 256>>>(peh);

    // qkv = x @ W_qkv (half C)
    {
        dim3 grid(3072 / 128, 4096 / 128);
        gemm_h_kernel<true><<<grid, 256, GEMMH_SMEM_BYTES>>>(
            xh, wqkvh, qkvh, BSZ * SEQ, 3 * DMODEL, DMODEL);
    }
    // pe_key = pe @ W_pe (half C)
    {
        dim3 grid(1024 / 128, (LPE + 127) / 128);
        gemm_h_kernel<true><<<grid, 256, GEMMH_SMEM_BYTES>>>(
            peh, wpeh, pekh, LPE, DMODEL, DMODEL);
    }

    pbias_kernel<<<(NHEAD * 2048 * 32) / 256, 256>>>(pekh, cb, pb, pbias);

    attn_mma7_kernel<<<BSZ * NHEAD * (SEQ / 256), 512, A5_SMEM_BYTES>>>(
        qkvh, pekh, mk, cb, pbias, aoh);

    // out = ao @ W_o (fp32 C)
    {
        dim3 grid(1024 / 128, 4096 / 128);
        gemm_h_kernel<false><<<grid, 256, GEMMH_SMEM_BYTES>>>(
            aoh, woh, out, BSZ * SEQ, DMODEL, DMODEL);
    }
}